// round 7
// baseline (speedup 1.0000x reference)
#include <cuda_runtime.h>
#include <cuda_bf16.h>
#include <cstdint>
#include <cstddef>

// Problem constants
#define Bq   4
#define Sq   2048
#define Dq   1024
#define Hq   16
#define DHq  64
#define BSDq (Bq*Sq*Dq)   // 8388608

typedef unsigned long long u64;

// ---------------- generic-PTX tensor-core helpers (sm_80+ ISA) -------------
__device__ __forceinline__ uint32_t smem_u32(const void* p) {
    uint32_t a;
    asm("{ .reg .u64 t; cvta.to.shared.u64 t, %1; cvt.u32.u64 %0, t; }"
        : "=r"(a) : "l"(p));
    return a;
}
__device__ __forceinline__ void cp_async16(uint32_t s, const void* g) {
    asm volatile("cp.async.cg.shared.global [%0], [%1], 16;" :: "r"(s), "l"(g));
}
#define CP_COMMIT() asm volatile("cp.async.commit_group;" ::: "memory")
#define CP_WAIT(n)  asm volatile("cp.async.wait_group %0;" :: "n"(n) : "memory")

__device__ __forceinline__ void ldsm4(uint32_t* r, uint32_t addr) {
    asm volatile("ldmatrix.sync.aligned.m8n8.x4.shared.b16 {%0,%1,%2,%3}, [%4];"
                 : "=r"(r[0]), "=r"(r[1]), "=r"(r[2]), "=r"(r[3]) : "r"(addr));
}
__device__ __forceinline__ void ldsm4t(uint32_t* r, uint32_t addr) {
    asm volatile("ldmatrix.sync.aligned.m8n8.x4.trans.shared.b16 {%0,%1,%2,%3}, [%4];"
                 : "=r"(r[0]), "=r"(r[1]), "=r"(r[2]), "=r"(r[3]) : "r"(addr));
}
// D(f32) += A(bf16) * B(bf16); m16n8k16 row.col
__device__ __forceinline__ void mma16816(float* d, const uint32_t* a,
                                         uint32_t b0, uint32_t b1) {
    asm volatile(
        "mma.sync.aligned.m16n8k16.row.col.f32.bf16.bf16.f32 "
        "{%0,%1,%2,%3}, {%4,%5,%6,%7}, {%8,%9}, {%0,%1,%2,%3};"
        : "+f"(d[0]), "+f"(d[1]), "+f"(d[2]), "+f"(d[3])
        : "r"(a[0]), "r"(a[1]), "r"(a[2]), "r"(a[3]), "r"(b0), "r"(b1));
}
// byte offset of (row, 16B-chunk) in a [rows][64 bf16] tile, xor swizzle
__device__ __forceinline__ uint32_t swz(int row, int ch) {
    uint32_t off = (uint32_t)(row * 128 + ch * 16);
    return off ^ (((uint32_t)row & 7u) << 4);
}

// ---------------- scratch (device globals: allocation-free rule) -----------
__device__ int g_mask_kind;
__device__ __align__(16) __nv_bfloat16 g_qh[BSDq];
__device__ __align__(16) __nv_bfloat16 g_ql[BSDq];
__device__ __align__(16) __nv_bfloat16 g_kh[BSDq];
__device__ __align__(16) __nv_bfloat16 g_kl[BSDq];
__device__ __align__(16) __nv_bfloat16 g_vh[BSDq];
__device__ __align__(16) __nv_bfloat16 g_vl[BSDq];
__device__ __align__(16) __nv_bfloat16 g_xhi[BSDq];
__device__ __align__(16) __nv_bfloat16 g_xlo[BSDq];
__device__ __align__(16) __nv_bfloat16 g_whi[Dq * Dq];
__device__ __align__(16) __nv_bfloat16 g_wlo[Dq * Dq];

// ---------------------------------------------------------------------------
__global__ void detect_mask_kernel(const unsigned char* __restrict__ m) {
    if (threadIdx.x != 0) return;
    int c0 = 0, c1 = 0, c2 = 0, c3 = 0;
    for (int i = 0; i < 4096; i += 4) {
        if (m[i + 0]) c0++;
        if (m[i + 1]) c1++;
        if (m[i + 2]) c2++;
        if (m[i + 3]) c3++;
    }
    int kind;
    if (c1 == 0 && c2 == 0 && c3 == 0) kind = 1;   // int32
    else if (c0 == 0 && c1 == 0)       kind = 2;   // float32
    else                               kind = 0;   // uint8
    g_mask_kind = kind;
}

// fp32 -> bf16 hi/lo split
__global__ __launch_bounds__(256)
void split_kernel(const float* __restrict__ x, __nv_bfloat16* __restrict__ hi,
                  __nv_bfloat16* __restrict__ lo, int n)
{
    int i = (blockIdx.x * 256 + threadIdx.x) * 4;
    if (i >= n) return;
    float4 v = *(const float4*)(x + i);
    __nv_bfloat16 h0 = __float2bfloat16(v.x), h1 = __float2bfloat16(v.y);
    __nv_bfloat16 h2 = __float2bfloat16(v.z), h3 = __float2bfloat16(v.w);
    __nv_bfloat162 hA, hB, lA, lB;
    hA.x = h0; hA.y = h1; hB.x = h2; hB.y = h3;
    lA.x = __float2bfloat16(v.x - __bfloat162float(h0));
    lA.y = __float2bfloat16(v.y - __bfloat162float(h1));
    lB.x = __float2bfloat16(v.z - __bfloat162float(h2));
    lB.y = __float2bfloat16(v.w - __bfloat162float(h3));
    *(__nv_bfloat162*)(hi + i)     = hA;
    *(__nv_bfloat162*)(hi + i + 2) = hB;
    *(__nv_bfloat162*)(lo + i)     = lA;
    *(__nv_bfloat162*)(lo + i + 2) = lB;
}

// ---------------------------------------------------------------------------
// HMMA split-bf16 GEMM: X @ W^T. Output either fp32 (+bias) or split bf16
// hi/lo (with scale) for downstream tensor-core consumers.
// ---------------------------------------------------------------------------
#define GSTAGE  65536
#define GA_HI   0
#define GA_LO   16384
#define GB_HI   32768
#define GB_LO   49152
#define GSMEM   (2*GSTAGE)

__global__ __launch_bounds__(256, 1)
void gemm_tc_kernel(const __nv_bfloat16* __restrict__ Ahi,
                    const __nv_bfloat16* __restrict__ Alo,
                    const __nv_bfloat16* __restrict__ Bhi,
                    const __nv_bfloat16* __restrict__ Blo,
                    const float* __restrict__ bias, float* __restrict__ out32,
                    __nv_bfloat16* __restrict__ outh,
                    __nv_bfloat16* __restrict__ outl, float scale,
                    int M, int N, int K)
{
    extern __shared__ char smem[];
    const uint32_t sbase = smem_u32(smem);
    const int tid  = threadIdx.x;
    const int wid  = tid >> 5;
    const int lane = tid & 31;
    const int m0 = blockIdx.y * 128;
    const int n0 = blockIdx.x * 128;
    const int wm = wid & 1;
    const int wn = wid >> 1;

    float acc[4][4][4];
#pragma unroll
    for (int i = 0; i < 4; i++)
#pragma unroll
        for (int j = 0; j < 4; j++)
#pragma unroll
            for (int c = 0; c < 4; c++) acc[i][j][c] = 0.f;

    int lrow[4], lch[4];
#pragma unroll
    for (int l = 0; l < 4; l++) {
        int idx = l * 256 + tid;
        lrow[l] = idx >> 3;
        lch[l]  = idx & 7;
    }

    auto load_stage = [&](int t, int buf) {
        const int k0 = t * 64;
        const uint32_t sb = sbase + buf * GSTAGE;
#pragma unroll
        for (int l = 0; l < 4; l++) {
            uint32_t sw = swz(lrow[l], lch[l]);
            size_t ao = (size_t)(m0 + lrow[l]) * K + k0 + lch[l] * 8;
            size_t bo = (size_t)(n0 + lrow[l]) * K + k0 + lch[l] * 8;
            cp_async16(sb + GA_HI + sw, Ahi + ao);
            cp_async16(sb + GA_LO + sw, Alo + ao);
            cp_async16(sb + GB_HI + sw, Bhi + bo);
            cp_async16(sb + GB_LO + sw, Blo + bo);
        }
    };

    load_stage(0, 0);
    CP_COMMIT();

    const int NT = K / 64;
#pragma unroll 1
    for (int t = 0; t < NT; t++) {
        const int buf = t & 1;
        if (t + 1 < NT) {
            load_stage(t + 1, (t + 1) & 1);
            CP_COMMIT();
            CP_WAIT(1);
        } else {
            CP_WAIT(0);
        }
        __syncthreads();

        const uint32_t sb = sbase + buf * GSTAGE;
        const int arow = wm * 64 + (lane & 15);
        const int brow = wn * 32 + (lane & 15);
#pragma unroll
        for (int ks = 0; ks < 4; ks++) {
            const int ch = ks * 2 + (lane >> 4);
            uint32_t ah[4][4], al[4][4];
#pragma unroll
            for (int mt = 0; mt < 4; mt++) {
                uint32_t sw = swz(arow + mt * 16, ch);
                ldsm4(ah[mt], sb + GA_HI + sw);
                ldsm4(al[mt], sb + GA_LO + sw);
            }
            uint32_t bh[2][4], bl[2][4];
#pragma unroll
            for (int nb = 0; nb < 2; nb++) {
                uint32_t sw = swz(brow + nb * 16, ch);
                ldsm4(bh[nb], sb + GB_HI + sw);
                ldsm4(bl[nb], sb + GB_LO + sw);
            }
#pragma unroll
            for (int mt = 0; mt < 4; mt++)
#pragma unroll
                for (int nt = 0; nt < 4; nt++) {
                    const int nb = nt >> 1, hh = nt & 1;
                    mma16816(acc[mt][nt], ah[mt], bh[nb][hh], bh[nb][2 + hh]);
                    mma16816(acc[mt][nt], ah[mt], bl[nb][hh], bl[nb][2 + hh]);
                    mma16816(acc[mt][nt], al[mt], bh[nb][hh], bh[nb][2 + hh]);
                }
        }
        __syncthreads();
    }

#pragma unroll
    for (int mt = 0; mt < 4; mt++) {
#pragma unroll
        for (int nt = 0; nt < 4; nt++) {
            int row = m0 + wm * 64 + mt * 16 + (lane >> 2);
            int col = n0 + wn * 32 + nt * 8 + (lane & 3) * 2;
            if (out32) {
                float2 v0, v1;
                v0.x = acc[mt][nt][0]; v0.y = acc[mt][nt][1];
                v1.x = acc[mt][nt][2]; v1.y = acc[mt][nt][3];
                if (bias) {
                    float b0 = bias[col], b1 = bias[col + 1];
                    v0.x += b0; v0.y += b1;
                    v1.x += b0; v1.y += b1;
                }
                *(float2*)(out32 + (size_t)row * N + col)       = v0;
                *(float2*)(out32 + (size_t)(row + 8) * N + col) = v1;
            } else {
#pragma unroll
                for (int rr = 0; rr < 2; rr++) {
                    size_t o = (size_t)(row + rr * 8) * N + col;
                    float x0 = acc[mt][nt][rr * 2 + 0] * scale;
                    float x1 = acc[mt][nt][rr * 2 + 1] * scale;
                    __nv_bfloat162 hv, lv;
                    hv.x = __float2bfloat16(x0);
                    hv.y = __float2bfloat16(x1);
                    lv.x = __float2bfloat16(x0 - __bfloat162float(hv.x));
                    lv.y = __float2bfloat16(x1 - __bfloat162float(hv.y));
                    *(__nv_bfloat162*)(outh + o) = hv;
                    *(__nv_bfloat162*)(outl + o) = lv;
                }
            }
        }
    }
}

// ---------------------------------------------------------------------------
// HMMA flash attention, fragment-resident softmax:
// mask+exp+hi/lo split happen in MMA fragment registers (no fp32 S smem,
// no half-row gather); per-row denominators accumulate in registers and are
// reduced once (quad shfl + 2KB smem) after the k-loop. 2 barriers/k-tile.
// ---------------------------------------------------------------------------
#define AS_QH   0
#define AS_QL   16384
#define AS_K    32768                 // [buf][hi 8192 | lo 8192] x2
#define AS_V    65536
#define AS_PH   98304                 // [128][64] bf16 swizzled
#define AS_PL   114688
#define AS_DEN  131072                // [4 wn][128] float
#define ATT_SMEM (AS_DEN + 2048)

__global__ __launch_bounds__(256, 1)
void attention_tc_kernel(const void* __restrict__ mask, float* __restrict__ resT,
                         __nv_bfloat16* __restrict__ ctx_h,
                         __nv_bfloat16* __restrict__ ctx_l)
{
    extern __shared__ char smem[];
    const uint32_t sbase = smem_u32(smem);
    float* sDen4 = (float*)(smem + AS_DEN);   // [4][128]

    const int tid  = threadIdx.x;
    const int wid  = tid >> 5;
    const int lane = tid & 31;
    const int wm = wid & 1;        // 2 m-warps (64 q-rows)
    const int wn = wid >> 1;       // 4 n-warps (16 k-cols)
    const int blk = blockIdx.x;
    const int qt  = blk & 15;
    const int h   = (blk >> 4) & 15;
    const int b   = blk >> 8;
    const int q0  = qt * 128;
    const int mk  = g_mask_kind;

    const size_t headBase = (size_t)b * Sq * Dq + (size_t)h * Sq * DHq;
    const __nv_bfloat16* Qh = g_qh + headBase;
    const __nv_bfloat16* Ql = g_ql + headBase;
    const __nv_bfloat16* Kh = g_kh + headBase;
    const __nv_bfloat16* Kl = g_kl + headBase;
    const __nv_bfloat16* Vh = g_vh + headBase;
    const __nv_bfloat16* Vl = g_vl + headBase;

    // ---- initial loads: Q (persistent) + K/V stage 0 ----
#pragma unroll
    for (int l = 0; l < 4; l++) {
        int idx = l * 256 + tid;
        int row = idx >> 3, ch = idx & 7;
        uint32_t sw = swz(row, ch);
        size_t o = (size_t)(q0 + row) * DHq + ch * 8;
        cp_async16(sbase + AS_QH + sw, Qh + o);
        cp_async16(sbase + AS_QL + sw, Ql + o);
    }
#pragma unroll
    for (int l = 0; l < 2; l++) {
        int id2 = l * 256 + tid;
        int row = id2 >> 3, ch = id2 & 7;
        uint32_t sw = swz(row, ch);
        size_t o = (size_t)row * DHq + ch * 8;
        cp_async16(sbase + AS_K + sw,        Kh + o);
        cp_async16(sbase + AS_K + 8192 + sw, Kl + o);
        cp_async16(sbase + AS_V + sw,        Vh + o);
        cp_async16(sbase + AS_V + 8192 + sw, Vl + o);
    }
    CP_COMMIT();

    float oacc[4][2][4];
#pragma unroll
    for (int mt = 0; mt < 4; mt++)
#pragma unroll
        for (int nt = 0; nt < 2; nt++)
#pragma unroll
            for (int c = 0; c < 4; c++) oacc[mt][nt][c] = 0.f;
    float denAcc[4][2];
#pragma unroll
    for (int mt = 0; mt < 4; mt++) { denAcc[mt][0] = 0.f; denAcc[mt][1] = 0.f; }

    const int arow = wm * 64 + (lane & 15);
    const int brow = wn * 16 + (lane & 15);
    const int frow = wm * 64 + (lane >> 2);      // fragment row base
    const int fcol = wn * 16 + (lane & 3) * 2;   // fragment col base
    const int vrow0 = (lane & 7) + ((lane >> 4) << 3);
    const int vch   = wn * 2 + ((lane >> 3) & 1);

    const int NT = Sq / 64;
#pragma unroll 1
    for (int kt = 0; kt < NT; kt++) {
        const int buf = kt & 1;
        CP_WAIT(0);
        __syncthreads();   // K/V[buf] ready; P smem free (prev PV done)

        // prefetch next K/V stage
        if (kt + 1 < NT) {
            const uint32_t kb = sbase + AS_K + (1 - buf) * 16384;
            const uint32_t vb = sbase + AS_V + (1 - buf) * 16384;
            const size_t gk = (size_t)(kt + 1) * 64 * DHq;
#pragma unroll
            for (int l = 0; l < 2; l++) {
                int id2 = l * 256 + tid;
                int row = id2 >> 3, ch = id2 & 7;
                uint32_t sw = swz(row, ch);
                size_t o = gk + (size_t)row * DHq + ch * 8;
                cp_async16(kb + sw,        Kh + o);
                cp_async16(kb + 8192 + sw, Kl + o);
                cp_async16(vb + sw,        Vh + o);
                cp_async16(vb + 8192 + sw, Vl + o);
            }
            CP_COMMIT();
        }

        // ---- S = Q K^T (3-term split) ----
        float sacc[4][2][4];
#pragma unroll
        for (int mt = 0; mt < 4; mt++)
#pragma unroll
            for (int nt = 0; nt < 2; nt++)
#pragma unroll
                for (int c = 0; c < 4; c++) sacc[mt][nt][c] = 0.f;

        const uint32_t kbh = sbase + AS_K + buf * 16384;
        const uint32_t kbl = kbh + 8192;
#pragma unroll
        for (int ks = 0; ks < 4; ks++) {
            const int ch = ks * 2 + (lane >> 4);
            uint32_t ah[4][4], al[4][4];
#pragma unroll
            for (int mt = 0; mt < 4; mt++) {
                uint32_t sw = swz(arow + mt * 16, ch);
                ldsm4(ah[mt], sbase + AS_QH + sw);
                ldsm4(al[mt], sbase + AS_QL + sw);
            }
            uint32_t bh[4], bl[4];
            {
                uint32_t sw = swz(brow, ch);
                ldsm4(bh, kbh + sw);
                ldsm4(bl, kbl + sw);
            }
#pragma unroll
            for (int mt = 0; mt < 4; mt++)
#pragma unroll
                for (int hh = 0; hh < 2; hh++) {
                    mma16816(sacc[mt][hh], ah[mt], bh[hh], bh[2 + hh]);
                    mma16816(sacc[mt][hh], ah[mt], bl[hh], bl[2 + hh]);
                    mma16816(sacc[mt][hh], al[mt], bh[hh], bh[2 + hh]);
                }
        }

        // ---- fragment-resident softmax: mask+exp+split in registers ----
        {
            const int k0 = kt * 64;
            const size_t mrowB = (size_t)b * Sq * Sq + (size_t)q0 * Sq + k0;
#pragma unroll
            for (int mt = 0; mt < 4; mt++)
#pragma unroll
                for (int rr = 0; rr < 2; rr++) {
                    const int row = frow + mt * 16 + rr * 8;
                    const size_t mrow = mrowB + (size_t)row * Sq;
#pragma unroll
                    for (int nt = 0; nt < 2; nt++) {
                        const int col = fcol + nt * 8;
                        float v0 = sacc[mt][nt][rr * 2 + 0];
                        float v1 = sacc[mt][nt][rr * 2 + 1];
                        bool vis0, vis1;
                        if (mk == 0) {
                            const unsigned char* mp =
                                (const unsigned char*)mask + mrow + col;
                            unsigned short mm = *(const unsigned short*)mp;
                            vis0 = (mm & 0xff) != 0;
                            vis1 = (mm >> 8) != 0;
                        } else if (mk == 1) {
                            int2 mm = *(const int2*)((const int*)mask + mrow + col);
                            vis0 = mm.x != 0; vis1 = mm.y != 0;
                        } else {
                            float2 mm = *(const float2*)((const float*)mask + mrow + col);
                            vis0 = mm.x != 0.f; vis1 = mm.y != 0.f;
                        }
                        float p0 = vis0 ? __expf(v0) : 0.f;
                        float p1 = vis1 ? __expf(v1) : 0.f;
                        denAcc[mt][rr] += p0 + p1;
                        __nv_bfloat162 h2, l2;
                        h2.x = __float2bfloat16(p0);
                        h2.y = __float2bfloat16(p1);
                        l2.x = __float2bfloat16(p0 - __bfloat162float(h2.x));
                        l2.y = __float2bfloat16(p1 - __bfloat162float(h2.y));
                        uint32_t off = (uint32_t)(row * 128 + col * 2);
                        off ^= ((uint32_t)row & 7u) << 4;
                        *(uint32_t*)(smem + AS_PH + off) = *(uint32_t*)&h2;
                        *(uint32_t*)(smem + AS_PL + off) = *(uint32_t*)&l2;
                    }
                }
        }
        __syncthreads();   // P visible to all warps

        // ---- O += P V (3-term split; V via ldmatrix.trans) ----
        const uint32_t vbh = sbase + AS_V + buf * 16384;
        const uint32_t vbl = vbh + 8192;
#pragma unroll
        for (int ks = 0; ks < 4; ks++) {
            const int ch = ks * 2 + (lane >> 4);
            uint32_t ah[4][4], al[4][4];
#pragma unroll
            for (int mt = 0; mt < 4; mt++) {
                uint32_t sw = swz(arow + mt * 16, ch);
                ldsm4(ah[mt], sbase + AS_PH + sw);
                ldsm4(al[mt], sbase + AS_PL + sw);
            }
            uint32_t bh[4], bl[4];
            {
                uint32_t sw = swz(ks * 16 + vrow0, vch);
                ldsm4t(bh, vbh + sw);
                ldsm4t(bl, vbl + sw);
            }
#pragma unroll
            for (int mt = 0; mt < 4; mt++)
#pragma unroll
                for (int hh = 0; hh < 2; hh++) {
                    mma16816(oacc[mt][hh], ah[mt], bh[hh], bh[2 + hh]);
                    mma16816(oacc[mt][hh], ah[mt], bl[hh], bl[2 + hh]);
                    mma16816(oacc[mt][hh], al[mt], bh[hh], bh[2 + hh]);
                }
        }
    }

    // ---- one-shot denominator reduction: quad shfl + cross-warp smem ----
#pragma unroll
    for (int mt = 0; mt < 4; mt++)
#pragma unroll
        for (int rr = 0; rr < 2; rr++) {
            float d = denAcc[mt][rr];
            d += __shfl_xor_sync(0xffffffffu, d, 1);
            d += __shfl_xor_sync(0xffffffffu, d, 2);
            if ((lane & 3) == 0)
                sDen4[wn * 128 + frow + mt * 16 + rr * 8] = d;
        }
    __syncthreads();

    // ---- epilogue: normalize, write split context + resT ----
#pragma unroll
    for (int mt = 0; mt < 4; mt++)
#pragma unroll
        for (int nt = 0; nt < 2; nt++)
#pragma unroll
            for (int rr = 0; rr < 2; rr++) {
                int r   = frow + mt * 16 + rr * 8;
                int col = fcol + nt * 8;
                float dn = sDen4[r] + sDen4[128 + r] + sDen4[256 + r]
                         + sDen4[384 + r];
                float inv = dn > 0.f ? 1.f / dn : 0.f;     // NaN->0 semantics
                float x0 = oacc[mt][nt][rr * 2 + 0] * inv;
                float x1 = oacc[mt][nt][rr * 2 + 1] * inv;
                int s2 = q0 + r;
                size_t co = ((size_t)b * Sq + s2) * Dq + h * DHq + col;
                __nv_bfloat162 hv, lv;
                hv.x = __float2bfloat16(x0);
                hv.y = __float2bfloat16(x1);
                lv.x = __float2bfloat16(x0 - __bfloat162float(hv.x));
                lv.y = __float2bfloat16(x1 - __bfloat162float(hv.y));
                *(__nv_bfloat162*)(ctx_h + co) = hv;
                *(__nv_bfloat162*)(ctx_l + co) = lv;
                if (resT) {
                    float2 rv; rv.x = x0; rv.y = x1;
                    *(float2*)(resT + (((size_t)h * Bq + b) * Sq + s2) * DHq + col) = rv;
                }
            }
}

// ---------------------------------------------------------------------------
extern "C" void kernel_launch(void* const* d_in, const int* in_sizes, int n_in,
                              void* d_out, int out_size)
{
    const float* query = (const float*)d_in[0];
    const float* key_  = (const float*)d_in[1];
    const float* value = (const float*)d_in[2];
    const void*  mask  = d_in[3];
    const float* Wq    = (const float*)d_in[4];
    const float* Wk    = (const float*)d_in[5];
    const float* Wv    = (const float*)d_in[6];
    const float* fcw   = (const float*)d_in[7];
    const float* fcb   = (const float*)d_in[8];
    float* out = (float*)d_out;

    __nv_bfloat16 *qh, *ql, *kh, *kl, *vh, *vl, *xhi, *xlo, *whi, *wlo;
    cudaGetSymbolAddress((void**)&qh,  g_qh);
    cudaGetSymbolAddress((void**)&ql,  g_ql);
    cudaGetSymbolAddress((void**)&kh,  g_kh);
    cudaGetSymbolAddress((void**)&kl,  g_kl);
    cudaGetSymbolAddress((void**)&vh,  g_vh);
    cudaGetSymbolAddress((void**)&vl,  g_vl);
    cudaGetSymbolAddress((void**)&xhi, g_xhi);
    cudaGetSymbolAddress((void**)&xlo, g_xlo);
    cudaGetSymbolAddress((void**)&whi, g_whi);
    cudaGetSymbolAddress((void**)&wlo, g_wlo);

    cudaFuncSetAttribute(gemm_tc_kernel,
                         cudaFuncAttributeMaxDynamicSharedMemorySize, GSMEM);
    cudaFuncSetAttribute(attention_tc_kernel,
                         cudaFuncAttributeMaxDynamicSharedMemorySize, ATT_SMEM);

    detect_mask_kernel<<<1, 32>>>((const unsigned char*)mask);

    const int M = Bq * Sq;               // 8192
    dim3 gtc(Dq / 128, M / 128);         // (8, 64)
    const int nX = M * Dq, nW = Dq * Dq;
    const int bX = nX / 4 / 256, bW = nW / 4 / 256;

    // Q projection (pre-scaled by 1/8), K, V -> split bf16 outputs
    split_kernel<<<bX, 256>>>(query, xhi, xlo, nX);
    split_kernel<<<bW, 256>>>(Wq, whi, wlo, nW);
    gemm_tc_kernel<<<gtc, 256, GSMEM>>>(xhi, xlo, whi, wlo, nullptr, nullptr,
                                        qh, ql, 0.125f, M, Dq, Dq);

    split_kernel<<<bX, 256>>>(key_, xhi, xlo, nX);
    split_kernel<<<bW, 256>>>(Wk, whi, wlo, nW);
    gemm_tc_kernel<<<gtc, 256, GSMEM>>>(xhi, xlo, whi, wlo, nullptr, nullptr,
                                        kh, kl, 1.0f, M, Dq, Dq);

    split_kernel<<<bX, 256>>>(value, xhi, xlo, nX);
    split_kernel<<<bW, 256>>>(Wv, whi, wlo, nW);
    gemm_tc_kernel<<<gtc, 256, GSMEM>>>(xhi, xlo, whi, wlo, nullptr, nullptr,
                                        vh, vl, 1.0f, M, Dq, Dq);

    // attention writes context split into xhi/xlo + resT fp32
    float* resT = (out_size >= 2 * BSDq) ? (out + BSDq) : nullptr;
    attention_tc_kernel<<<Bq * Hq * (Sq / 128), 256, ATT_SMEM>>>(mask, resT,
                                                                 xhi, xlo);

    // final FC: fp32 out with bias
    split_kernel<<<bW, 256>>>(fcw, whi, wlo, nW);
    gemm_tc_kernel<<<gtc, 256, GSMEM>>>(xhi, xlo, whi, wlo, fcb, out,
                                        nullptr, nullptr, 1.0f, M, Dq, Dq);
}

// round 9
// speedup vs baseline: 1.6921x; 1.6921x over previous
#include <cuda_runtime.h>
#include <cuda_bf16.h>
#include <cstdint>
#include <cstddef>

// Problem constants
#define Bq   4
#define Sq   2048
#define Dq   1024
#define Hq   16
#define DHq  64
#define BSDq (Bq*Sq*Dq)   // 8388608
#define MWORDS (Bq*Sq*(Sq/64))   // 262144 u64 mask words

typedef unsigned long long u64;

// ---------------- generic-PTX tensor-core helpers (sm_80+ ISA) -------------
__device__ __forceinline__ uint32_t smem_u32(const void* p) {
    uint32_t a;
    asm("{ .reg .u64 t; cvta.to.shared.u64 t, %1; cvt.u32.u64 %0, t; }"
        : "=r"(a) : "l"(p));
    return a;
}
__device__ __forceinline__ void cp_async16(uint32_t s, const void* g) {
    asm volatile("cp.async.cg.shared.global [%0], [%1], 16;" :: "r"(s), "l"(g));
}
#define CP_COMMIT() asm volatile("cp.async.commit_group;" ::: "memory")
#define CP_WAIT(n)  asm volatile("cp.async.wait_group %0;" :: "n"(n) : "memory")

__device__ __forceinline__ void ldsm4(uint32_t* r, uint32_t addr) {
    asm volatile("ldmatrix.sync.aligned.m8n8.x4.shared.b16 {%0,%1,%2,%3}, [%4];"
                 : "=r"(r[0]), "=r"(r[1]), "=r"(r[2]), "=r"(r[3]) : "r"(addr));
}
__device__ __forceinline__ void ldsm4t(uint32_t* r, uint32_t addr) {
    asm volatile("ldmatrix.sync.aligned.m8n8.x4.trans.shared.b16 {%0,%1,%2,%3}, [%4];"
                 : "=r"(r[0]), "=r"(r[1]), "=r"(r[2]), "=r"(r[3]) : "r"(addr));
}
// D(f32) += A(bf16) * B(bf16); m16n8k16 row.col
__device__ __forceinline__ void mma16816(float* d, const uint32_t* a,
                                         uint32_t b0, uint32_t b1) {
    asm volatile(
        "mma.sync.aligned.m16n8k16.row.col.f32.bf16.bf16.f32 "
        "{%0,%1,%2,%3}, {%4,%5,%6,%7}, {%8,%9}, {%0,%1,%2,%3};"
        : "+f"(d[0]), "+f"(d[1]), "+f"(d[2]), "+f"(d[3])
        : "r"(a[0]), "r"(a[1]), "r"(a[2]), "r"(a[3]), "r"(b0), "r"(b1));
}
// byte offset of (row, 16B-chunk) in a [rows][64 bf16] tile, xor swizzle
__device__ __forceinline__ uint32_t swz(int row, int ch) {
    uint32_t off = (uint32_t)(row * 128 + ch * 16);
    return off ^ (((uint32_t)row & 7u) << 4);
}

// ---------------- scratch (device globals: allocation-free rule) -----------
__device__ int g_mask_kind;                      // 0=uint8, else 4-byte elems
__device__ __align__(16) u64 g_mbits[MWORDS];    // packed mask bits
__device__ __align__(16) __nv_bfloat16 g_qh[BSDq];
__device__ __align__(16) __nv_bfloat16 g_ql[BSDq];
__device__ __align__(16) __nv_bfloat16 g_kh[BSDq];
__device__ __align__(16) __nv_bfloat16 g_kl[BSDq];
__device__ __align__(16) __nv_bfloat16 g_vh[BSDq];
__device__ __align__(16) __nv_bfloat16 g_vl[BSDq];
__device__ __align__(16) __nv_bfloat16 g_xhi[BSDq];
__device__ __align__(16) __nv_bfloat16 g_xlo[BSDq];
__device__ __align__(16) __nv_bfloat16 g_whi[Dq * Dq];
__device__ __align__(16) __nv_bfloat16 g_wlo[Dq * Dq];

// ---------------------------------------------------------------------------
__global__ void detect_mask_kernel(const unsigned char* __restrict__ m) {
    if (threadIdx.x != 0) return;
    int c0 = 0, c1 = 0, c2 = 0, c3 = 0;
    for (int i = 0; i < 4096; i += 4) {
        if (m[i + 0]) c0++;
        if (m[i + 1]) c1++;
        if (m[i + 2]) c2++;
        if (m[i + 3]) c3++;
    }
    int kind;
    if (c1 == 0 && c2 == 0 && c3 == 0) kind = 1;   // int32
    else if (c0 == 0 && c1 == 0)       kind = 2;   // float32
    else                               kind = 0;   // uint8
    g_mask_kind = kind;
}

// pack mask -> 64-bit words (bit j = element j nonzero)
__global__ __launch_bounds__(256)
void mask_bits_kernel(const void* __restrict__ mask) {
    int w = blockIdx.x * 256 + threadIdx.x;
    if (w >= MWORDS) return;
    u64 bits = 0;
    if (g_mask_kind == 0) {
        const uint4* p = (const uint4*)((const unsigned char*)mask + (size_t)w * 64);
#pragma unroll
        for (int q = 0; q < 4; q++) {
            uint4 v = p[q];
            const uint32_t ww[4] = {v.x, v.y, v.z, v.w};
#pragma unroll
            for (int k = 0; k < 4; k++)
#pragma unroll
                for (int j = 0; j < 4; j++)
                    if ((ww[k] >> (8 * j)) & 0xffu)
                        bits |= 1ull << (q * 16 + k * 4 + j);
        }
    } else {   // 4-byte elements (int32 or float32; nonzero bits == true)
        const uint4* p = (const uint4*)((const uint32_t*)mask + (size_t)w * 64);
#pragma unroll
        for (int q = 0; q < 16; q++) {
            uint4 v = p[q];
            if (v.x) bits |= 1ull << (q * 4 + 0);
            if (v.y) bits |= 1ull << (q * 4 + 1);
            if (v.z) bits |= 1ull << (q * 4 + 2);
            if (v.w) bits |= 1ull << (q * 4 + 3);
        }
    }
    g_mbits[w] = bits;
}

// fp32 -> bf16 hi/lo split
__global__ __launch_bounds__(256)
void split_kernel(const float* __restrict__ x, __nv_bfloat16* __restrict__ hi,
                  __nv_bfloat16* __restrict__ lo, int n)
{
    int i = (blockIdx.x * 256 + threadIdx.x) * 4;
    if (i >= n) return;
    float4 v = *(const float4*)(x + i);
    __nv_bfloat16 h0 = __float2bfloat16(v.x), h1 = __float2bfloat16(v.y);
    __nv_bfloat16 h2 = __float2bfloat16(v.z), h3 = __float2bfloat16(v.w);
    __nv_bfloat162 hA, hB, lA, lB;
    hA.x = h0; hA.y = h1; hB.x = h2; hB.y = h3;
    lA.x = __float2bfloat16(v.x - __bfloat162float(h0));
    lA.y = __float2bfloat16(v.y - __bfloat162float(h1));
    lB.x = __float2bfloat16(v.z - __bfloat162float(h2));
    lB.y = __float2bfloat16(v.w - __bfloat162float(h3));
    *(__nv_bfloat162*)(hi + i)     = hA;
    *(__nv_bfloat162*)(hi + i + 2) = hB;
    *(__nv_bfloat162*)(lo + i)     = lA;
    *(__nv_bfloat162*)(lo + i + 2) = lB;
}

// ---------------------------------------------------------------------------
// HMMA split-bf16 GEMM: X @ W^T. Output either fp32 (+bias) or split bf16.
// Mainloop: R6-proven order (load next, commit, wait(1), sync, compute, sync)
// -- the wait-count depends on this exact issue order.
// ---------------------------------------------------------------------------
#define GSTAGE  65536
#define GA_HI   0
#define GA_LO   16384
#define GB_HI   32768
#define GB_LO   49152
#define GSMEM   (2*GSTAGE)

__global__ __launch_bounds__(256, 1)
void gemm_tc_kernel(const __nv_bfloat16* __restrict__ Ahi,
                    const __nv_bfloat16* __restrict__ Alo,
                    const __nv_bfloat16* __restrict__ Bhi,
                    const __nv_bfloat16* __restrict__ Blo,
                    const float* __restrict__ bias, float* __restrict__ out32,
                    __nv_bfloat16* __restrict__ outh,
                    __nv_bfloat16* __restrict__ outl, float scale,
                    int M, int N, int K)
{
    extern __shared__ char smem[];
    const uint32_t sbase = smem_u32(smem);
    const int tid  = threadIdx.x;
    const int wid  = tid >> 5;
    const int lane = tid & 31;
    const int m0 = blockIdx.y * 128;
    const int n0 = blockIdx.x * 128;
    const int wm = wid & 1;
    const int wn = wid >> 1;

    float acc[4][4][4];
#pragma unroll
    for (int i = 0; i < 4; i++)
#pragma unroll
        for (int j = 0; j < 4; j++)
#pragma unroll
            for (int c = 0; c < 4; c++) acc[i][j][c] = 0.f;

    int lrow[4], lch[4];
#pragma unroll
    for (int l = 0; l < 4; l++) {
        int idx = l * 256 + tid;
        lrow[l] = idx >> 3;
        lch[l]  = idx & 7;
    }

    auto load_stage = [&](int t, int buf) {
        const int k0 = t * 64;
        const uint32_t sb = sbase + buf * GSTAGE;
#pragma unroll
        for (int l = 0; l < 4; l++) {
            uint32_t sw = swz(lrow[l], lch[l]);
            size_t ao = (size_t)(m0 + lrow[l]) * K + k0 + lch[l] * 8;
            size_t bo = (size_t)(n0 + lrow[l]) * K + k0 + lch[l] * 8;
            cp_async16(sb + GA_HI + sw, Ahi + ao);
            cp_async16(sb + GA_LO + sw, Alo + ao);
            cp_async16(sb + GB_HI + sw, Bhi + bo);
            cp_async16(sb + GB_LO + sw, Blo + bo);
        }
    };

    load_stage(0, 0);
    CP_COMMIT();

    const int NT = K / 64;
#pragma unroll 1
    for (int t = 0; t < NT; t++) {
        const int buf = t & 1;
        if (t + 1 < NT) {
            load_stage(t + 1, (t + 1) & 1);
            CP_COMMIT();
            CP_WAIT(1);        // 2 groups in flight -> drains the older (buf t)
        } else {
            CP_WAIT(0);
        }
        __syncthreads();

        const uint32_t sb = sbase + buf * GSTAGE;
        const int arow = wm * 64 + (lane & 15);
        const int brow = wn * 32 + (lane & 15);
#pragma unroll
        for (int ks = 0; ks < 4; ks++) {
            const int ch = ks * 2 + (lane >> 4);
            uint32_t ah[4][4], al[4][4];
#pragma unroll
            for (int mt = 0; mt < 4; mt++) {
                uint32_t sw = swz(arow + mt * 16, ch);
                ldsm4(ah[mt], sb + GA_HI + sw);
                ldsm4(al[mt], sb + GA_LO + sw);
            }
            uint32_t bh[2][4], bl[2][4];
#pragma unroll
            for (int nb = 0; nb < 2; nb++) {
                uint32_t sw = swz(brow + nb * 16, ch);
                ldsm4(bh[nb], sb + GB_HI + sw);
                ldsm4(bl[nb], sb + GB_LO + sw);
            }
#pragma unroll
            for (int mt = 0; mt < 4; mt++)
#pragma unroll
                for (int nt = 0; nt < 4; nt++) {
                    const int nb = nt >> 1, hh = nt & 1;
                    mma16816(acc[mt][nt], ah[mt], bh[nb][hh], bh[nb][2 + hh]);
                    mma16816(acc[mt][nt], ah[mt], bl[nb][hh], bl[nb][2 + hh]);
                    mma16816(acc[mt][nt], al[mt], bh[nb][hh], bh[nb][2 + hh]);
                }
        }
        __syncthreads();       // compute(t) done before load_stage(t+2) -> buf t
    }

#pragma unroll
    for (int mt = 0; mt < 4; mt++) {
#pragma unroll
        for (int nt = 0; nt < 4; nt++) {
            int row = m0 + wm * 64 + mt * 16 + (lane >> 2);
            int col = n0 + wn * 32 + nt * 8 + (lane & 3) * 2;
            if (out32) {
                float2 v0, v1;
                v0.x = acc[mt][nt][0]; v0.y = acc[mt][nt][1];
                v1.x = acc[mt][nt][2]; v1.y = acc[mt][nt][3];
                if (bias) {
                    float b0 = bias[col], b1 = bias[col + 1];
                    v0.x += b0; v0.y += b1;
                    v1.x += b0; v1.y += b1;
                }
                *(float2*)(out32 + (size_t)row * N + col)       = v0;
                *(float2*)(out32 + (size_t)(row + 8) * N + col) = v1;
            } else {
#pragma unroll
                for (int rr = 0; rr < 2; rr++) {
                    size_t o = (size_t)(row + rr * 8) * N + col;
                    float x0 = acc[mt][nt][rr * 2 + 0] * scale;
                    float x1 = acc[mt][nt][rr * 2 + 1] * scale;
                    __nv_bfloat162 hv, lv;
                    hv.x = __float2bfloat16(x0);
                    hv.y = __float2bfloat16(x1);
                    lv.x = __float2bfloat16(x0 - __bfloat162float(hv.x));
                    lv.y = __float2bfloat16(x1 - __bfloat162float(hv.y));
                    *(__nv_bfloat162*)(outh + o) = hv;
                    *(__nv_bfloat162*)(outl + o) = lv;
                }
            }
        }
    }
}

// ---------------------------------------------------------------------------
// HMMA flash attention (R6 structure) + packed-bitmask mask:
// S fragments -> fp32 smem -> half-row P-phase (1 u64 bitmask load, exp,
// row-sum, bf16 hi/lo split) -> PV via ldmatrix. 3 barriers per k-tile.
// ---------------------------------------------------------------------------
#define AS_QH   0
#define AS_QL   16384
#define AS_K    32768                 // [buf][hi 8192 | lo 8192] x2
#define AS_V    65536
#define AS_S    98304                 // fp32 [128][68]
#define AS_PH   (98304 + 34816)      // 133120
#define AS_PL   (AS_PH + 16384)      // 149504
#define AS_DEN  (AS_PL + 16384)      // 165888 : 256 floats
#define ATT_SMEM (AS_DEN + 1024)

__global__ __launch_bounds__(256, 1)
void attention_tc_kernel(float* __restrict__ resT,
                         __nv_bfloat16* __restrict__ ctx_h,
                         __nv_bfloat16* __restrict__ ctx_l)
{
    extern __shared__ char smem[];
    const uint32_t sbase = smem_u32(smem);
    float* sS   = (float*)(smem + AS_S);
    float* sDen = (float*)(smem + AS_DEN);

    const int tid  = threadIdx.x;
    const int wid  = tid >> 5;
    const int lane = tid & 31;
    const int wm = wid & 1;        // 2 m-warps (64 q-rows)
    const int wn = wid >> 1;       // 4 n-warps (16 k-cols)
    const int blk = blockIdx.x;
    const int qt  = blk & 15;
    const int h   = (blk >> 4) & 15;
    const int b   = blk >> 8;
    const int q0  = qt * 128;

    const size_t headBase = (size_t)b * Sq * Dq + (size_t)h * Sq * DHq;
    const __nv_bfloat16* Qh = g_qh + headBase;
    const __nv_bfloat16* Ql = g_ql + headBase;
    const __nv_bfloat16* Kh = g_kh + headBase;
    const __nv_bfloat16* Kl = g_kl + headBase;
    const __nv_bfloat16* Vh = g_vh + headBase;
    const __nv_bfloat16* Vl = g_vl + headBase;

    // ---- initial loads: Q (persistent) + K/V stage 0, all cp.async ----
#pragma unroll
    for (int l = 0; l < 4; l++) {
        int idx = l * 256 + tid;
        int row = idx >> 3, ch = idx & 7;
        uint32_t sw = swz(row, ch);
        size_t o = (size_t)(q0 + row) * DHq + ch * 8;
        cp_async16(sbase + AS_QH + sw, Qh + o);
        cp_async16(sbase + AS_QL + sw, Ql + o);
    }
#pragma unroll
    for (int l = 0; l < 2; l++) {
        int id2 = l * 256 + tid;
        int row = id2 >> 3, ch = id2 & 7;
        uint32_t sw = swz(row, ch);
        size_t o = (size_t)row * DHq + ch * 8;
        cp_async16(sbase + AS_K + sw,        Kh + o);
        cp_async16(sbase + AS_K + 8192 + sw, Kl + o);
        cp_async16(sbase + AS_V + sw,        Vh + o);
        cp_async16(sbase + AS_V + 8192 + sw, Vl + o);
    }
    CP_COMMIT();

    float oacc[4][2][4];
#pragma unroll
    for (int mt = 0; mt < 4; mt++)
#pragma unroll
        for (int nt = 0; nt < 2; nt++)
#pragma unroll
            for (int c = 0; c < 4; c++) oacc[mt][nt][c] = 0.f;
    float denAcc = 0.f;

    const int prow = tid >> 1;           // P-phase: half-row per thread
    const int pcol = (tid & 1) * 32;
    const u64* mrowPtr = g_mbits + ((size_t)b * Sq + q0 + prow) * (Sq / 64);

    const int arow = wm * 64 + (lane & 15);
    const int brow = wn * 16 + (lane & 15);
    const int vrow0 = (lane & 7) + ((lane >> 4) << 3);
    const int vch   = wn * 2 + ((lane >> 3) & 1);

    const int NT = Sq / 64;
#pragma unroll 1
    for (int kt = 0; kt < NT; kt++) {
        const int buf = kt & 1;
        CP_WAIT(0);
        __syncthreads();   // K/V[buf] ready; prev PV reads of this buf done

        // prefetch next K/V stage
        if (kt + 1 < NT) {
            const uint32_t kb = sbase + AS_K + (1 - buf) * 16384;
            const uint32_t vb = sbase + AS_V + (1 - buf) * 16384;
            const size_t gk = (size_t)(kt + 1) * 64 * DHq;
#pragma unroll
            for (int l = 0; l < 2; l++) {
                int id2 = l * 256 + tid;
                int row = id2 >> 3, ch = id2 & 7;
                uint32_t sw = swz(row, ch);
                size_t o = gk + (size_t)row * DHq + ch * 8;
                cp_async16(kb + sw,        Kh + o);
                cp_async16(kb + 8192 + sw, Kl + o);
                cp_async16(vb + sw,        Vh + o);
                cp_async16(vb + 8192 + sw, Vl + o);
            }
            CP_COMMIT();
        }

        // mask word for this thread's half-row (single L2-resident load)
        const uint32_t mbits = (uint32_t)(mrowPtr[kt] >> pcol);

        // ---- S = Q K^T (3-term split) ----
        float sacc[4][2][4];
#pragma unroll
        for (int mt = 0; mt < 4; mt++)
#pragma unroll
            for (int nt = 0; nt < 2; nt++)
#pragma unroll
                for (int c = 0; c < 4; c++) sacc[mt][nt][c] = 0.f;

        const uint32_t kbh = sbase + AS_K + buf * 16384;
        const uint32_t kbl = kbh + 8192;
#pragma unroll
        for (int ks = 0; ks < 4; ks++) {
            const int ch = ks * 2 + (lane >> 4);
            uint32_t ah[4][4], al[4][4];
#pragma unroll
            for (int mt = 0; mt < 4; mt++) {
                uint32_t sw = swz(arow + mt * 16, ch);
                ldsm4(ah[mt], sbase + AS_QH + sw);
                ldsm4(al[mt], sbase + AS_QL + sw);
            }
            uint32_t bh[4], bl[4];
            {
                uint32_t sw = swz(brow, ch);
                ldsm4(bh, kbh + sw);
                ldsm4(bl, kbl + sw);
            }
#pragma unroll
            for (int mt = 0; mt < 4; mt++)
#pragma unroll
                for (int hh = 0; hh < 2; hh++) {
                    mma16816(sacc[mt][hh], ah[mt], bh[hh], bh[2 + hh]);
                    mma16816(sacc[mt][hh], ah[mt], bl[hh], bl[2 + hh]);
                    mma16816(sacc[mt][hh], al[mt], bh[hh], bh[2 + hh]);
                }
        }

        // ---- store S fragments to smem (fp32) ----
#pragma unroll
        for (int mt = 0; mt < 4; mt++)
#pragma unroll
            for (int nt = 0; nt < 2; nt++) {
                int r0 = wm * 64 + mt * 16 + (lane >> 2);
                int c0 = wn * 16 + nt * 8 + (lane & 3) * 2;
                float2 v0, v1;
                v0.x = sacc[mt][nt][0]; v0.y = sacc[mt][nt][1];
                v1.x = sacc[mt][nt][2]; v1.y = sacc[mt][nt][3];
                *(float2*)&sS[r0 * 68 + c0]       = v0;
                *(float2*)&sS[(r0 + 8) * 68 + c0] = v1;
            }
        __syncthreads();

        // ---- P = bit ? exp(S) : 0 ; row-sums ; split bf16 to smem ----
#pragma unroll
        for (int chk = 0; chk < 4; chk++) {
            int cb = pcol + chk * 8;
            float4 x0 = *(const float4*)&sS[prow * 68 + cb];
            float4 x1 = *(const float4*)&sS[prow * 68 + cb + 4];
            float p[8];
            p[0] = __expf(x0.x); p[1] = __expf(x0.y);
            p[2] = __expf(x0.z); p[3] = __expf(x0.w);
            p[4] = __expf(x1.x); p[5] = __expf(x1.y);
            p[6] = __expf(x1.z); p[7] = __expf(x1.w);
#pragma unroll
            for (int j = 0; j < 8; j++) {
                if (!((mbits >> (chk * 8 + j)) & 1u)) p[j] = 0.f;
                denAcc += p[j];
            }
            uint32_t hv[4], lv[4];
#pragma unroll
            for (int j = 0; j < 4; j++) {
                __nv_bfloat162 h2, l2;
                h2.x = __float2bfloat16(p[2 * j]);
                h2.y = __float2bfloat16(p[2 * j + 1]);
                l2.x = __float2bfloat16(p[2 * j]     - __bfloat162float(h2.x));
                l2.y = __float2bfloat16(p[2 * j + 1] - __bfloat162float(h2.y));
                hv[j] = *(uint32_t*)&h2;
                lv[j] = *(uint32_t*)&l2;
            }
            uint32_t sw = swz(prow, (tid & 1) * 4 + chk);
            *(uint4*)(smem + AS_PH + sw) = *(uint4*)hv;
            *(uint4*)(smem + AS_PL + sw) = *(uint4*)lv;
        }
        __syncthreads();

        // ---- O += P V (3-term split; V via ldmatrix.trans) ----
        const uint32_t vbh = sbase + AS_V + buf * 16384;
        const uint32_t vbl = vbh + 8192;
#pragma unroll
        for (int ks = 0; ks < 4; ks++) {
            const int ch = ks * 2 + (lane >> 4);
            uint32_t ah[4][4], al[4][4];
#pragma unroll
            for (int mt = 0; mt < 4; mt++) {
                uint32_t sw = swz(arow + mt * 16, ch);
                ldsm4(ah[mt], sbase + AS_PH + sw);
                ldsm4(al[mt], sbase + AS_PL + sw);
            }
            uint32_t bh[4], bl[4];
            {
                uint32_t sw = swz(ks * 16 + vrow0, vch);
                ldsm4t(bh, vbh + sw);
                ldsm4t(bl, vbl + sw);
            }
#pragma unroll
            for (int mt = 0; mt < 4; mt++)
#pragma unroll
                for (int hh = 0; hh < 2; hh++) {
                    mma16816(oacc[mt][hh], ah[mt], bh[hh], bh[2 + hh]);
                    mma16816(oacc[mt][hh], ah[mt], bl[hh], bl[2 + hh]);
                    mma16816(oacc[mt][hh], al[mt], bh[hh], bh[2 + hh]);
                }
        }
    }

    // ---- epilogue: normalize, write split context + resT ----
    sDen[tid] = denAcc;
    __syncthreads();

#pragma unroll
    for (int mt = 0; mt < 4; mt++)
#pragma unroll
        for (int nt = 0; nt < 2; nt++)
#pragma unroll
            for (int rr = 0; rr < 2; rr++) {
                int r   = wm * 64 + mt * 16 + (lane >> 2) + rr * 8;
                int col = wn * 16 + nt * 8 + (lane & 3) * 2;
                float dn  = sDen[2 * r] + sDen[2 * r + 1];
                float inv = dn > 0.f ? 1.f / dn : 0.f;     // NaN->0 semantics
                float x0 = oacc[mt][nt][rr * 2 + 0] * inv;
                float x1 = oacc[mt][nt][rr * 2 + 1] * inv;
                int s2 = q0 + r;
                size_t co = ((size_t)b * Sq + s2) * Dq + h * DHq + col;
                __nv_bfloat162 hv, lv;
                hv.x = __float2bfloat16(x0);
                hv.y = __float2bfloat16(x1);
                lv.x = __float2bfloat16(x0 - __bfloat162float(hv.x));
                lv.y = __float2bfloat16(x1 - __bfloat162float(hv.y));
                *(__nv_bfloat162*)(ctx_h + co) = hv;
                *(__nv_bfloat162*)(ctx_l + co) = lv;
                if (resT) {
                    float2 rv; rv.x = x0; rv.y = x1;
                    *(float2*)(resT + (((size_t)h * Bq + b) * Sq + s2) * DHq + col) = rv;
                }
            }
}

// ---------------------------------------------------------------------------
extern "C" void kernel_launch(void* const* d_in, const int* in_sizes, int n_in,
                              void* d_out, int out_size)
{
    const float* query = (const float*)d_in[0];
    const float* key_  = (const float*)d_in[1];
    const float* value = (const float*)d_in[2];
    const void*  mask  = d_in[3];
    const float* Wq    = (const float*)d_in[4];
    const float* Wk    = (const float*)d_in[5];
    const float* Wv    = (const float*)d_in[6];
    const float* fcw   = (const float*)d_in[7];
    const float* fcb   = (const float*)d_in[8];
    float* out = (float*)d_out;

    __nv_bfloat16 *qh, *ql, *kh, *kl, *vh, *vl, *xhi, *xlo, *whi, *wlo;
    cudaGetSymbolAddress((void**)&qh,  g_qh);
    cudaGetSymbolAddress((void**)&ql,  g_ql);
    cudaGetSymbolAddress((void**)&kh,  g_kh);
    cudaGetSymbolAddress((void**)&kl,  g_kl);
    cudaGetSymbolAddress((void**)&vh,  g_vh);
    cudaGetSymbolAddress((void**)&vl,  g_vl);
    cudaGetSymbolAddress((void**)&xhi, g_xhi);
    cudaGetSymbolAddress((void**)&xlo, g_xlo);
    cudaGetSymbolAddress((void**)&whi, g_whi);
    cudaGetSymbolAddress((void**)&wlo, g_wlo);

    cudaFuncSetAttribute(gemm_tc_kernel,
                         cudaFuncAttributeMaxDynamicSharedMemorySize, GSMEM);
    cudaFuncSetAttribute(attention_tc_kernel,
                         cudaFuncAttributeMaxDynamicSharedMemorySize, ATT_SMEM);

    detect_mask_kernel<<<1, 32>>>((const unsigned char*)mask);
    mask_bits_kernel<<<MWORDS / 256, 256>>>(mask);

    const int M = Bq * Sq;               // 8192
    dim3 gtc(Dq / 128, M / 128);         // (8, 64)
    const int nX = M * Dq, nW = Dq * Dq;
    const int bX = nX / 4 / 256, bW = nW / 4 / 256;

    // Q projection (pre-scaled by 1/8), K, V -> split bf16 outputs
    split_kernel<<<bX, 256>>>(query, xhi, xlo, nX);
    split_kernel<<<bW, 256>>>(Wq, whi, wlo, nW);
    gemm_tc_kernel<<<gtc, 256, GSMEM>>>(xhi, xlo, whi, wlo, nullptr, nullptr,
                                        qh, ql, 0.125f, M, Dq, Dq);

    split_kernel<<<bX, 256>>>(key_, xhi, xlo, nX);
    split_kernel<<<bW, 256>>>(Wk, whi, wlo, nW);
    gemm_tc_kernel<<<gtc, 256, GSMEM>>>(xhi, xlo, whi, wlo, nullptr, nullptr,
                                        kh, kl, 1.0f, M, Dq, Dq);

    split_kernel<<<bX, 256>>>(value, xhi, xlo, nX);
    split_kernel<<<bW, 256>>>(Wv, whi, wlo, nW);
    gemm_tc_kernel<<<gtc, 256, GSMEM>>>(xhi, xlo, whi, wlo, nullptr, nullptr,
                                        vh, vl, 1.0f, M, Dq, Dq);

    // attention writes context split into xhi/xlo + resT fp32
    float* resT = (out_size >= 2 * BSDq) ? (out + BSDq) : nullptr;
    attention_tc_kernel<<<Bq * Hq * (Sq / 128), 256, ATT_SMEM>>>(resT, xhi, xlo);

    // final FC: fp32 out with bias
    split_kernel<<<bW, 256>>>(fcw, whi, wlo, nW);
    gemm_tc_kernel<<<gtc, 256, GSMEM>>>(xhi, xlo, whi, wlo, fcb, out,
                                        nullptr, nullptr, 1.0f, M, Dq, Dq);
}

// round 10
// speedup vs baseline: 1.7387x; 1.0276x over previous
#include <cuda_runtime.h>
#include <cuda_bf16.h>
#include <cstdint>
#include <cstddef>

// Problem constants
#define Bq   4
#define Sq   2048
#define Dq   1024
#define Hq   16
#define DHq  64
#define BSDq (Bq*Sq*Dq)   // 8388608
#define MWORDS (Bq*Sq*(Sq/64))   // 262144 u64 mask words

typedef unsigned long long u64;

// ---------------- generic-PTX tensor-core helpers (sm_80+ ISA) -------------
__device__ __forceinline__ uint32_t smem_u32(const void* p) {
    uint32_t a;
    asm("{ .reg .u64 t; cvta.to.shared.u64 t, %1; cvt.u32.u64 %0, t; }"
        : "=r"(a) : "l"(p));
    return a;
}
__device__ __forceinline__ void cp_async16(uint32_t s, const void* g) {
    asm volatile("cp.async.cg.shared.global [%0], [%1], 16;" :: "r"(s), "l"(g));
}
#define CP_COMMIT() asm volatile("cp.async.commit_group;" ::: "memory")
#define CP_WAIT(n)  asm volatile("cp.async.wait_group %0;" :: "n"(n) : "memory")

__device__ __forceinline__ void ldsm4(uint32_t* r, uint32_t addr) {
    asm volatile("ldmatrix.sync.aligned.m8n8.x4.shared.b16 {%0,%1,%2,%3}, [%4];"
                 : "=r"(r[0]), "=r"(r[1]), "=r"(r[2]), "=r"(r[3]) : "r"(addr));
}
__device__ __forceinline__ void ldsm4t(uint32_t* r, uint32_t addr) {
    asm volatile("ldmatrix.sync.aligned.m8n8.x4.trans.shared.b16 {%0,%1,%2,%3}, [%4];"
                 : "=r"(r[0]), "=r"(r[1]), "=r"(r[2]), "=r"(r[3]) : "r"(addr));
}
// D(f32) += A(bf16) * B(bf16); m16n8k16 row.col
__device__ __forceinline__ void mma16816(float* d, const uint32_t* a,
                                         uint32_t b0, uint32_t b1) {
    asm volatile(
        "mma.sync.aligned.m16n8k16.row.col.f32.bf16.bf16.f32 "
        "{%0,%1,%2,%3}, {%4,%5,%6,%7}, {%8,%9}, {%0,%1,%2,%3};"
        : "+f"(d[0]), "+f"(d[1]), "+f"(d[2]), "+f"(d[3])
        : "r"(a[0]), "r"(a[1]), "r"(a[2]), "r"(a[3]), "r"(b0), "r"(b1));
}
// byte offset of (row, 16B-chunk) in a [rows][64 bf16] tile, xor swizzle
__device__ __forceinline__ uint32_t swz(int row, int ch) {
    uint32_t off = (uint32_t)(row * 128 + ch * 16);
    return off ^ (((uint32_t)row & 7u) << 4);
}

// ---------------- scratch (device globals: allocation-free rule) -----------
__device__ int g_mask_kind;                      // 0=uint8, else 4-byte elems
__device__ __align__(16) u64 g_mbits[MWORDS];    // packed mask bits
__device__ __align__(16) __nv_bfloat16 g_qh[BSDq];
__device__ __align__(16) __nv_bfloat16 g_ql[BSDq];
__device__ __align__(16) __nv_bfloat16 g_kh[BSDq];
__device__ __align__(16) __nv_bfloat16 g_kl[BSDq];
__device__ __align__(16) __nv_bfloat16 g_vh[BSDq];
__device__ __align__(16) __nv_bfloat16 g_vl[BSDq];
__device__ __align__(16) __nv_bfloat16 g_xhi[BSDq];   // q split / ctx split
__device__ __align__(16) __nv_bfloat16 g_xlo[BSDq];
__device__ __align__(16) __nv_bfloat16 g_yhi[BSDq];   // k split
__device__ __align__(16) __nv_bfloat16 g_ylo[BSDq];
__device__ __align__(16) __nv_bfloat16 g_zhi[BSDq];   // v split
__device__ __align__(16) __nv_bfloat16 g_zlo[BSDq];
__device__ __align__(16) __nv_bfloat16 g_w1h[Dq * Dq]; // Wq
__device__ __align__(16) __nv_bfloat16 g_w1l[Dq * Dq];
__device__ __align__(16) __nv_bfloat16 g_w2h[Dq * Dq]; // Wk
__device__ __align__(16) __nv_bfloat16 g_w2l[Dq * Dq];
__device__ __align__(16) __nv_bfloat16 g_w3h[Dq * Dq]; // Wv
__device__ __align__(16) __nv_bfloat16 g_w3l[Dq * Dq];
__device__ __align__(16) __nv_bfloat16 g_w4h[Dq * Dq]; // fc_w
__device__ __align__(16) __nv_bfloat16 g_w4l[Dq * Dq];

// ---------------------------------------------------------------------------
__global__ void detect_mask_kernel(const unsigned char* __restrict__ m) {
    if (threadIdx.x != 0) return;
    int c0 = 0, c1 = 0, c2 = 0, c3 = 0;
    for (int i = 0; i < 4096; i += 4) {
        if (m[i + 0]) c0++;
        if (m[i + 1]) c1++;
        if (m[i + 2]) c2++;
        if (m[i + 3]) c3++;
    }
    int kind;
    if (c1 == 0 && c2 == 0 && c3 == 0) kind = 1;   // int32
    else if (c0 == 0 && c1 == 0)       kind = 2;   // float32
    else                               kind = 0;   // uint8
    g_mask_kind = kind;
}

// pack mask -> 64-bit words (bit j = element j nonzero)
__global__ __launch_bounds__(256)
void mask_bits_kernel(const void* __restrict__ mask) {
    int w = blockIdx.x * 256 + threadIdx.x;
    if (w >= MWORDS) return;
    u64 bits = 0;
    if (g_mask_kind == 0) {
        const uint4* p = (const uint4*)((const unsigned char*)mask + (size_t)w * 64);
#pragma unroll
        for (int q = 0; q < 4; q++) {
            uint4 v = p[q];
            const uint32_t ww[4] = {v.x, v.y, v.z, v.w};
#pragma unroll
            for (int k = 0; k < 4; k++)
#pragma unroll
                for (int j = 0; j < 4; j++)
                    if ((ww[k] >> (8 * j)) & 0xffu)
                        bits |= 1ull << (q * 16 + k * 4 + j);
        }
    } else {   // 4-byte elements
        const uint4* p = (const uint4*)((const uint32_t*)mask + (size_t)w * 64);
#pragma unroll
        for (int q = 0; q < 16; q++) {
            uint4 v = p[q];
            if (v.x) bits |= 1ull << (q * 4 + 0);
            if (v.y) bits |= 1ull << (q * 4 + 1);
            if (v.z) bits |= 1ull << (q * 4 + 2);
            if (v.w) bits |= 1ull << (q * 4 + 3);
        }
    }
    g_mbits[w] = bits;
}

// ---- batched fp32 -> bf16 hi/lo split for up to 8 tensors -----------------
struct SplitParams {
    const float* src[8];
    __nv_bfloat16* hi[8];
    __nv_bfloat16* lo[8];
    int blkStart[9];   // cumulative block offsets
    int nT;
};

__global__ __launch_bounds__(256)
void split_all_kernel(SplitParams P)
{
    int blk = blockIdx.x;
    int t = 0;
    while (t + 1 < P.nT && blk >= P.blkStart[t + 1]) t++;
    int i = (blk - P.blkStart[t]) * 256 * 4 + threadIdx.x * 4;
    const float* x = P.src[t];
    float4 v = *(const float4*)(x + i);
    __nv_bfloat16 h0 = __float2bfloat16(v.x), h1 = __float2bfloat16(v.y);
    __nv_bfloat16 h2 = __float2bfloat16(v.z), h3 = __float2bfloat16(v.w);
    __nv_bfloat162 hA, hB, lA, lB;
    hA.x = h0; hA.y = h1; hB.x = h2; hB.y = h3;
    lA.x = __float2bfloat16(v.x - __bfloat162float(h0));
    lA.y = __float2bfloat16(v.y - __bfloat162float(h1));
    lB.x = __float2bfloat16(v.z - __bfloat162float(h2));
    lB.y = __float2bfloat16(v.w - __bfloat162float(h3));
    *(__nv_bfloat162*)(P.hi[t] + i)     = hA;
    *(__nv_bfloat162*)(P.hi[t] + i + 2) = hB;
    *(__nv_bfloat162*)(P.lo[t] + i)     = lA;
    *(__nv_bfloat162*)(P.lo[t] + i + 2) = lB;
}

// ---------------------------------------------------------------------------
// Shared HMMA split-bf16 GEMM core: X @ W^T (128x128 CTA tile), fragment
// double-buffered inner loop (ldsm for ks+1 issued before mma of ks).
// ---------------------------------------------------------------------------
#define GSTAGE  65536
#define GA_HI   0
#define GA_LO   16384
#define GB_HI   32768
#define GB_LO   49152
#define GSMEM   (2*GSTAGE)

__device__ __forceinline__ void gemm_core(
    const __nv_bfloat16* __restrict__ Ahi, const __nv_bfloat16* __restrict__ Alo,
    const __nv_bfloat16* __restrict__ Bhi, const __nv_bfloat16* __restrict__ Blo,
    const float* __restrict__ bias, float* __restrict__ out32,
    __nv_bfloat16* __restrict__ outh, __nv_bfloat16* __restrict__ outl,
    float scale, int M, int N, int K, char* smem)
{
    const uint32_t sbase = smem_u32(smem);
    const int tid  = threadIdx.x;
    const int wid  = tid >> 5;
    const int lane = tid & 31;
    const int m0 = blockIdx.y * 128;
    const int n0 = blockIdx.x * 128;
    const int wm = wid & 1;
    const int wn = wid >> 1;

    float acc[4][4][4];
#pragma unroll
    for (int i = 0; i < 4; i++)
#pragma unroll
        for (int j = 0; j < 4; j++)
#pragma unroll
            for (int c = 0; c < 4; c++) acc[i][j][c] = 0.f;

    int lrow[4], lch[4];
#pragma unroll
    for (int l = 0; l < 4; l++) {
        int idx = l * 256 + tid;
        lrow[l] = idx >> 3;
        lch[l]  = idx & 7;
    }

    auto load_stage = [&](int t, int buf) {
        const int k0 = t * 64;
        const uint32_t sb = sbase + buf * GSTAGE;
#pragma unroll
        for (int l = 0; l < 4; l++) {
            uint32_t sw = swz(lrow[l], lch[l]);
            size_t ao = (size_t)(m0 + lrow[l]) * K + k0 + lch[l] * 8;
            size_t bo = (size_t)(n0 + lrow[l]) * K + k0 + lch[l] * 8;
            cp_async16(sb + GA_HI + sw, Ahi + ao);
            cp_async16(sb + GA_LO + sw, Alo + ao);
            cp_async16(sb + GB_HI + sw, Bhi + bo);
            cp_async16(sb + GB_LO + sw, Blo + bo);
        }
    };

    load_stage(0, 0);
    CP_COMMIT();

    const int arow = wm * 64 + (lane & 15);
    const int brow = wn * 32 + (lane & 15);

    const int NT = K / 64;
#pragma unroll 1
    for (int t = 0; t < NT; t++) {
        const int buf = t & 1;
        if (t + 1 < NT) {
            load_stage(t + 1, (t + 1) & 1);
            CP_COMMIT();
            CP_WAIT(1);        // 2 groups in flight -> drains the older (buf t)
        } else {
            CP_WAIT(0);
        }
        __syncthreads();

        const uint32_t sb = sbase + buf * GSTAGE;
        // fragment double buffers
        uint32_t ah[2][4][4], al[2][4][4], bh[2][2][4], bl[2][2][4];
        auto load_frag = [&](int ks, int fb) {
            const int ch = ks * 2 + (lane >> 4);
#pragma unroll
            for (int mt = 0; mt < 4; mt++) {
                uint32_t sw = swz(arow + mt * 16, ch);
                ldsm4(ah[fb][mt], sb + GA_HI + sw);
                ldsm4(al[fb][mt], sb + GA_LO + sw);
            }
#pragma unroll
            for (int nb = 0; nb < 2; nb++) {
                uint32_t sw = swz(brow + nb * 16, ch);
                ldsm4(bh[fb][nb], sb + GB_HI + sw);
                ldsm4(bl[fb][nb], sb + GB_LO + sw);
            }
        };
        load_frag(0, 0);
#pragma unroll
        for (int ks = 0; ks < 4; ks++) {
            const int fb = ks & 1;
            if (ks < 3) load_frag(ks + 1, fb ^ 1);
#pragma unroll
            for (int mt = 0; mt < 4; mt++)
#pragma unroll
                for (int nt = 0; nt < 4; nt++) {
                    const int nb = nt >> 1, hh = nt & 1;
                    mma16816(acc[mt][nt], ah[fb][mt], bh[fb][nb][hh], bh[fb][nb][2 + hh]);
                    mma16816(acc[mt][nt], ah[fb][mt], bl[fb][nb][hh], bl[fb][nb][2 + hh]);
                    mma16816(acc[mt][nt], al[fb][mt], bh[fb][nb][hh], bh[fb][nb][2 + hh]);
                }
        }
        __syncthreads();       // compute(t) done before load_stage(t+2) -> buf t
    }

#pragma unroll
    for (int mt = 0; mt < 4; mt++) {
#pragma unroll
        for (int nt = 0; nt < 4; nt++) {
            int row = m0 + wm * 64 + mt * 16 + (lane >> 2);
            int col = n0 + wn * 32 + nt * 8 + (lane & 3) * 2;
            if (out32) {
                float2 v0, v1;
                v0.x = acc[mt][nt][0]; v0.y = acc[mt][nt][1];
                v1.x = acc[mt][nt][2]; v1.y = acc[mt][nt][3];
                if (bias) {
                    float b0 = bias[col], b1 = bias[col + 1];
                    v0.x += b0; v0.y += b1;
                    v1.x += b0; v1.y += b1;
                }
                *(float2*)(out32 + (size_t)row * N + col)       = v0;
                *(float2*)(out32 + (size_t)(row + 8) * N + col) = v1;
            } else {
#pragma unroll
                for (int rr = 0; rr < 2; rr++) {
                    size_t o = (size_t)(row + rr * 8) * N + col;
                    float x0 = acc[mt][nt][rr * 2 + 0] * scale;
                    float x1 = acc[mt][nt][rr * 2 + 1] * scale;
                    __nv_bfloat162 hv, lv;
                    hv.x = __float2bfloat16(x0);
                    hv.y = __float2bfloat16(x1);
                    lv.x = __float2bfloat16(x0 - __bfloat162float(hv.x));
                    lv.y = __float2bfloat16(x1 - __bfloat162float(hv.y));
                    *(__nv_bfloat162*)(outh + o) = hv;
                    *(__nv_bfloat162*)(outl + o) = lv;
                }
            }
        }
    }
}

// single GEMM (FC): fp32 out + bias
__global__ __launch_bounds__(256, 1)
void gemm_tc_kernel(const __nv_bfloat16* __restrict__ Ahi,
                    const __nv_bfloat16* __restrict__ Alo,
                    const __nv_bfloat16* __restrict__ Bhi,
                    const __nv_bfloat16* __restrict__ Blo,
                    const float* __restrict__ bias, float* __restrict__ out32,
                    int M, int N, int K)
{
    extern __shared__ char smem[];
    gemm_core(Ahi, Alo, Bhi, Blo, bias, out32, nullptr, nullptr, 1.0f,
              M, N, K, smem);
}

// merged Q/K/V projection GEMMs: z selects the projection
struct QKVParams {
    const __nv_bfloat16 *Ahi[3], *Alo[3], *Bhi[3], *Blo[3];
    __nv_bfloat16 *oh[3], *ol[3];
    float scale[3];
};
__global__ __launch_bounds__(256, 1)
void gemm_qkv_kernel(QKVParams P, int M, int N, int K)
{
    extern __shared__ char smem[];
    const int z = blockIdx.z;
    gemm_core(P.Ahi[z], P.Alo[z], P.Bhi[z], P.Blo[z], nullptr, nullptr,
              P.oh[z], P.ol[z], P.scale[z], M, N, K, smem);
}

// ---------------------------------------------------------------------------
// HMMA flash attention + packed-bitmask softmax, fragment double-buffered.
// ---------------------------------------------------------------------------
#define AS_QH   0
#define AS_QL   16384
#define AS_K    32768                 // [buf][hi 8192 | lo 8192] x2
#define AS_V    65536
#define AS_S    98304                 // fp32 [128][68]
#define AS_PH   (98304 + 34816)      // 133120
#define AS_PL   (AS_PH + 16384)      // 149504
#define AS_DEN  (AS_PL + 16384)      // 165888 : 256 floats
#define ATT_SMEM (AS_DEN + 1024)

__global__ __launch_bounds__(256, 1)
void attention_tc_kernel(float* __restrict__ resT,
                         __nv_bfloat16* __restrict__ ctx_h,
                         __nv_bfloat16* __restrict__ ctx_l)
{
    extern __shared__ char smem[];
    const uint32_t sbase = smem_u32(smem);
    float* sS   = (float*)(smem + AS_S);
    float* sDen = (float*)(smem + AS_DEN);

    const int tid  = threadIdx.x;
    const int wid  = tid >> 5;
    const int lane = tid & 31;
    const int wm = wid & 1;        // 2 m-warps (64 q-rows)
    const int wn = wid >> 1;       // 4 n-warps (16 k-cols)
    const int blk = blockIdx.x;
    const int qt  = blk & 15;
    const int h   = (blk >> 4) & 15;
    const int b   = blk >> 8;
    const int q0  = qt * 128;

    const size_t headBase = (size_t)b * Sq * Dq + (size_t)h * Sq * DHq;
    const __nv_bfloat16* Qh = g_qh + headBase;
    const __nv_bfloat16* Ql = g_ql + headBase;
    const __nv_bfloat16* Kh = g_kh + headBase;
    const __nv_bfloat16* Kl = g_kl + headBase;
    const __nv_bfloat16* Vh = g_vh + headBase;
    const __nv_bfloat16* Vl = g_vl + headBase;

    // ---- initial loads: Q (persistent) + K/V stage 0, all cp.async ----
#pragma unroll
    for (int l = 0; l < 4; l++) {
        int idx = l * 256 + tid;
        int row = idx >> 3, ch = idx & 7;
        uint32_t sw = swz(row, ch);
        size_t o = (size_t)(q0 + row) * DHq + ch * 8;
        cp_async16(sbase + AS_QH + sw, Qh + o);
        cp_async16(sbase + AS_QL + sw, Ql + o);
    }
#pragma unroll
    for (int l = 0; l < 2; l++) {
        int id2 = l * 256 + tid;
        int row = id2 >> 3, ch = id2 & 7;
        uint32_t sw = swz(row, ch);
        size_t o = (size_t)row * DHq + ch * 8;
        cp_async16(sbase + AS_K + sw,        Kh + o);
        cp_async16(sbase + AS_K + 8192 + sw, Kl + o);
        cp_async16(sbase + AS_V + sw,        Vh + o);
        cp_async16(sbase + AS_V + 8192 + sw, Vl + o);
    }
    CP_COMMIT();

    float oacc[4][2][4];
#pragma unroll
    for (int mt = 0; mt < 4; mt++)
#pragma unroll
        for (int nt = 0; nt < 2; nt++)
#pragma unroll
            for (int c = 0; c < 4; c++) oacc[mt][nt][c] = 0.f;
    float denAcc = 0.f;

    const int prow = tid >> 1;           // P-phase: half-row per thread
    const int pcol = (tid & 1) * 32;
    const u64* mrowPtr = g_mbits + ((size_t)b * Sq + q0 + prow) * (Sq / 64);

    const int arow = wm * 64 + (lane & 15);
    const int brow = wn * 16 + (lane & 15);
    const int vrow0 = (lane & 7) + ((lane >> 4) << 3);
    const int vch   = wn * 2 + ((lane >> 3) & 1);

    const int NT = Sq / 64;
#pragma unroll 1
    for (int kt = 0; kt < NT; kt++) {
        const int buf = kt & 1;
        CP_WAIT(0);
        __syncthreads();   // K/V[buf] ready; prev PV reads of this buf done

        // prefetch next K/V stage
        if (kt + 1 < NT) {
            const uint32_t kb = sbase + AS_K + (1 - buf) * 16384;
            const uint32_t vb = sbase + AS_V + (1 - buf) * 16384;
            const size_t gk = (size_t)(kt + 1) * 64 * DHq;
#pragma unroll
            for (int l = 0; l < 2; l++) {
                int id2 = l * 256 + tid;
                int row = id2 >> 3, ch = id2 & 7;
                uint32_t sw = swz(row, ch);
                size_t o = gk + (size_t)row * DHq + ch * 8;
                cp_async16(kb + sw,        Kh + o);
                cp_async16(kb + 8192 + sw, Kl + o);
                cp_async16(vb + sw,        Vh + o);
                cp_async16(vb + 8192 + sw, Vl + o);
            }
            CP_COMMIT();
        }

        // mask word for this thread's half-row (single L2-resident load)
        const uint32_t mbits = (uint32_t)(mrowPtr[kt] >> pcol);

        // ---- S = Q K^T (3-term split, fragment double-buffered) ----
        float sacc[4][2][4];
#pragma unroll
        for (int mt = 0; mt < 4; mt++)
#pragma unroll
            for (int nt = 0; nt < 2; nt++)
#pragma unroll
                for (int c = 0; c < 4; c++) sacc[mt][nt][c] = 0.f;

        const uint32_t kbh = sbase + AS_K + buf * 16384;
        const uint32_t kbl = kbh + 8192;
        {
            uint32_t ah[2][4][4], al[2][4][4], bh[2][4], bl[2][4];
            auto load_frag = [&](int ks, int fb) {
                const int ch = ks * 2 + (lane >> 4);
#pragma unroll
                for (int mt = 0; mt < 4; mt++) {
                    uint32_t sw = swz(arow + mt * 16, ch);
                    ldsm4(ah[fb][mt], sbase + AS_QH + sw);
                    ldsm4(al[fb][mt], sbase + AS_QL + sw);
                }
                uint32_t sw = swz(brow, ch);
                ldsm4(bh[fb], kbh + sw);
                ldsm4(bl[fb], kbl + sw);
            };
            load_frag(0, 0);
#pragma unroll
            for (int ks = 0; ks < 4; ks++) {
                const int fb = ks & 1;
                if (ks < 3) load_frag(ks + 1, fb ^ 1);
#pragma unroll
                for (int mt = 0; mt < 4; mt++)
#pragma unroll
                    for (int hh = 0; hh < 2; hh++) {
                        mma16816(sacc[mt][hh], ah[fb][mt], bh[fb][hh], bh[fb][2 + hh]);
                        mma16816(sacc[mt][hh], ah[fb][mt], bl[fb][hh], bl[fb][2 + hh]);
                        mma16816(sacc[mt][hh], al[fb][mt], bh[fb][hh], bh[fb][2 + hh]);
                    }
            }
        }

        // ---- store S fragments to smem (fp32) ----
#pragma unroll
        for (int mt = 0; mt < 4; mt++)
#pragma unroll
            for (int nt = 0; nt < 2; nt++) {
                int r0 = wm * 64 + mt * 16 + (lane >> 2);
                int c0 = wn * 16 + nt * 8 + (lane & 3) * 2;
                float2 v0, v1;
                v0.x = sacc[mt][nt][0]; v0.y = sacc[mt][nt][1];
                v1.x = sacc[mt][nt][2]; v1.y = sacc[mt][nt][3];
                *(float2*)&sS[r0 * 68 + c0]       = v0;
                *(float2*)&sS[(r0 + 8) * 68 + c0] = v1;
            }
        __syncthreads();

        // ---- P = bit ? exp(S) : 0 ; row-sums ; split bf16 to smem ----
#pragma unroll
        for (int chk = 0; chk < 4; chk++) {
            int cb = pcol + chk * 8;
            float4 x0 = *(const float4*)&sS[prow * 68 + cb];
            float4 x1 = *(const float4*)&sS[prow * 68 + cb + 4];
            float p[8];
            p[0] = __expf(x0.x); p[1] = __expf(x0.y);
            p[2] = __expf(x0.z); p[3] = __expf(x0.w);
            p[4] = __expf(x1.x); p[5] = __expf(x1.y);
            p[6] = __expf(x1.z); p[7] = __expf(x1.w);
#pragma unroll
            for (int j = 0; j < 8; j++) {
                if (!((mbits >> (chk * 8 + j)) & 1u)) p[j] = 0.f;
                denAcc += p[j];
            }
            uint32_t hv[4], lv[4];
#pragma unroll
            for (int j = 0; j < 4; j++) {
                __nv_bfloat162 h2, l2;
                h2.x = __float2bfloat16(p[2 * j]);
                h2.y = __float2bfloat16(p[2 * j + 1]);
                l2.x = __float2bfloat16(p[2 * j]     - __bfloat162float(h2.x));
                l2.y = __float2bfloat16(p[2 * j + 1] - __bfloat162float(h2.y));
                hv[j] = *(uint32_t*)&h2;
                lv[j] = *(uint32_t*)&l2;
            }
            uint32_t sw = swz(prow, (tid & 1) * 4 + chk);
            *(uint4*)(smem + AS_PH + sw) = *(uint4*)hv;
            *(uint4*)(smem + AS_PL + sw) = *(uint4*)lv;
        }
        __syncthreads();

        // ---- O += P V (3-term split, fragment double-buffered) ----
        const uint32_t vbh = sbase + AS_V + buf * 16384;
        const uint32_t vbl = vbh + 8192;
        {
            uint32_t ah[2][4][4], al[2][4][4], bh[2][4], bl[2][4];
            auto load_frag = [&](int ks, int fb) {
                const int ch = ks * 2 + (lane >> 4);
#pragma unroll
                for (int mt = 0; mt < 4; mt++) {
                    uint32_t sw = swz(arow + mt * 16, ch);
                    ldsm4(ah[fb][mt], sbase + AS_PH + sw);
                    ldsm4(al[fb][mt], sbase + AS_PL + sw);
                }
                uint32_t sw = swz(ks * 16 + vrow0, vch);
                ldsm4t(bh[fb], vbh + sw);
                ldsm4t(bl[fb], vbl + sw);
            };
            load_frag(0, 0);
#pragma unroll
            for (int ks = 0; ks < 4; ks++) {
                const int fb = ks & 1;
                if (ks < 3) load_frag(ks + 1, fb ^ 1);
#pragma unroll
                for (int mt = 0; mt < 4; mt++)
#pragma unroll
                    for (int hh = 0; hh < 2; hh++) {
                        mma16816(oacc[mt][hh], ah[fb][mt], bh[fb][hh], bh[fb][2 + hh]);
                        mma16816(oacc[mt][hh], ah[fb][mt], bl[fb][hh], bl[fb][2 + hh]);
                        mma16816(oacc[mt][hh], al[fb][mt], bh[fb][hh], bh[fb][2 + hh]);
                    }
            }
        }
    }

    // ---- epilogue: normalize, write split context + resT ----
    sDen[tid] = denAcc;
    __syncthreads();

#pragma unroll
    for (int mt = 0; mt < 4; mt++)
#pragma unroll
        for (int nt = 0; nt < 2; nt++)
#pragma unroll
            for (int rr = 0; rr < 2; rr++) {
                int r   = wm * 64 + mt * 16 + (lane >> 2) + rr * 8;
                int col = wn * 16 + nt * 8 + (lane & 3) * 2;
                float dn  = sDen[2 * r] + sDen[2 * r + 1];
                float inv = dn > 0.f ? 1.f / dn : 0.f;     // NaN->0 semantics
                float x0 = oacc[mt][nt][rr * 2 + 0] * inv;
                float x1 = oacc[mt][nt][rr * 2 + 1] * inv;
                int s2 = q0 + r;
                size_t co = ((size_t)b * Sq + s2) * Dq + h * DHq + col;
                __nv_bfloat162 hv, lv;
                hv.x = __float2bfloat16(x0);
                hv.y = __float2bfloat16(x1);
                lv.x = __float2bfloat16(x0 - __bfloat162float(hv.x));
                lv.y = __float2bfloat16(x1 - __bfloat162float(hv.y));
                *(__nv_bfloat162*)(ctx_h + co) = hv;
                *(__nv_bfloat162*)(ctx_l + co) = lv;
                if (resT) {
                    float2 rv; rv.x = x0; rv.y = x1;
                    *(float2*)(resT + (((size_t)h * Bq + b) * Sq + s2) * DHq + col) = rv;
                }
            }
}

// ---------------------------------------------------------------------------
extern "C" void kernel_launch(void* const* d_in, const int* in_sizes, int n_in,
                              void* d_out, int out_size)
{
    const float* query = (const float*)d_in[0];
    const float* key_  = (const float*)d_in[1];
    const float* value = (const float*)d_in[2];
    const void*  mask  = d_in[3];
    const float* Wq    = (const float*)d_in[4];
    const float* Wk    = (const float*)d_in[5];
    const float* Wv    = (const float*)d_in[6];
    const float* fcw   = (const float*)d_in[7];
    const float* fcb   = (const float*)d_in[8];
    float* out = (float*)d_out;

    __nv_bfloat16 *qh, *ql, *kh, *kl, *vh, *vl;
    __nv_bfloat16 *xhi, *xlo, *yhi, *ylo, *zhi, *zlo;
    __nv_bfloat16 *w1h, *w1l, *w2h, *w2l, *w3h, *w3l, *w4h, *w4l;
    cudaGetSymbolAddress((void**)&qh,  g_qh);
    cudaGetSymbolAddress((void**)&ql,  g_ql);
    cudaGetSymbolAddress((void**)&kh,  g_kh);
    cudaGetSymbolAddress((void**)&kl,  g_kl);
    cudaGetSymbolAddress((void**)&vh,  g_vh);
    cudaGetSymbolAddress((void**)&vl,  g_vl);
    cudaGetSymbolAddress((void**)&xhi, g_xhi);
    cudaGetSymbolAddress((void**)&xlo, g_xlo);
    cudaGetSymbolAddress((void**)&yhi, g_yhi);
    cudaGetSymbolAddress((void**)&ylo, g_ylo);
    cudaGetSymbolAddress((void**)&zhi, g_zhi);
    cudaGetSymbolAddress((void**)&zlo, g_zlo);
    cudaGetSymbolAddress((void**)&w1h, g_w1h);
    cudaGetSymbolAddress((void**)&w1l, g_w1l);
    cudaGetSymbolAddress((void**)&w2h, g_w2h);
    cudaGetSymbolAddress((void**)&w2l, g_w2l);
    cudaGetSymbolAddress((void**)&w3h, g_w3h);
    cudaGetSymbolAddress((void**)&w3l, g_w3l);
    cudaGetSymbolAddress((void**)&w4h, g_w4h);
    cudaGetSymbolAddress((void**)&w4l, g_w4l);

    cudaFuncSetAttribute(gemm_tc_kernel,
                         cudaFuncAttributeMaxDynamicSharedMemorySize, GSMEM);
    cudaFuncSetAttribute(gemm_qkv_kernel,
                         cudaFuncAttributeMaxDynamicSharedMemorySize, GSMEM);
    cudaFuncSetAttribute(attention_tc_kernel,
                         cudaFuncAttributeMaxDynamicSharedMemorySize, ATT_SMEM);

    detect_mask_kernel<<<1, 32>>>((const unsigned char*)mask);
    mask_bits_kernel<<<MWORDS / 256, 256>>>(mask);

    const int M = Bq * Sq;               // 8192
    const int nX = M * Dq, nW = Dq * Dq;
    const int bX = nX / 1024, bW = nW / 1024;   // blocks (256 thr x 4 elem)

    // one batched split launch: q, k, v, Wq, Wk, Wv, fcw
    SplitParams sp{};
    const float* srcs[7] = {query, key_, value, Wq, Wk, Wv, fcw};
    __nv_bfloat16* his[7] = {xhi, yhi, zhi, w1h, w2h, w3h, w4h};
    __nv_bfloat16* los[7] = {xlo, ylo, zlo, w1l, w2l, w3l, w4l};
    int off = 0;
    for (int t = 0; t < 7; t++) {
        sp.src[t] = srcs[t]; sp.hi[t] = his[t]; sp.lo[t] = los[t];
        sp.blkStart[t] = off;
        off += (t < 3) ? bX : bW;
    }
    sp.blkStart[7] = off;
    sp.nT = 7;
    split_all_kernel<<<off, 256>>>(sp);

    // merged Q/K/V projection GEMMs (Q pre-scaled by 1/8)
    QKVParams qp{};
    qp.Ahi[0] = xhi; qp.Alo[0] = xlo; qp.Bhi[0] = w1h; qp.Blo[0] = w1l;
    qp.oh[0] = qh; qp.ol[0] = ql; qp.scale[0] = 0.125f;
    qp.Ahi[1] = yhi; qp.Alo[1] = ylo; qp.Bhi[1] = w2h; qp.Blo[1] = w2l;
    qp.oh[1] = kh; qp.ol[1] = kl; qp.scale[1] = 1.0f;
    qp.Ahi[2] = zhi; qp.Alo[2] = zlo; qp.Bhi[2] = w3h; qp.Blo[2] = w3l;
    qp.oh[2] = vh; qp.ol[2] = vl; qp.scale[2] = 1.0f;
    dim3 gq(Dq / 128, M / 128, 3);
    gemm_qkv_kernel<<<gq, 256, GSMEM>>>(qp, M, Dq, Dq);

    // attention writes context split into xhi/xlo + resT fp32
    float* resT = (out_size >= 2 * BSDq) ? (out + BSDq) : nullptr;
    attention_tc_kernel<<<Bq * Hq * (Sq / 128), 256, ATT_SMEM>>>(resT, xhi, xlo);

    // final FC: fp32 out with bias
    dim3 gf(Dq / 128, M / 128);
    gemm_tc_kernel<<<gf, 256, GSMEM>>>(xhi, xlo, w4h, w4l, fcb, out, M, Dq, Dq);
}

// round 11
// speedup vs baseline: 1.8046x; 1.0379x over previous
#include <cuda_runtime.h>
#include <cuda_bf16.h>
#include <cstdint>
#include <cstddef>

// Problem constants
#define Bq   4
#define Sq   2048
#define Dq   1024
#define Hq   16
#define DHq  64
#define BSDq (Bq*Sq*Dq)   // 8388608
#define MWORDS (Bq*Sq*(Sq/64))   // 262144 u64 mask words

typedef unsigned long long u64;

// ---------------- generic-PTX tensor-core helpers (sm_80+ ISA) -------------
__device__ __forceinline__ uint32_t smem_u32(const void* p) {
    uint32_t a;
    asm("{ .reg .u64 t; cvta.to.shared.u64 t, %1; cvt.u32.u64 %0, t; }"
        : "=r"(a) : "l"(p));
    return a;
}
__device__ __forceinline__ void cp_async16(uint32_t s, const void* g) {
    asm volatile("cp.async.cg.shared.global [%0], [%1], 16;" :: "r"(s), "l"(g));
}
#define CP_COMMIT() asm volatile("cp.async.commit_group;" ::: "memory")
#define CP_WAIT(n)  asm volatile("cp.async.wait_group %0;" :: "n"(n) : "memory")

__device__ __forceinline__ void ldsm4(uint32_t* r, uint32_t addr) {
    asm volatile("ldmatrix.sync.aligned.m8n8.x4.shared.b16 {%0,%1,%2,%3}, [%4];"
                 : "=r"(r[0]), "=r"(r[1]), "=r"(r[2]), "=r"(r[3]) : "r"(addr));
}
__device__ __forceinline__ void ldsm4t(uint32_t* r, uint32_t addr) {
    asm volatile("ldmatrix.sync.aligned.m8n8.x4.trans.shared.b16 {%0,%1,%2,%3}, [%4];"
                 : "=r"(r[0]), "=r"(r[1]), "=r"(r[2]), "=r"(r[3]) : "r"(addr));
}
// D(f32) += A(bf16) * B(bf16); m16n8k16 row.col
__device__ __forceinline__ void mma16816(float* d, const uint32_t* a,
                                         uint32_t b0, uint32_t b1) {
    asm volatile(
        "mma.sync.aligned.m16n8k16.row.col.f32.bf16.bf16.f32 "
        "{%0,%1,%2,%3}, {%4,%5,%6,%7}, {%8,%9}, {%0,%1,%2,%3};"
        : "+f"(d[0]), "+f"(d[1]), "+f"(d[2]), "+f"(d[3])
        : "r"(a[0]), "r"(a[1]), "r"(a[2]), "r"(a[3]), "r"(b0), "r"(b1));
}
// byte offset of (row, 16B-chunk) in a [rows][64 bf16] tile, xor swizzle
__device__ __forceinline__ uint32_t swz(int row, int ch) {
    uint32_t off = (uint32_t)(row * 128 + ch * 16);
    return off ^ (((uint32_t)row & 7u) << 4);
}

// ---------------- scratch (device globals: allocation-free rule) -----------
__device__ int g_mask_kind;                      // 0=uint8, else 4-byte elems
__device__ __align__(16) u64 g_mbits[MWORDS];    // packed mask bits
__device__ __align__(16) __nv_bfloat16 g_qh[BSDq];
__device__ __align__(16) __nv_bfloat16 g_ql[BSDq];
__device__ __align__(16) __nv_bfloat16 g_kh[BSDq];
__device__ __align__(16) __nv_bfloat16 g_kl[BSDq];
__device__ __align__(16) __nv_bfloat16 g_vh[BSDq];
__device__ __align__(16) __nv_bfloat16 g_vl[BSDq];
__device__ __align__(16) __nv_bfloat16 g_xhi[BSDq];   // q split / ctx split
__device__ __align__(16) __nv_bfloat16 g_xlo[BSDq];
__device__ __align__(16) __nv_bfloat16 g_yhi[BSDq];   // k split
__device__ __align__(16) __nv_bfloat16 g_ylo[BSDq];
__device__ __align__(16) __nv_bfloat16 g_zhi[BSDq];   // v split
__device__ __align__(16) __nv_bfloat16 g_zlo[BSDq];
__device__ __align__(16) __nv_bfloat16 g_w1h[Dq * Dq]; // Wq
__device__ __align__(16) __nv_bfloat16 g_w1l[Dq * Dq];
__device__ __align__(16) __nv_bfloat16 g_w2h[Dq * Dq]; // Wk
__device__ __align__(16) __nv_bfloat16 g_w2l[Dq * Dq];
__device__ __align__(16) __nv_bfloat16 g_w3h[Dq * Dq]; // Wv
__device__ __align__(16) __nv_bfloat16 g_w3l[Dq * Dq];
__device__ __align__(16) __nv_bfloat16 g_w4h[Dq * Dq]; // fc_w
__device__ __align__(16) __nv_bfloat16 g_w4l[Dq * Dq];

// ---------------------------------------------------------------------------
__global__ void detect_mask_kernel(const unsigned char* __restrict__ m) {
    if (threadIdx.x != 0) return;
    int c0 = 0, c1 = 0, c2 = 0, c3 = 0;
    for (int i = 0; i < 4096; i += 4) {
        if (m[i + 0]) c0++;
        if (m[i + 1]) c1++;
        if (m[i + 2]) c2++;
        if (m[i + 3]) c3++;
    }
    int kind;
    if (c1 == 0 && c2 == 0 && c3 == 0) kind = 1;   // int32
    else if (c0 == 0 && c1 == 0)       kind = 2;   // float32
    else                               kind = 0;   // uint8
    g_mask_kind = kind;
}

// pack mask -> 64-bit words (bit j = element j nonzero)
__global__ __launch_bounds__(256)
void mask_bits_kernel(const void* __restrict__ mask) {
    int w = blockIdx.x * 256 + threadIdx.x;
    if (w >= MWORDS) return;
    u64 bits = 0;
    if (g_mask_kind == 0) {
        const uint4* p = (const uint4*)((const unsigned char*)mask + (size_t)w * 64);
#pragma unroll
        for (int q = 0; q < 4; q++) {
            uint4 v = p[q];
            const uint32_t ww[4] = {v.x, v.y, v.z, v.w};
#pragma unroll
            for (int k = 0; k < 4; k++)
#pragma unroll
                for (int j = 0; j < 4; j++)
                    if ((ww[k] >> (8 * j)) & 0xffu)
                        bits |= 1ull << (q * 16 + k * 4 + j);
        }
    } else {   // 4-byte elements
        const uint4* p = (const uint4*)((const uint32_t*)mask + (size_t)w * 64);
#pragma unroll
        for (int q = 0; q < 16; q++) {
            uint4 v = p[q];
            if (v.x) bits |= 1ull << (q * 4 + 0);
            if (v.y) bits |= 1ull << (q * 4 + 1);
            if (v.z) bits |= 1ull << (q * 4 + 2);
            if (v.w) bits |= 1ull << (q * 4 + 3);
        }
    }
    g_mbits[w] = bits;
}

// ---- batched fp32 -> bf16 hi/lo split for up to 8 tensors -----------------
struct SplitParams {
    const float* src[8];
    __nv_bfloat16* hi[8];
    __nv_bfloat16* lo[8];
    int blkStart[9];
    int nT;
};

__global__ __launch_bounds__(256)
void split_all_kernel(SplitParams P)
{
    int blk = blockIdx.x;
    int t = 0;
    while (t + 1 < P.nT && blk >= P.blkStart[t + 1]) t++;
    int i = (blk - P.blkStart[t]) * 256 * 4 + threadIdx.x * 4;
    const float* x = P.src[t];
    float4 v = *(const float4*)(x + i);
    __nv_bfloat16 h0 = __float2bfloat16(v.x), h1 = __float2bfloat16(v.y);
    __nv_bfloat16 h2 = __float2bfloat16(v.z), h3 = __float2bfloat16(v.w);
    __nv_bfloat162 hA, hB, lA, lB;
    hA.x = h0; hA.y = h1; hB.x = h2; hB.y = h3;
    lA.x = __float2bfloat16(v.x - __bfloat162float(h0));
    lA.y = __float2bfloat16(v.y - __bfloat162float(h1));
    lB.x = __float2bfloat16(v.z - __bfloat162float(h2));
    lB.y = __float2bfloat16(v.w - __bfloat162float(h3));
    *(__nv_bfloat162*)(P.hi[t] + i)     = hA;
    *(__nv_bfloat162*)(P.hi[t] + i + 2) = hB;
    *(__nv_bfloat162*)(P.lo[t] + i)     = lA;
    *(__nv_bfloat162*)(P.lo[t] + i + 2) = lB;
}

// ---------------------------------------------------------------------------
// HMMA split-bf16 GEMM core: 128x128 CTA tile, 512 threads (16 warps, 4x4).
// Per warp: 32 rows x 32 cols. 4 warps/SMSP hide LDSM + barrier latency.
// ---------------------------------------------------------------------------
#define GSTAGE  65536
#define GA_HI   0
#define GA_LO   16384
#define GB_HI   32768
#define GB_LO   49152
#define GSMEM   (2*GSTAGE)

__device__ __forceinline__ void gemm_core(
    const __nv_bfloat16* __restrict__ Ahi, const __nv_bfloat16* __restrict__ Alo,
    const __nv_bfloat16* __restrict__ Bhi, const __nv_bfloat16* __restrict__ Blo,
    const float* __restrict__ bias, float* __restrict__ out32,
    __nv_bfloat16* __restrict__ outh, __nv_bfloat16* __restrict__ outl,
    float scale, int M, int N, int K, char* smem)
{
    const uint32_t sbase = smem_u32(smem);
    const int tid  = threadIdx.x;
    const int wid  = tid >> 5;
    const int lane = tid & 31;
    const int m0 = blockIdx.y * 128;
    const int n0 = blockIdx.x * 128;
    const int wm = wid & 3;        // 4 m-warps (32 rows each)
    const int wn = wid >> 2;       // 4 n-warps (32 cols each)

    float acc[2][4][4];
#pragma unroll
    for (int i = 0; i < 2; i++)
#pragma unroll
        for (int j = 0; j < 4; j++)
#pragma unroll
            for (int c = 0; c < 4; c++) acc[i][j][c] = 0.f;

    // stage load: per tensor 128 rows x 8 chunks = 1024; 512 thr -> 2 iters
    int lrow[2], lch[2];
#pragma unroll
    for (int l = 0; l < 2; l++) {
        int idx = l * 512 + tid;
        lrow[l] = idx >> 3;
        lch[l]  = idx & 7;
    }

    auto load_stage = [&](int t, int buf) {
        const int k0 = t * 64;
        const uint32_t sb = sbase + buf * GSTAGE;
#pragma unroll
        for (int l = 0; l < 2; l++) {
            uint32_t sw = swz(lrow[l], lch[l]);
            size_t ao = (size_t)(m0 + lrow[l]) * K + k0 + lch[l] * 8;
            size_t bo = (size_t)(n0 + lrow[l]) * K + k0 + lch[l] * 8;
            cp_async16(sb + GA_HI + sw, Ahi + ao);
            cp_async16(sb + GA_LO + sw, Alo + ao);
            cp_async16(sb + GB_HI + sw, Bhi + bo);
            cp_async16(sb + GB_LO + sw, Blo + bo);
        }
    };

    load_stage(0, 0);
    CP_COMMIT();

    const int arow = wm * 32 + (lane & 15);
    const int brow = wn * 32 + (lane & 15);

    const int NT = K / 64;
#pragma unroll 1
    for (int t = 0; t < NT; t++) {
        const int buf = t & 1;
        if (t + 1 < NT) {
            load_stage(t + 1, (t + 1) & 1);
            CP_COMMIT();
            CP_WAIT(1);        // 2 groups in flight -> drains the older (buf t)
        } else {
            CP_WAIT(0);
        }
        __syncthreads();

        const uint32_t sb = sbase + buf * GSTAGE;
#pragma unroll
        for (int ks = 0; ks < 4; ks++) {
            const int ch = ks * 2 + (lane >> 4);
            uint32_t ah[2][4], al[2][4];
#pragma unroll
            for (int mt = 0; mt < 2; mt++) {
                uint32_t sw = swz(arow + mt * 16, ch);
                ldsm4(ah[mt], sb + GA_HI + sw);
                ldsm4(al[mt], sb + GA_LO + sw);
            }
            uint32_t bh[2][4], bl[2][4];
#pragma unroll
            for (int nb = 0; nb < 2; nb++) {
                uint32_t sw = swz(brow + nb * 16, ch);
                ldsm4(bh[nb], sb + GB_HI + sw);
                ldsm4(bl[nb], sb + GB_LO + sw);
            }
#pragma unroll
            for (int mt = 0; mt < 2; mt++)
#pragma unroll
                for (int nt = 0; nt < 4; nt++) {
                    const int nb = nt >> 1, hh = nt & 1;
                    mma16816(acc[mt][nt], ah[mt], bh[nb][hh], bh[nb][2 + hh]);
                    mma16816(acc[mt][nt], ah[mt], bl[nb][hh], bl[nb][2 + hh]);
                    mma16816(acc[mt][nt], al[mt], bh[nb][hh], bh[nb][2 + hh]);
                }
        }
        __syncthreads();       // compute(t) done before load_stage(t+2) -> buf t
    }

#pragma unroll
    for (int mt = 0; mt < 2; mt++) {
#pragma unroll
        for (int nt = 0; nt < 4; nt++) {
            int row = m0 + wm * 32 + mt * 16 + (lane >> 2);
            int col = n0 + wn * 32 + nt * 8 + (lane & 3) * 2;
            if (out32) {
                float2 v0, v1;
                v0.x = acc[mt][nt][0]; v0.y = acc[mt][nt][1];
                v1.x = acc[mt][nt][2]; v1.y = acc[mt][nt][3];
                if (bias) {
                    float b0 = bias[col], b1 = bias[col + 1];
                    v0.x += b0; v0.y += b1;
                    v1.x += b0; v1.y += b1;
                }
                *(float2*)(out32 + (size_t)row * N + col)       = v0;
                *(float2*)(out32 + (size_t)(row + 8) * N + col) = v1;
            } else {
#pragma unroll
                for (int rr = 0; rr < 2; rr++) {
                    size_t o = (size_t)(row + rr * 8) * N + col;
                    float x0 = acc[mt][nt][rr * 2 + 0] * scale;
                    float x1 = acc[mt][nt][rr * 2 + 1] * scale;
                    __nv_bfloat162 hv, lv;
                    hv.x = __float2bfloat16(x0);
                    hv.y = __float2bfloat16(x1);
                    lv.x = __float2bfloat16(x0 - __bfloat162float(hv.x));
                    lv.y = __float2bfloat16(x1 - __bfloat162float(hv.y));
                    *(__nv_bfloat162*)(outh + o) = hv;
                    *(__nv_bfloat162*)(outl + o) = lv;
                }
            }
        }
    }
}

// single GEMM (FC): fp32 out + bias
__global__ __launch_bounds__(512, 1)
void gemm_tc_kernel(const __nv_bfloat16* __restrict__ Ahi,
                    const __nv_bfloat16* __restrict__ Alo,
                    const __nv_bfloat16* __restrict__ Bhi,
                    const __nv_bfloat16* __restrict__ Blo,
                    const float* __restrict__ bias, float* __restrict__ out32,
                    int M, int N, int K)
{
    extern __shared__ char smem[];
    gemm_core(Ahi, Alo, Bhi, Blo, bias, out32, nullptr, nullptr, 1.0f,
              M, N, K, smem);
}

// merged Q/K/V projection GEMMs: z selects the projection
struct QKVParams {
    const __nv_bfloat16 *Ahi[3], *Alo[3], *Bhi[3], *Blo[3];
    __nv_bfloat16 *oh[3], *ol[3];
    float scale[3];
};
__global__ __launch_bounds__(512, 1)
void gemm_qkv_kernel(QKVParams P, int M, int N, int K)
{
    extern __shared__ char smem[];
    const int z = blockIdx.z;
    gemm_core(P.Ahi[z], P.Alo[z], P.Bhi[z], P.Blo[z], nullptr, nullptr,
              P.oh[z], P.ol[z], P.scale[z], M, N, K, smem);
}

// ---------------------------------------------------------------------------
// HMMA flash attention, 512 threads (16 warps 4x4) + packed-bitmask softmax.
// ---------------------------------------------------------------------------
#define AS_QH   0
#define AS_QL   16384
#define AS_K    32768                 // [buf][hi 8192 | lo 8192] x2
#define AS_V    65536
#define AS_S    98304                 // fp32 [128][68]
#define AS_PH   (98304 + 34816)      // 133120
#define AS_PL   (AS_PH + 16384)      // 149504
#define AS_DEN  (AS_PL + 16384)      // 165888 : 512 floats
#define ATT_SMEM (AS_DEN + 2048)

__global__ __launch_bounds__(512, 1)
void attention_tc_kernel(float* __restrict__ resT,
                         __nv_bfloat16* __restrict__ ctx_h,
                         __nv_bfloat16* __restrict__ ctx_l)
{
    extern __shared__ char smem[];
    const uint32_t sbase = smem_u32(smem);
    float* sS   = (float*)(smem + AS_S);
    float* sDen = (float*)(smem + AS_DEN);

    const int tid  = threadIdx.x;
    const int wid  = tid >> 5;
    const int lane = tid & 31;
    const int wm = wid & 3;        // 4 m-warps (32 q-rows each)
    const int wn = wid >> 2;       // 4 n-warps (16 k-cols each)
    const int blk = blockIdx.x;
    const int qt  = blk & 15;
    const int h   = (blk >> 4) & 15;
    const int b   = blk >> 8;
    const int q0  = qt * 128;

    const size_t headBase = (size_t)b * Sq * Dq + (size_t)h * Sq * DHq;
    const __nv_bfloat16* Qh = g_qh + headBase;
    const __nv_bfloat16* Ql = g_ql + headBase;
    const __nv_bfloat16* Kh = g_kh + headBase;
    const __nv_bfloat16* Kl = g_kl + headBase;
    const __nv_bfloat16* Vh = g_vh + headBase;
    const __nv_bfloat16* Vl = g_vl + headBase;

    // ---- initial loads: Q (persistent, 2 iters) + K/V stage 0 (1 iter) ----
#pragma unroll
    for (int l = 0; l < 2; l++) {
        int idx = l * 512 + tid;
        int row = idx >> 3, ch = idx & 7;
        uint32_t sw = swz(row, ch);
        size_t o = (size_t)(q0 + row) * DHq + ch * 8;
        cp_async16(sbase + AS_QH + sw, Qh + o);
        cp_async16(sbase + AS_QL + sw, Ql + o);
    }
    {
        int row = tid >> 3, ch = tid & 7;    // 64 rows x 8 chunks = 512
        uint32_t sw = swz(row, ch);
        size_t o = (size_t)row * DHq + ch * 8;
        cp_async16(sbase + AS_K + sw,        Kh + o);
        cp_async16(sbase + AS_K + 8192 + sw, Kl + o);
        cp_async16(sbase + AS_V + sw,        Vh + o);
        cp_async16(sbase + AS_V + 8192 + sw, Vl + o);
    }
    CP_COMMIT();

    float oacc[2][2][4];
#pragma unroll
    for (int mt = 0; mt < 2; mt++)
#pragma unroll
        for (int nt = 0; nt < 2; nt++)
#pragma unroll
            for (int c = 0; c < 4; c++) oacc[mt][nt][c] = 0.f;
    float denAcc = 0.f;

    const int prow = tid >> 2;           // P-phase: quarter-row per thread
    const int pcol = (tid & 3) * 16;
    const u64* mrowPtr = g_mbits + ((size_t)b * Sq + q0 + prow) * (Sq / 64);

    const int arow = wm * 32 + (lane & 15);
    const int brow = wn * 16 + (lane & 15);
    const int vrow0 = (lane & 7) + ((lane >> 4) << 3);
    const int vch   = wn * 2 + ((lane >> 3) & 1);

    const int NT = Sq / 64;
#pragma unroll 1
    for (int kt = 0; kt < NT; kt++) {
        const int buf = kt & 1;
        CP_WAIT(0);
        __syncthreads();   // K/V[buf] ready; prev PV reads of this buf done

        // prefetch next K/V stage (1 iter: 512 chunks)
        if (kt + 1 < NT) {
            const uint32_t kb = sbase + AS_K + (1 - buf) * 16384;
            const uint32_t vb = sbase + AS_V + (1 - buf) * 16384;
            const size_t gk = (size_t)(kt + 1) * 64 * DHq;
            int row = tid >> 3, ch = tid & 7;
            uint32_t sw = swz(row, ch);
            size_t o = gk + (size_t)row * DHq + ch * 8;
            cp_async16(kb + sw,        Kh + o);
            cp_async16(kb + 8192 + sw, Kl + o);
            cp_async16(vb + sw,        Vh + o);
            cp_async16(vb + 8192 + sw, Vl + o);
            CP_COMMIT();
        }

        // mask slice for this thread's quarter-row (16 bits)
        const uint32_t mbits = (uint32_t)(mrowPtr[kt] >> pcol);

        // ---- S = Q K^T (3-term split) ----
        float sacc[2][2][4];
#pragma unroll
        for (int mt = 0; mt < 2; mt++)
#pragma unroll
            for (int nt = 0; nt < 2; nt++)
#pragma unroll
                for (int c = 0; c < 4; c++) sacc[mt][nt][c] = 0.f;

        const uint32_t kbh = sbase + AS_K + buf * 16384;
        const uint32_t kbl = kbh + 8192;
#pragma unroll
        for (int ks = 0; ks < 4; ks++) {
            const int ch = ks * 2 + (lane >> 4);
            uint32_t ah[2][4], al[2][4];
#pragma unroll
            for (int mt = 0; mt < 2; mt++) {
                uint32_t sw = swz(arow + mt * 16, ch);
                ldsm4(ah[mt], sbase + AS_QH + sw);
                ldsm4(al[mt], sbase + AS_QL + sw);
            }
            uint32_t bh[4], bl[4];
            {
                uint32_t sw = swz(brow, ch);
                ldsm4(bh, kbh + sw);
                ldsm4(bl, kbl + sw);
            }
#pragma unroll
            for (int mt = 0; mt < 2; mt++)
#pragma unroll
                for (int hh = 0; hh < 2; hh++) {
                    mma16816(sacc[mt][hh], ah[mt], bh[hh], bh[2 + hh]);
                    mma16816(sacc[mt][hh], ah[mt], bl[hh], bl[2 + hh]);
                    mma16816(sacc[mt][hh], al[mt], bh[hh], bh[2 + hh]);
                }
        }

        // ---- store S fragments to smem (fp32) ----
#pragma unroll
        for (int mt = 0; mt < 2; mt++)
#pragma unroll
            for (int nt = 0; nt < 2; nt++) {
                int r0 = wm * 32 + mt * 16 + (lane >> 2);
                int c0 = wn * 16 + nt * 8 + (lane & 3) * 2;
                float2 v0, v1;
                v0.x = sacc[mt][nt][0]; v0.y = sacc[mt][nt][1];
                v1.x = sacc[mt][nt][2]; v1.y = sacc[mt][nt][3];
                *(float2*)&sS[r0 * 68 + c0]       = v0;
                *(float2*)&sS[(r0 + 8) * 68 + c0] = v1;
            }
        __syncthreads();

        // ---- P = bit ? exp(S) : 0 ; row-sums ; split bf16 to smem ----
#pragma unroll
        for (int chk = 0; chk < 2; chk++) {
            int cb = pcol + chk * 8;
            float4 x0 = *(const float4*)&sS[prow * 68 + cb];
            float4 x1 = *(const float4*)&sS[prow * 68 + cb + 4];
            float p[8];
            p[0] = __expf(x0.x); p[1] = __expf(x0.y);
            p[2] = __expf(x0.z); p[3] = __expf(x0.w);
            p[4] = __expf(x1.x); p[5] = __expf(x1.y);
            p[6] = __expf(x1.z); p[7] = __expf(x1.w);
#pragma unroll
            for (int j = 0; j < 8; j++) {
                if (!((mbits >> (chk * 8 + j)) & 1u)) p[j] = 0.f;
                denAcc += p[j];
            }
            uint32_t hv[4], lv[4];
#pragma unroll
            for (int j = 0; j < 4; j++) {
                __nv_bfloat162 h2, l2;
                h2.x = __float2bfloat16(p[2 * j]);
                h2.y = __float2bfloat16(p[2 * j + 1]);
                l2.x = __float2bfloat16(p[2 * j]     - __bfloat162float(h2.x));
                l2.y = __float2bfloat16(p[2 * j + 1] - __bfloat162float(h2.y));
                hv[j] = *(uint32_t*)&h2;
                lv[j] = *(uint32_t*)&l2;
            }
            uint32_t sw = swz(prow, (tid & 3) * 2 + chk);
            *(uint4*)(smem + AS_PH + sw) = *(uint4*)hv;
            *(uint4*)(smem + AS_PL + sw) = *(uint4*)lv;
        }
        __syncthreads();

        // ---- O += P V (3-term split; V via ldmatrix.trans) ----
        const uint32_t vbh = sbase + AS_V + buf * 16384;
        const uint32_t vbl = vbh + 8192;
#pragma unroll
        for (int ks = 0; ks < 4; ks++) {
            const int ch = ks * 2 + (lane >> 4);
            uint32_t ah[2][4], al[2][4];
#pragma unroll
            for (int mt = 0; mt < 2; mt++) {
                uint32_t sw = swz(arow + mt * 16, ch);
                ldsm4(ah[mt], sbase + AS_PH + sw);
                ldsm4(al[mt], sbase + AS_PL + sw);
            }
            uint32_t bh[4], bl[4];
            {
                uint32_t sw = swz(ks * 16 + vrow0, vch);
                ldsm4t(bh, vbh + sw);
                ldsm4t(bl, vbl + sw);
            }
#pragma unroll
            for (int mt = 0; mt < 2; mt++)
#pragma unroll
                for (int hh = 0; hh < 2; hh++) {
                    mma16816(oacc[mt][hh], ah[mt], bh[hh], bh[2 + hh]);
                    mma16816(oacc[mt][hh], ah[mt], bl[hh], bl[2 + hh]);
                    mma16816(oacc[mt][hh], al[mt], bh[hh], bh[2 + hh]);
                }
        }
    }

    // ---- epilogue: normalize, write split context + resT ----
    sDen[tid] = denAcc;
    __syncthreads();

#pragma unroll
    for (int mt = 0; mt < 2; mt++)
#pragma unroll
        for (int nt = 0; nt < 2; nt++)
#pragma unroll
            for (int rr = 0; rr < 2; rr++) {
                int r   = wm * 32 + mt * 16 + (lane >> 2) + rr * 8;
                int col = wn * 16 + nt * 8 + (lane & 3) * 2;
                float dn = sDen[4 * r] + sDen[4 * r + 1]
                         + sDen[4 * r + 2] + sDen[4 * r + 3];
                float inv = dn > 0.f ? 1.f / dn : 0.f;     // NaN->0 semantics
                float x0 = oacc[mt][nt][rr * 2 + 0] * inv;
                float x1 = oacc[mt][nt][rr * 2 + 1] * inv;
                int s2 = q0 + r;
                size_t co = ((size_t)b * Sq + s2) * Dq + h * DHq + col;
                __nv_bfloat162 hv, lv;
                hv.x = __float2bfloat16(x0);
                hv.y = __float2bfloat16(x1);
                lv.x = __float2bfloat16(x0 - __bfloat162float(hv.x));
                lv.y = __float2bfloat16(x1 - __bfloat162float(hv.y));
                *(__nv_bfloat162*)(ctx_h + co) = hv;
                *(__nv_bfloat162*)(ctx_l + co) = lv;
                if (resT) {
                    float2 rv; rv.x = x0; rv.y = x1;
                    *(float2*)(resT + (((size_t)h * Bq + b) * Sq + s2) * DHq + col) = rv;
                }
            }
}

// ---------------------------------------------------------------------------
extern "C" void kernel_launch(void* const* d_in, const int* in_sizes, int n_in,
                              void* d_out, int out_size)
{
    const float* query = (const float*)d_in[0];
    const float* key_  = (const float*)d_in[1];
    const float* value = (const float*)d_in[2];
    const void*  mask  = d_in[3];
    const float* Wq    = (const float*)d_in[4];
    const float* Wk    = (const float*)d_in[5];
    const float* Wv    = (const float*)d_in[6];
    const float* fcw   = (const float*)d_in[7];
    const float* fcb   = (const float*)d_in[8];
    float* out = (float*)d_out;

    __nv_bfloat16 *qh, *ql, *kh, *kl, *vh, *vl;
    __nv_bfloat16 *xhi, *xlo, *yhi, *ylo, *zhi, *zlo;
    __nv_bfloat16 *w1h, *w1l, *w2h, *w2l, *w3h, *w3l, *w4h, *w4l;
    cudaGetSymbolAddress((void**)&qh,  g_qh);
    cudaGetSymbolAddress((void**)&ql,  g_ql);
    cudaGetSymbolAddress((void**)&kh,  g_kh);
    cudaGetSymbolAddress((void**)&kl,  g_kl);
    cudaGetSymbolAddress((void**)&vh,  g_vh);
    cudaGetSymbolAddress((void**)&vl,  g_vl);
    cudaGetSymbolAddress((void**)&xhi, g_xhi);
    cudaGetSymbolAddress((void**)&xlo, g_xlo);
    cudaGetSymbolAddress((void**)&yhi, g_yhi);
    cudaGetSymbolAddress((void**)&ylo, g_ylo);
    cudaGetSymbolAddress((void**)&zhi, g_zhi);
    cudaGetSymbolAddress((void**)&zlo, g_zlo);
    cudaGetSymbolAddress((void**)&w1h, g_w1h);
    cudaGetSymbolAddress((void**)&w1l, g_w1l);
    cudaGetSymbolAddress((void**)&w2h, g_w2h);
    cudaGetSymbolAddress((void**)&w2l, g_w2l);
    cudaGetSymbolAddress((void**)&w3h, g_w3h);
    cudaGetSymbolAddress((void**)&w3l, g_w3l);
    cudaGetSymbolAddress((void**)&w4h, g_w4h);
    cudaGetSymbolAddress((void**)&w4l, g_w4l);

    cudaFuncSetAttribute(gemm_tc_kernel,
                         cudaFuncAttributeMaxDynamicSharedMemorySize, GSMEM);
    cudaFuncSetAttribute(gemm_qkv_kernel,
                         cudaFuncAttributeMaxDynamicSharedMemorySize, GSMEM);
    cudaFuncSetAttribute(attention_tc_kernel,
                         cudaFuncAttributeMaxDynamicSharedMemorySize, ATT_SMEM);

    detect_mask_kernel<<<1, 32>>>((const unsigned char*)mask);
    mask_bits_kernel<<<MWORDS / 256, 256>>>(mask);

    const int M = Bq * Sq;               // 8192
    const int nX = M * Dq, nW = Dq * Dq;
    const int bX = nX / 1024, bW = nW / 1024;

    // one batched split launch: q, k, v, Wq, Wk, Wv, fcw
    SplitParams sp{};
    const float* srcs[7] = {query, key_, value, Wq, Wk, Wv, fcw};
    __nv_bfloat16* his[7] = {xhi, yhi, zhi, w1h, w2h, w3h, w4h};
    __nv_bfloat16* los[7] = {xlo, ylo, zlo, w1l, w2l, w3l, w4l};
    int off = 0;
    for (int t = 0; t < 7; t++) {
        sp.src[t] = srcs[t]; sp.hi[t] = his[t]; sp.lo[t] = los[t];
        sp.blkStart[t] = off;
        off += (t < 3) ? bX : bW;
    }
    sp.blkStart[7] = off;
    sp.nT = 7;
    split_all_kernel<<<off, 256>>>(sp);

    // merged Q/K/V projection GEMMs (Q pre-scaled by 1/8)
    QKVParams qp{};
    qp.Ahi[0] = xhi; qp.Alo[0] = xlo; qp.Bhi[0] = w1h; qp.Blo[0] = w1l;
    qp.oh[0] = qh; qp.ol[0] = ql; qp.scale[0] = 0.125f;
    qp.Ahi[1] = yhi; qp.Alo[1] = ylo; qp.Bhi[1] = w2h; qp.Blo[1] = w2l;
    qp.oh[1] = kh; qp.ol[1] = kl; qp.scale[1] = 1.0f;
    qp.Ahi[2] = zhi; qp.Alo[2] = zlo; qp.Bhi[2] = w3h; qp.Blo[2] = w3l;
    qp.oh[2] = vh; qp.ol[2] = vl; qp.scale[2] = 1.0f;
    dim3 gq(Dq / 128, M / 128, 3);
    gemm_qkv_kernel<<<gq, 512, GSMEM>>>(qp, M, Dq, Dq);

    // attention writes context split into xhi/xlo + resT fp32
    float* resT = (out_size >= 2 * BSDq) ? (out + BSDq) : nullptr;
    attention_tc_kernel<<<Bq * Hq * (Sq / 128), 512, ATT_SMEM>>>(resT, xhi, xlo);

    // final FC: fp32 out with bias
    dim3 gf(Dq / 128, M / 128);
    gemm_tc_kernel<<<gf, 512, GSMEM>>>(xhi, xlo, w4h, w4l, fcb, out, M, Dq, Dq);
}

// round 12
// speedup vs baseline: 1.9291x; 1.0690x over previous
#include <cuda_runtime.h>
#include <cuda_bf16.h>
#include <cstdint>
#include <cstddef>

// Problem constants
#define Bq   4
#define Sq   2048
#define Dq   1024
#define Hq   16
#define DHq  64
#define BSDq (Bq*Sq*Dq)   // 8388608
#define MWORDS (Bq*Sq*(Sq/64))   // 262144 u64 mask words

typedef unsigned long long u64;

// ---------------- generic-PTX tensor-core helpers (sm_80+ ISA) -------------
__device__ __forceinline__ uint32_t smem_u32(const void* p) {
    uint32_t a;
    asm("{ .reg .u64 t; cvta.to.shared.u64 t, %1; cvt.u32.u64 %0, t; }"
        : "=r"(a) : "l"(p));
    return a;
}
__device__ __forceinline__ void cp_async16(uint32_t s, const void* g) {
    asm volatile("cp.async.cg.shared.global [%0], [%1], 16;" :: "r"(s), "l"(g));
}
#define CP_COMMIT() asm volatile("cp.async.commit_group;" ::: "memory")
#define CP_WAIT(n)  asm volatile("cp.async.wait_group %0;" :: "n"(n) : "memory")

__device__ __forceinline__ void ldsm4(uint32_t* r, uint32_t addr) {
    asm volatile("ldmatrix.sync.aligned.m8n8.x4.shared.b16 {%0,%1,%2,%3}, [%4];"
                 : "=r"(r[0]), "=r"(r[1]), "=r"(r[2]), "=r"(r[3]) : "r"(addr));
}
__device__ __forceinline__ void ldsm4t(uint32_t* r, uint32_t addr) {
    asm volatile("ldmatrix.sync.aligned.m8n8.x4.trans.shared.b16 {%0,%1,%2,%3}, [%4];"
                 : "=r"(r[0]), "=r"(r[1]), "=r"(r[2]), "=r"(r[3]) : "r"(addr));
}
// D(f32) += A(bf16) * B(bf16); m16n8k16 row.col
__device__ __forceinline__ void mma16816(float* d, const uint32_t* a,
                                         uint32_t b0, uint32_t b1) {
    asm volatile(
        "mma.sync.aligned.m16n8k16.row.col.f32.bf16.bf16.f32 "
        "{%0,%1,%2,%3}, {%4,%5,%6,%7}, {%8,%9}, {%0,%1,%2,%3};"
        : "+f"(d[0]), "+f"(d[1]), "+f"(d[2]), "+f"(d[3])
        : "r"(a[0]), "r"(a[1]), "r"(a[2]), "r"(a[3]), "r"(b0), "r"(b1));
}
// byte offset of (row, 16B-chunk) in a [rows][64 bf16] tile, xor swizzle
__device__ __forceinline__ uint32_t swz(int row, int ch) {
    uint32_t off = (uint32_t)(row * 128 + ch * 16);
    return off ^ (((uint32_t)row & 7u) << 4);
}

// ---------------- scratch (device globals: allocation-free rule) -----------
__device__ int g_mask_kind;                      // 0=uint8, else 4-byte elems
__device__ __align__(16) u64 g_mbits[MWORDS];    // packed mask bits
__device__ __align__(16) __nv_bfloat16 g_qh[BSDq];
__device__ __align__(16) __nv_bfloat16 g_ql[BSDq];
__device__ __align__(16) __nv_bfloat16 g_kh[BSDq];
__device__ __align__(16) __nv_bfloat16 g_kl[BSDq];
__device__ __align__(16) __nv_bfloat16 g_vh[BSDq];
__device__ __align__(16) __nv_bfloat16 g_vl[BSDq];
__device__ __align__(16) __nv_bfloat16 g_xhi[BSDq];   // q split / ctx split
__device__ __align__(16) __nv_bfloat16 g_xlo[BSDq];
__device__ __align__(16) __nv_bfloat16 g_yhi[BSDq];   // k split
__device__ __align__(16) __nv_bfloat16 g_ylo[BSDq];
__device__ __align__(16) __nv_bfloat16 g_zhi[BSDq];   // v split
__device__ __align__(16) __nv_bfloat16 g_zlo[BSDq];
__device__ __align__(16) __nv_bfloat16 g_w1h[Dq * Dq]; // Wq
__device__ __align__(16) __nv_bfloat16 g_w1l[Dq * Dq];
__device__ __align__(16) __nv_bfloat16 g_w2h[Dq * Dq]; // Wk
__device__ __align__(16) __nv_bfloat16 g_w2l[Dq * Dq];
__device__ __align__(16) __nv_bfloat16 g_w3h[Dq * Dq]; // Wv
__device__ __align__(16) __nv_bfloat16 g_w3l[Dq * Dq];
__device__ __align__(16) __nv_bfloat16 g_w4h[Dq * Dq]; // fc_w
__device__ __align__(16) __nv_bfloat16 g_w4l[Dq * Dq];

// ---------------------------------------------------------------------------
__global__ void detect_mask_kernel(const unsigned char* __restrict__ m) {
    if (threadIdx.x != 0) return;
    int c0 = 0, c1 = 0, c2 = 0, c3 = 0;
    for (int i = 0; i < 4096; i += 4) {
        if (m[i + 0]) c0++;
        if (m[i + 1]) c1++;
        if (m[i + 2]) c2++;
        if (m[i + 3]) c3++;
    }
    int kind;
    if (c1 == 0 && c2 == 0 && c3 == 0) kind = 1;   // int32
    else if (c0 == 0 && c1 == 0)       kind = 2;   // float32
    else                               kind = 0;   // uint8
    g_mask_kind = kind;
}

// pack mask -> 64-bit words (bit j = element j nonzero)
__global__ __launch_bounds__(256)
void mask_bits_kernel(const void* __restrict__ mask) {
    int w = blockIdx.x * 256 + threadIdx.x;
    if (w >= MWORDS) return;
    u64 bits = 0;
    if (g_mask_kind == 0) {
        const uint4* p = (const uint4*)((const unsigned char*)mask + (size_t)w * 64);
#pragma unroll
        for (int q = 0; q < 4; q++) {
            uint4 v = p[q];
            const uint32_t ww[4] = {v.x, v.y, v.z, v.w};
#pragma unroll
            for (int k = 0; k < 4; k++)
#pragma unroll
                for (int j = 0; j < 4; j++)
                    if ((ww[k] >> (8 * j)) & 0xffu)
                        bits |= 1ull << (q * 16 + k * 4 + j);
        }
    } else {   // 4-byte elements
        const uint4* p = (const uint4*)((const uint32_t*)mask + (size_t)w * 64);
#pragma unroll
        for (int q = 0; q < 16; q++) {
            uint4 v = p[q];
            if (v.x) bits |= 1ull << (q * 4 + 0);
            if (v.y) bits |= 1ull << (q * 4 + 1);
            if (v.z) bits |= 1ull << (q * 4 + 2);
            if (v.w) bits |= 1ull << (q * 4 + 3);
        }
    }
    g_mbits[w] = bits;
}

// ---- batched fp32 -> bf16 hi/lo split for up to 8 tensors -----------------
struct SplitParams {
    const float* src[8];
    __nv_bfloat16* hi[8];
    __nv_bfloat16* lo[8];
    int blkStart[9];
    int nT;
};

__global__ __launch_bounds__(256)
void split_all_kernel(SplitParams P)
{
    int blk = blockIdx.x;
    int t = 0;
    while (t + 1 < P.nT && blk >= P.blkStart[t + 1]) t++;
    int i = (blk - P.blkStart[t]) * 256 * 4 + threadIdx.x * 4;
    const float* x = P.src[t];
    float4 v = *(const float4*)(x + i);
    __nv_bfloat16 h0 = __float2bfloat16(v.x), h1 = __float2bfloat16(v.y);
    __nv_bfloat16 h2 = __float2bfloat16(v.z), h3 = __float2bfloat16(v.w);
    __nv_bfloat162 hA, hB, lA, lB;
    hA.x = h0; hA.y = h1; hB.x = h2; hB.y = h3;
    lA.x = __float2bfloat16(v.x - __bfloat162float(h0));
    lA.y = __float2bfloat16(v.y - __bfloat162float(h1));
    lB.x = __float2bfloat16(v.z - __bfloat162float(h2));
    lB.y = __float2bfloat16(v.w - __bfloat162float(h3));
    *(__nv_bfloat162*)(P.hi[t] + i)     = hA;
    *(__nv_bfloat162*)(P.hi[t] + i + 2) = hB;
    *(__nv_bfloat162*)(P.lo[t] + i)     = lA;
    *(__nv_bfloat162*)(P.lo[t] + i + 2) = lB;
}

// ---------------------------------------------------------------------------
// HMMA split-bf16 GEMM core: 128x64 CTA tile, 256 threads (8 warps, 4m x 2n),
// 96KB smem -> 2 CTAs/SM so one CTA's MMAs cover the other's barriers/waits.
// ---------------------------------------------------------------------------
#define GSTAGE  49152               // A 32KB (hi+lo) + B 16KB (hi+lo)
#define GA_HI   0
#define GA_LO   16384
#define GB_HI   32768
#define GB_LO   40960
#define GSMEM   (2*GSTAGE)          // 96KB

__device__ __forceinline__ void gemm_core(
    const __nv_bfloat16* __restrict__ Ahi, const __nv_bfloat16* __restrict__ Alo,
    const __nv_bfloat16* __restrict__ Bhi, const __nv_bfloat16* __restrict__ Blo,
    const float* __restrict__ bias, float* __restrict__ out32,
    __nv_bfloat16* __restrict__ outh, __nv_bfloat16* __restrict__ outl,
    float scale, int M, int N, int K, char* smem)
{
    const uint32_t sbase = smem_u32(smem);
    const int tid  = threadIdx.x;
    const int wid  = tid >> 5;
    const int lane = tid & 31;
    const int m0 = blockIdx.y * 128;
    const int n0 = blockIdx.x * 64;
    const int wm = wid & 3;        // 4 m-warps (32 rows each)
    const int wn = wid >> 2;       // 2 n-warps (32 cols each)

    float acc[2][4][4];
#pragma unroll
    for (int i = 0; i < 2; i++)
#pragma unroll
        for (int j = 0; j < 4; j++)
#pragma unroll
            for (int c = 0; c < 4; c++) acc[i][j][c] = 0.f;

    // A: 128 rows x 8 chunks = 1024 -> 4 iters; B: 64 rows x 8 = 512 -> 2
    auto load_stage = [&](int t, int buf) {
        const int k0 = t * 64;
        const uint32_t sb = sbase + buf * GSTAGE;
#pragma unroll
        for (int l = 0; l < 4; l++) {
            int idx = l * 256 + tid;
            int row = idx >> 3, ch = idx & 7;
            uint32_t sw = swz(row, ch);
            size_t ao = (size_t)(m0 + row) * K + k0 + ch * 8;
            cp_async16(sb + GA_HI + sw, Ahi + ao);
            cp_async16(sb + GA_LO + sw, Alo + ao);
        }
#pragma unroll
        for (int l = 0; l < 2; l++) {
            int idx = l * 256 + tid;
            int row = idx >> 3, ch = idx & 7;
            uint32_t sw = swz(row, ch);
            size_t bo = (size_t)(n0 + row) * K + k0 + ch * 8;
            cp_async16(sb + GB_HI + sw, Bhi + bo);
            cp_async16(sb + GB_LO + sw, Blo + bo);
        }
    };

    load_stage(0, 0);
    CP_COMMIT();

    const int arow = wm * 32 + (lane & 15);
    const int brow = wn * 32 + (lane & 15);

    const int NT = K / 64;
#pragma unroll 1
    for (int t = 0; t < NT; t++) {
        const int buf = t & 1;
        if (t + 1 < NT) {
            load_stage(t + 1, (t + 1) & 1);
            CP_COMMIT();
            CP_WAIT(1);        // 2 groups in flight -> drains the older (buf t)
        } else {
            CP_WAIT(0);
        }
        __syncthreads();

        const uint32_t sb = sbase + buf * GSTAGE;
#pragma unroll
        for (int ks = 0; ks < 4; ks++) {
            const int ch = ks * 2 + (lane >> 4);
            uint32_t ah[2][4], al[2][4];
#pragma unroll
            for (int mt = 0; mt < 2; mt++) {
                uint32_t sw = swz(arow + mt * 16, ch);
                ldsm4(ah[mt], sb + GA_HI + sw);
                ldsm4(al[mt], sb + GA_LO + sw);
            }
            uint32_t bh[2][4], bl[2][4];
#pragma unroll
            for (int nb = 0; nb < 2; nb++) {
                uint32_t sw = swz(brow + nb * 16, ch);
                ldsm4(bh[nb], sb + GB_HI + sw);
                ldsm4(bl[nb], sb + GB_LO + sw);
            }
#pragma unroll
            for (int mt = 0; mt < 2; mt++)
#pragma unroll
                for (int nt = 0; nt < 4; nt++) {
                    const int nb = nt >> 1, hh = nt & 1;
                    mma16816(acc[mt][nt], ah[mt], bh[nb][hh], bh[nb][2 + hh]);
                    mma16816(acc[mt][nt], ah[mt], bl[nb][hh], bl[nb][2 + hh]);
                    mma16816(acc[mt][nt], al[mt], bh[nb][hh], bh[nb][2 + hh]);
                }
        }
        __syncthreads();       // compute(t) done before load_stage(t+2) -> buf t
    }

#pragma unroll
    for (int mt = 0; mt < 2; mt++) {
#pragma unroll
        for (int nt = 0; nt < 4; nt++) {
            int row = m0 + wm * 32 + mt * 16 + (lane >> 2);
            int col = n0 + wn * 32 + nt * 8 + (lane & 3) * 2;
            if (out32) {
                float2 v0, v1;
                v0.x = acc[mt][nt][0]; v0.y = acc[mt][nt][1];
                v1.x = acc[mt][nt][2]; v1.y = acc[mt][nt][3];
                if (bias) {
                    float b0 = bias[col], b1 = bias[col + 1];
                    v0.x += b0; v0.y += b1;
                    v1.x += b0; v1.y += b1;
                }
                *(float2*)(out32 + (size_t)row * N + col)       = v0;
                *(float2*)(out32 + (size_t)(row + 8) * N + col) = v1;
            } else {
#pragma unroll
                for (int rr = 0; rr < 2; rr++) {
                    size_t o = (size_t)(row + rr * 8) * N + col;
                    float x0 = acc[mt][nt][rr * 2 + 0] * scale;
                    float x1 = acc[mt][nt][rr * 2 + 1] * scale;
                    __nv_bfloat162 hv, lv;
                    hv.x = __float2bfloat16(x0);
                    hv.y = __float2bfloat16(x1);
                    lv.x = __float2bfloat16(x0 - __bfloat162float(hv.x));
                    lv.y = __float2bfloat16(x1 - __bfloat162float(hv.y));
                    *(__nv_bfloat162*)(outh + o) = hv;
                    *(__nv_bfloat162*)(outl + o) = lv;
                }
            }
        }
    }
}

// single GEMM (FC): fp32 out + bias
__global__ __launch_bounds__(256, 2)
void gemm_tc_kernel(const __nv_bfloat16* __restrict__ Ahi,
                    const __nv_bfloat16* __restrict__ Alo,
                    const __nv_bfloat16* __restrict__ Bhi,
                    const __nv_bfloat16* __restrict__ Blo,
                    const float* __restrict__ bias, float* __restrict__ out32,
                    int M, int N, int K)
{
    extern __shared__ char smem[];
    gemm_core(Ahi, Alo, Bhi, Blo, bias, out32, nullptr, nullptr, 1.0f,
              M, N, K, smem);
}

// merged Q/K/V projection GEMMs: z selects the projection
struct QKVParams {
    const __nv_bfloat16 *Ahi[3], *Alo[3], *Bhi[3], *Blo[3];
    __nv_bfloat16 *oh[3], *ol[3];
    float scale[3];
};
__global__ __launch_bounds__(256, 2)
void gemm_qkv_kernel(QKVParams P, int M, int N, int K)
{
    extern __shared__ char smem[];
    const int z = blockIdx.z;
    gemm_core(P.Ahi[z], P.Alo[z], P.Bhi[z], P.Blo[z], nullptr, nullptr,
              P.oh[z], P.ol[z], P.scale[z], M, N, K, smem);
}

// ---------------------------------------------------------------------------
// HMMA flash attention, 512 threads (16 warps 4x4) + packed-bitmask softmax.
// (unchanged from R11 — validated)
// ---------------------------------------------------------------------------
#define AS_QH   0
#define AS_QL   16384
#define AS_K    32768                 // [buf][hi 8192 | lo 8192] x2
#define AS_V    65536
#define AS_S    98304                 // fp32 [128][68]
#define AS_PH   (98304 + 34816)      // 133120
#define AS_PL   (AS_PH + 16384)      // 149504
#define AS_DEN  (AS_PL + 16384)      // 165888 : 512 floats
#define ATT_SMEM (AS_DEN + 2048)

__global__ __launch_bounds__(512, 1)
void attention_tc_kernel(float* __restrict__ resT,
                         __nv_bfloat16* __restrict__ ctx_h,
                         __nv_bfloat16* __restrict__ ctx_l)
{
    extern __shared__ char smem[];
    const uint32_t sbase = smem_u32(smem);
    float* sS   = (float*)(smem + AS_S);
    float* sDen = (float*)(smem + AS_DEN);

    const int tid  = threadIdx.x;
    const int wid  = tid >> 5;
    const int lane = tid & 31;
    const int wm = wid & 3;        // 4 m-warps (32 q-rows each)
    const int wn = wid >> 2;       // 4 n-warps (16 k-cols each)
    const int blk = blockIdx.x;
    const int qt  = blk & 15;
    const int h   = (blk >> 4) & 15;
    const int b   = blk >> 8;
    const int q0  = qt * 128;

    const size_t headBase = (size_t)b * Sq * Dq + (size_t)h * Sq * DHq;
    const __nv_bfloat16* Qh = g_qh + headBase;
    const __nv_bfloat16* Ql = g_ql + headBase;
    const __nv_bfloat16* Kh = g_kh + headBase;
    const __nv_bfloat16* Kl = g_kl + headBase;
    const __nv_bfloat16* Vh = g_vh + headBase;
    const __nv_bfloat16* Vl = g_vl + headBase;

    // ---- initial loads: Q (persistent, 2 iters) + K/V stage 0 (1 iter) ----
#pragma unroll
    for (int l = 0; l < 2; l++) {
        int idx = l * 512 + tid;
        int row = idx >> 3, ch = idx & 7;
        uint32_t sw = swz(row, ch);
        size_t o = (size_t)(q0 + row) * DHq + ch * 8;
        cp_async16(sbase + AS_QH + sw, Qh + o);
        cp_async16(sbase + AS_QL + sw, Ql + o);
    }
    {
        int row = tid >> 3, ch = tid & 7;    // 64 rows x 8 chunks = 512
        uint32_t sw = swz(row, ch);
        size_t o = (size_t)row * DHq + ch * 8;
        cp_async16(sbase + AS_K + sw,        Kh + o);
        cp_async16(sbase + AS_K + 8192 + sw, Kl + o);
        cp_async16(sbase + AS_V + sw,        Vh + o);
        cp_async16(sbase + AS_V + 8192 + sw, Vl + o);
    }
    CP_COMMIT();

    float oacc[2][2][4];
#pragma unroll
    for (int mt = 0; mt < 2; mt++)
#pragma unroll
        for (int nt = 0; nt < 2; nt++)
#pragma unroll
            for (int c = 0; c < 4; c++) oacc[mt][nt][c] = 0.f;
    float denAcc = 0.f;

    const int prow = tid >> 2;           // P-phase: quarter-row per thread
    const int pcol = (tid & 3) * 16;
    const u64* mrowPtr = g_mbits + ((size_t)b * Sq + q0 + prow) * (Sq / 64);

    const int arow = wm * 32 + (lane & 15);
    const int brow = wn * 16 + (lane & 15);
    const int vrow0 = (lane & 7) + ((lane >> 4) << 3);
    const int vch   = wn * 2 + ((lane >> 3) & 1);

    const int NT = Sq / 64;
#pragma unroll 1
    for (int kt = 0; kt < NT; kt++) {
        const int buf = kt & 1;
        CP_WAIT(0);
        __syncthreads();   // K/V[buf] ready; prev PV reads of this buf done

        // prefetch next K/V stage (1 iter: 512 chunks)
        if (kt + 1 < NT) {
            const uint32_t kb = sbase + AS_K + (1 - buf) * 16384;
            const uint32_t vb = sbase + AS_V + (1 - buf) * 16384;
            const size_t gk = (size_t)(kt + 1) * 64 * DHq;
            int row = tid >> 3, ch = tid & 7;
            uint32_t sw = swz(row, ch);
            size_t o = gk + (size_t)row * DHq + ch * 8;
            cp_async16(kb + sw,        Kh + o);
            cp_async16(kb + 8192 + sw, Kl + o);
            cp_async16(vb + sw,        Vh + o);
            cp_async16(vb + 8192 + sw, Vl + o);
            CP_COMMIT();
        }

        // mask slice for this thread's quarter-row (16 bits)
        const uint32_t mbits = (uint32_t)(mrowPtr[kt] >> pcol);

        // ---- S = Q K^T (3-term split) ----
        float sacc[2][2][4];
#pragma unroll
        for (int mt = 0; mt < 2; mt++)
#pragma unroll
            for (int nt = 0; nt < 2; nt++)
#pragma unroll
                for (int c = 0; c < 4; c++) sacc[mt][nt][c] = 0.f;

        const uint32_t kbh = sbase + AS_K + buf * 16384;
        const uint32_t kbl = kbh + 8192;
#pragma unroll
        for (int ks = 0; ks < 4; ks++) {
            const int ch = ks * 2 + (lane >> 4);
            uint32_t ah[2][4], al[2][4];
#pragma unroll
            for (int mt = 0; mt < 2; mt++) {
                uint32_t sw = swz(arow + mt * 16, ch);
                ldsm4(ah[mt], sbase + AS_QH + sw);
                ldsm4(al[mt], sbase + AS_QL + sw);
            }
            uint32_t bh[4], bl[4];
            {
                uint32_t sw = swz(brow, ch);
                ldsm4(bh, kbh + sw);
                ldsm4(bl, kbl + sw);
            }
#pragma unroll
            for (int mt = 0; mt < 2; mt++)
#pragma unroll
                for (int hh = 0; hh < 2; hh++) {
                    mma16816(sacc[mt][hh], ah[mt], bh[hh], bh[2 + hh]);
                    mma16816(sacc[mt][hh], ah[mt], bl[hh], bl[2 + hh]);
                    mma16816(sacc[mt][hh], al[mt], bh[hh], bh[2 + hh]);
                }
        }

        // ---- store S fragments to smem (fp32) ----
#pragma unroll
        for (int mt = 0; mt < 2; mt++)
#pragma unroll
            for (int nt = 0; nt < 2; nt++) {
                int r0 = wm * 32 + mt * 16 + (lane >> 2);
                int c0 = wn * 16 + nt * 8 + (lane & 3) * 2;
                float2 v0, v1;
                v0.x = sacc[mt][nt][0]; v0.y = sacc[mt][nt][1];
                v1.x = sacc[mt][nt][2]; v1.y = sacc[mt][nt][3];
                *(float2*)&sS[r0 * 68 + c0]       = v0;
                *(float2*)&sS[(r0 + 8) * 68 + c0] = v1;
            }
        __syncthreads();

        // ---- P = bit ? exp(S) : 0 ; row-sums ; split bf16 to smem ----
#pragma unroll
        for (int chk = 0; chk < 2; chk++) {
            int cb = pcol + chk * 8;
            float4 x0 = *(const float4*)&sS[prow * 68 + cb];
            float4 x1 = *(const float4*)&sS[prow * 68 + cb + 4];
            float p[8];
            p[0] = __expf(x0.x); p[1] = __expf(x0.y);
            p[2] = __expf(x0.z); p[3] = __expf(x0.w);
            p[4] = __expf(x1.x); p[5] = __expf(x1.y);
            p[6] = __expf(x1.z); p[7] = __expf(x1.w);
#pragma unroll
            for (int j = 0; j < 8; j++) {
                if (!((mbits >> (chk * 8 + j)) & 1u)) p[j] = 0.f;
                denAcc += p[j];
            }
            uint32_t hv[4], lv[4];
#pragma unroll
            for (int j = 0; j < 4; j++) {
                __nv_bfloat162 h2, l2;
                h2.x = __float2bfloat16(p[2 * j]);
                h2.y = __float2bfloat16(p[2 * j + 1]);
                l2.x = __float2bfloat16(p[2 * j]     - __bfloat162float(h2.x));
                l2.y = __float2bfloat16(p[2 * j + 1] - __bfloat162float(h2.y));
                hv[j] = *(uint32_t*)&h2;
                lv[j] = *(uint32_t*)&l2;
            }
            uint32_t sw = swz(prow, (tid & 3) * 2 + chk);
            *(uint4*)(smem + AS_PH + sw) = *(uint4*)hv;
            *(uint4*)(smem + AS_PL + sw) = *(uint4*)lv;
        }
        __syncthreads();

        // ---- O += P V (3-term split; V via ldmatrix.trans) ----
        const uint32_t vbh = sbase + AS_V + buf * 16384;
        const uint32_t vbl = vbh + 8192;
#pragma unroll
        for (int ks = 0; ks < 4; ks++) {
            const int ch = ks * 2 + (lane >> 4);
            uint32_t ah[2][4], al[2][4];
#pragma unroll
            for (int mt = 0; mt < 2; mt++) {
                uint32_t sw = swz(arow + mt * 16, ch);
                ldsm4(ah[mt], sbase + AS_PH + sw);
                ldsm4(al[mt], sbase + AS_PL + sw);
            }
            uint32_t bh[4], bl[4];
            {
                uint32_t sw = swz(ks * 16 + vrow0, vch);
                ldsm4t(bh, vbh + sw);
                ldsm4t(bl, vbl + sw);
            }
#pragma unroll
            for (int mt = 0; mt < 2; mt++)
#pragma unroll
                for (int hh = 0; hh < 2; hh++) {
                    mma16816(oacc[mt][hh], ah[mt], bh[hh], bh[2 + hh]);
                    mma16816(oacc[mt][hh], ah[mt], bl[hh], bl[2 + hh]);
                    mma16816(oacc[mt][hh], al[mt], bh[hh], bh[2 + hh]);
                }
        }
    }

    // ---- epilogue: normalize, write split context + resT ----
    sDen[tid] = denAcc;
    __syncthreads();

#pragma unroll
    for (int mt = 0; mt < 2; mt++)
#pragma unroll
        for (int nt = 0; nt < 2; nt++)
#pragma unroll
            for (int rr = 0; rr < 2; rr++) {
                int r   = wm * 32 + mt * 16 + (lane >> 2) + rr * 8;
                int col = wn * 16 + nt * 8 + (lane & 3) * 2;
                float dn = sDen[4 * r] + sDen[4 * r + 1]
                         + sDen[4 * r + 2] + sDen[4 * r + 3];
                float inv = dn > 0.f ? 1.f / dn : 0.f;     // NaN->0 semantics
                float x0 = oacc[mt][nt][rr * 2 + 0] * inv;
                float x1 = oacc[mt][nt][rr * 2 + 1] * inv;
                int s2 = q0 + r;
                size_t co = ((size_t)b * Sq + s2) * Dq + h * DHq + col;
                __nv_bfloat162 hv, lv;
                hv.x = __float2bfloat16(x0);
                hv.y = __float2bfloat16(x1);
                lv.x = __float2bfloat16(x0 - __bfloat162float(hv.x));
                lv.y = __float2bfloat16(x1 - __bfloat162float(hv.y));
                *(__nv_bfloat162*)(ctx_h + co) = hv;
                *(__nv_bfloat162*)(ctx_l + co) = lv;
                if (resT) {
                    float2 rv; rv.x = x0; rv.y = x1;
                    *(float2*)(resT + (((size_t)h * Bq + b) * Sq + s2) * DHq + col) = rv;
                }
            }
}

// ---------------------------------------------------------------------------
extern "C" void kernel_launch(void* const* d_in, const int* in_sizes, int n_in,
                              void* d_out, int out_size)
{
    const float* query = (const float*)d_in[0];
    const float* key_  = (const float*)d_in[1];
    const float* value = (const float*)d_in[2];
    const void*  mask  = d_in[3];
    const float* Wq    = (const float*)d_in[4];
    const float* Wk    = (const float*)d_in[5];
    const float* Wv    = (const float*)d_in[6];
    const float* fcw   = (const float*)d_in[7];
    const float* fcb   = (const float*)d_in[8];
    float* out = (float*)d_out;

    __nv_bfloat16 *qh, *ql, *kh, *kl, *vh, *vl;
    __nv_bfloat16 *xhi, *xlo, *yhi, *ylo, *zhi, *zlo;
    __nv_bfloat16 *w1h, *w1l, *w2h, *w2l, *w3h, *w3l, *w4h, *w4l;
    cudaGetSymbolAddress((void**)&qh,  g_qh);
    cudaGetSymbolAddress((void**)&ql,  g_ql);
    cudaGetSymbolAddress((void**)&kh,  g_kh);
    cudaGetSymbolAddress((void**)&kl,  g_kl);
    cudaGetSymbolAddress((void**)&vh,  g_vh);
    cudaGetSymbolAddress((void**)&vl,  g_vl);
    cudaGetSymbolAddress((void**)&xhi, g_xhi);
    cudaGetSymbolAddress((void**)&xlo, g_xlo);
    cudaGetSymbolAddress((void**)&yhi, g_yhi);
    cudaGetSymbolAddress((void**)&ylo, g_ylo);
    cudaGetSymbolAddress((void**)&zhi, g_zhi);
    cudaGetSymbolAddress((void**)&zlo, g_zlo);
    cudaGetSymbolAddress((void**)&w1h, g_w1h);
    cudaGetSymbolAddress((void**)&w1l, g_w1l);
    cudaGetSymbolAddress((void**)&w2h, g_w2h);
    cudaGetSymbolAddress((void**)&w2l, g_w2l);
    cudaGetSymbolAddress((void**)&w3h, g_w3h);
    cudaGetSymbolAddress((void**)&w3l, g_w3l);
    cudaGetSymbolAddress((void**)&w4h, g_w4h);
    cudaGetSymbolAddress((void**)&w4l, g_w4l);

    cudaFuncSetAttribute(gemm_tc_kernel,
                         cudaFuncAttributeMaxDynamicSharedMemorySize, GSMEM);
    cudaFuncSetAttribute(gemm_qkv_kernel,
                         cudaFuncAttributeMaxDynamicSharedMemorySize, GSMEM);
    cudaFuncSetAttribute(attention_tc_kernel,
                         cudaFuncAttributeMaxDynamicSharedMemorySize, ATT_SMEM);

    detect_mask_kernel<<<1, 32>>>((const unsigned char*)mask);
    mask_bits_kernel<<<MWORDS / 256, 256>>>(mask);

    const int M = Bq * Sq;               // 8192
    const int nX = M * Dq, nW = Dq * Dq;
    const int bX = nX / 1024, bW = nW / 1024;

    // one batched split launch: q, k, v, Wq, Wk, Wv, fcw
    SplitParams sp{};
    const float* srcs[7] = {query, key_, value, Wq, Wk, Wv, fcw};
    __nv_bfloat16* his[7] = {xhi, yhi, zhi, w1h, w2h, w3h, w4h};
    __nv_bfloat16* los[7] = {xlo, ylo, zlo, w1l, w2l, w3l, w4l};
    int off = 0;
    for (int t = 0; t < 7; t++) {
        sp.src[t] = srcs[t]; sp.hi[t] = his[t]; sp.lo[t] = los[t];
        sp.blkStart[t] = off;
        off += (t < 3) ? bX : bW;
    }
    sp.blkStart[7] = off;
    sp.nT = 7;
    split_all_kernel<<<off, 256>>>(sp);

    // merged Q/K/V projection GEMMs (Q pre-scaled by 1/8)
    QKVParams qp{};
    qp.Ahi[0] = xhi; qp.Alo[0] = xlo; qp.Bhi[0] = w1h; qp.Blo[0] = w1l;
    qp.oh[0] = qh; qp.ol[0] = ql; qp.scale[0] = 0.125f;
    qp.Ahi[1] = yhi; qp.Alo[1] = ylo; qp.Bhi[1] = w2h; qp.Blo[1] = w2l;
    qp.oh[1] = kh; qp.ol[1] = kl; qp.scale[1] = 1.0f;
    qp.Ahi[2] = zhi; qp.Alo[2] = zlo; qp.Bhi[2] = w3h; qp.Blo[2] = w3l;
    qp.oh[2] = vh; qp.ol[2] = vl; qp.scale[2] = 1.0f;
    dim3 gq(Dq / 64, M / 128, 3);      // (16, 64, 3)
    gemm_qkv_kernel<<<gq, 256, GSMEM>>>(qp, M, Dq, Dq);

    // attention writes context split into xhi/xlo + resT fp32
    float* resT = (out_size >= 2 * BSDq) ? (out + BSDq) : nullptr;
    attention_tc_kernel<<<Bq * Hq * (Sq / 128), 512, ATT_SMEM>>>(resT, xhi, xlo);

    // final FC: fp32 out with bias
    dim3 gf(Dq / 64, M / 128);         // (16, 64)
    gemm_tc_kernel<<<gf, 256, GSMEM>>>(xhi, xlo, w4h, w4l, fcb, out, M, Dq, Dq);
}

// round 13
// speedup vs baseline: 1.9471x; 1.0093x over previous
#include <cuda_runtime.h>
#include <cuda_bf16.h>
#include <cstdint>
#include <cstddef>

// Problem constants
#define Bq   4
#define Sq   2048
#define Dq   1024
#define Hq   16
#define DHq  64
#define BSDq (Bq*Sq*Dq)   // 8388608
#define MWORDS (Bq*Sq*(Sq/64))   // 262144 u64 mask words

typedef unsigned long long u64;

// ---------------- generic-PTX tensor-core helpers (sm_80+ ISA) -------------
__device__ __forceinline__ uint32_t smem_u32(const void* p) {
    uint32_t a;
    asm("{ .reg .u64 t; cvta.to.shared.u64 t, %1; cvt.u32.u64 %0, t; }"
        : "=r"(a) : "l"(p));
    return a;
}
__device__ __forceinline__ void cp_async16(uint32_t s, const void* g) {
    asm volatile("cp.async.cg.shared.global [%0], [%1], 16;" :: "r"(s), "l"(g));
}
#define CP_COMMIT() asm volatile("cp.async.commit_group;" ::: "memory")
#define CP_WAIT(n)  asm volatile("cp.async.wait_group %0;" :: "n"(n) : "memory")

__device__ __forceinline__ void ldsm4(uint32_t* r, uint32_t addr) {
    asm volatile("ldmatrix.sync.aligned.m8n8.x4.shared.b16 {%0,%1,%2,%3}, [%4];"
                 : "=r"(r[0]), "=r"(r[1]), "=r"(r[2]), "=r"(r[3]) : "r"(addr));
}
__device__ __forceinline__ void ldsm4t(uint32_t* r, uint32_t addr) {
    asm volatile("ldmatrix.sync.aligned.m8n8.x4.trans.shared.b16 {%0,%1,%2,%3}, [%4];"
                 : "=r"(r[0]), "=r"(r[1]), "=r"(r[2]), "=r"(r[3]) : "r"(addr));
}
// D(f32) += A(bf16) * B(bf16); m16n8k16 row.col
__device__ __forceinline__ void mma16816(float* d, const uint32_t* a,
                                         uint32_t b0, uint32_t b1) {
    asm volatile(
        "mma.sync.aligned.m16n8k16.row.col.f32.bf16.bf16.f32 "
        "{%0,%1,%2,%3}, {%4,%5,%6,%7}, {%8,%9}, {%0,%1,%2,%3};"
        : "+f"(d[0]), "+f"(d[1]), "+f"(d[2]), "+f"(d[3])
        : "r"(a[0]), "r"(a[1]), "r"(a[2]), "r"(a[3]), "r"(b0), "r"(b1));
}
// byte offset of (row, 16B-chunk) in a [rows][64 bf16] tile, xor swizzle
__device__ __forceinline__ uint32_t swz(int row, int ch) {
    uint32_t off = (uint32_t)(row * 128 + ch * 16);
    return off ^ (((uint32_t)row & 7u) << 4);
}
__device__ __forceinline__ uint32_t packbf2(float a, float b) {
    __nv_bfloat162 v;
    v.x = __float2bfloat16(a);
    v.y = __float2bfloat16(b);
    return *(uint32_t*)&v;
}

// ---------------- scratch (device globals: allocation-free rule) -----------
__device__ int g_mask_kind;                      // 0=uint8, else 4-byte elems
__device__ __align__(16) u64 g_mbits[MWORDS];    // packed mask bits [b][kt][row]
__device__ __align__(16) __nv_bfloat16 g_qh[BSDq];
__device__ __align__(16) __nv_bfloat16 g_ql[BSDq];
__device__ __align__(16) __nv_bfloat16 g_kh[BSDq];
__device__ __align__(16) __nv_bfloat16 g_kl[BSDq];
__device__ __align__(16) __nv_bfloat16 g_vh[BSDq];
__device__ __align__(16) __nv_bfloat16 g_vl[BSDq];
__device__ __align__(16) __nv_bfloat16 g_xhi[BSDq];   // q split / ctx split
__device__ __align__(16) __nv_bfloat16 g_xlo[BSDq];
__device__ __align__(16) __nv_bfloat16 g_yhi[BSDq];   // k split
__device__ __align__(16) __nv_bfloat16 g_ylo[BSDq];
__device__ __align__(16) __nv_bfloat16 g_zhi[BSDq];   // v split
__device__ __align__(16) __nv_bfloat16 g_zlo[BSDq];
__device__ __align__(16) __nv_bfloat16 g_w1h[Dq * Dq]; // Wq
__device__ __align__(16) __nv_bfloat16 g_w1l[Dq * Dq];
__device__ __align__(16) __nv_bfloat16 g_w2h[Dq * Dq]; // Wk
__device__ __align__(16) __nv_bfloat16 g_w2l[Dq * Dq];
__device__ __align__(16) __nv_bfloat16 g_w3h[Dq * Dq]; // Wv
__device__ __align__(16) __nv_bfloat16 g_w3l[Dq * Dq];
__device__ __align__(16) __nv_bfloat16 g_w4h[Dq * Dq]; // fc_w
__device__ __align__(16) __nv_bfloat16 g_w4l[Dq * Dq];

// ---------------------------------------------------------------------------
__global__ void detect_mask_kernel(const unsigned char* __restrict__ m) {
    if (threadIdx.x != 0) return;
    int c0 = 0, c1 = 0, c2 = 0, c3 = 0;
    for (int i = 0; i < 4096; i += 4) {
        if (m[i + 0]) c0++;
        if (m[i + 1]) c1++;
        if (m[i + 2]) c2++;
        if (m[i + 3]) c3++;
    }
    int kind;
    if (c1 == 0 && c2 == 0 && c3 == 0) kind = 1;   // int32
    else if (c0 == 0 && c1 == 0)       kind = 2;   // float32
    else                               kind = 0;   // uint8
    g_mask_kind = kind;
}

// pack mask -> u64 words, stored TRANSPOSED: [b][kt][row] for coalesced
// per-k-tile row access in the attention kernel.
__global__ __launch_bounds__(256)
void mask_bits_kernel(const void* __restrict__ mask) {
    int w = blockIdx.x * 256 + threadIdx.x;   // linear over [b][row][kt]
    if (w >= MWORDS) return;
    u64 bits = 0;
    if (g_mask_kind == 0) {
        const uint4* p = (const uint4*)((const unsigned char*)mask + (size_t)w * 64);
#pragma unroll
        for (int q = 0; q < 4; q++) {
            uint4 v = p[q];
            const uint32_t ww[4] = {v.x, v.y, v.z, v.w};
#pragma unroll
            for (int k = 0; k < 4; k++)
#pragma unroll
                for (int j = 0; j < 4; j++)
                    if ((ww[k] >> (8 * j)) & 0xffu)
                        bits |= 1ull << (q * 16 + k * 4 + j);
        }
    } else {   // 4-byte elements
        const uint4* p = (const uint4*)((const uint32_t*)mask + (size_t)w * 64);
#pragma unroll
        for (int q = 0; q < 16; q++) {
            uint4 v = p[q];
            if (v.x) bits |= 1ull << (q * 4 + 0);
            if (v.y) bits |= 1ull << (q * 4 + 1);
            if (v.z) bits |= 1ull << (q * 4 + 2);
            if (v.w) bits |= 1ull << (q * 4 + 3);
        }
    }
    int kt  = w & 31;
    int row = (w >> 5) & (Sq - 1);
    int b   = w >> 16;
    g_mbits[(((size_t)b * 32 + kt) << 11) + row] = bits;
}

// ---- batched fp32 -> bf16 hi/lo split for up to 8 tensors -----------------
struct SplitParams {
    const float* src[8];
    __nv_bfloat16* hi[8];
    __nv_bfloat16* lo[8];
    int blkStart[9];
    int nT;
};

__global__ __launch_bounds__(256)
void split_all_kernel(SplitParams P)
{
    int blk = blockIdx.x;
    int t = 0;
    while (t + 1 < P.nT && blk >= P.blkStart[t + 1]) t++;
    int i = (blk - P.blkStart[t]) * 256 * 4 + threadIdx.x * 4;
    const float* x = P.src[t];
    float4 v = *(const float4*)(x + i);
    __nv_bfloat16 h0 = __float2bfloat16(v.x), h1 = __float2bfloat16(v.y);
    __nv_bfloat16 h2 = __float2bfloat16(v.z), h3 = __float2bfloat16(v.w);
    __nv_bfloat162 hA, hB, lA, lB;
    hA.x = h0; hA.y = h1; hB.x = h2; hB.y = h3;
    lA.x = __float2bfloat16(v.x - __bfloat162float(h0));
    lA.y = __float2bfloat16(v.y - __bfloat162float(h1));
    lB.x = __float2bfloat16(v.z - __bfloat162float(h2));
    lB.y = __float2bfloat16(v.w - __bfloat162float(h3));
    *(__nv_bfloat162*)(P.hi[t] + i)     = hA;
    *(__nv_bfloat162*)(P.hi[t] + i + 2) = hB;
    *(__nv_bfloat162*)(P.lo[t] + i)     = lA;
    *(__nv_bfloat162*)(P.lo[t] + i + 2) = lB;
}

// ---------------------------------------------------------------------------
// HMMA split-bf16 GEMM core: 128x64 CTA tile, 256 threads, 2 CTAs/SM.
// (unchanged from R12 — validated at tensor=63.8%)
// ---------------------------------------------------------------------------
#define GSTAGE  49152
#define GA_HI   0
#define GA_LO   16384
#define GB_HI   32768
#define GB_LO   40960
#define GSMEM   (2*GSTAGE)          // 96KB

__device__ __forceinline__ void gemm_core(
    const __nv_bfloat16* __restrict__ Ahi, const __nv_bfloat16* __restrict__ Alo,
    const __nv_bfloat16* __restrict__ Bhi, const __nv_bfloat16* __restrict__ Blo,
    const float* __restrict__ bias, float* __restrict__ out32,
    __nv_bfloat16* __restrict__ outh, __nv_bfloat16* __restrict__ outl,
    float scale, int M, int N, int K, char* smem)
{
    const uint32_t sbase = smem_u32(smem);
    const int tid  = threadIdx.x;
    const int wid  = tid >> 5;
    const int lane = tid & 31;
    const int m0 = blockIdx.y * 128;
    const int n0 = blockIdx.x * 64;
    const int wm = wid & 3;
    const int wn = wid >> 2;

    float acc[2][4][4];
#pragma unroll
    for (int i = 0; i < 2; i++)
#pragma unroll
        for (int j = 0; j < 4; j++)
#pragma unroll
            for (int c = 0; c < 4; c++) acc[i][j][c] = 0.f;

    auto load_stage = [&](int t, int buf) {
        const int k0 = t * 64;
        const uint32_t sb = sbase + buf * GSTAGE;
#pragma unroll
        for (int l = 0; l < 4; l++) {
            int idx = l * 256 + tid;
            int row = idx >> 3, ch = idx & 7;
            uint32_t sw = swz(row, ch);
            size_t ao = (size_t)(m0 + row) * K + k0 + ch * 8;
            cp_async16(sb + GA_HI + sw, Ahi + ao);
            cp_async16(sb + GA_LO + sw, Alo + ao);
        }
#pragma unroll
        for (int l = 0; l < 2; l++) {
            int idx = l * 256 + tid;
            int row = idx >> 3, ch = idx & 7;
            uint32_t sw = swz(row, ch);
            size_t bo = (size_t)(n0 + row) * K + k0 + ch * 8;
            cp_async16(sb + GB_HI + sw, Bhi + bo);
            cp_async16(sb + GB_LO + sw, Blo + bo);
        }
    };

    load_stage(0, 0);
    CP_COMMIT();

    const int arow = wm * 32 + (lane & 15);
    const int brow = wn * 32 + (lane & 15);

    const int NT = K / 64;
#pragma unroll 1
    for (int t = 0; t < NT; t++) {
        const int buf = t & 1;
        if (t + 1 < NT) {
            load_stage(t + 1, (t + 1) & 1);
            CP_COMMIT();
            CP_WAIT(1);
        } else {
            CP_WAIT(0);
        }
        __syncthreads();

        const uint32_t sb = sbase + buf * GSTAGE;
#pragma unroll
        for (int ks = 0; ks < 4; ks++) {
            const int ch = ks * 2 + (lane >> 4);
            uint32_t ah[2][4], al[2][4];
#pragma unroll
            for (int mt = 0; mt < 2; mt++) {
                uint32_t sw = swz(arow + mt * 16, ch);
                ldsm4(ah[mt], sb + GA_HI + sw);
                ldsm4(al[mt], sb + GA_LO + sw);
            }
            uint32_t bh[2][4], bl[2][4];
#pragma unroll
            for (int nb = 0; nb < 2; nb++) {
                uint32_t sw = swz(brow + nb * 16, ch);
                ldsm4(bh[nb], sb + GB_HI + sw);
                ldsm4(bl[nb], sb + GB_LO + sw);
            }
#pragma unroll
            for (int mt = 0; mt < 2; mt++)
#pragma unroll
                for (int nt = 0; nt < 4; nt++) {
                    const int nb = nt >> 1, hh = nt & 1;
                    mma16816(acc[mt][nt], ah[mt], bh[nb][hh], bh[nb][2 + hh]);
                    mma16816(acc[mt][nt], ah[mt], bl[nb][hh], bl[nb][2 + hh]);
                    mma16816(acc[mt][nt], al[mt], bh[nb][hh], bh[nb][2 + hh]);
                }
        }
        __syncthreads();
    }

#pragma unroll
    for (int mt = 0; mt < 2; mt++) {
#pragma unroll
        for (int nt = 0; nt < 4; nt++) {
            int row = m0 + wm * 32 + mt * 16 + (lane >> 2);
            int col = n0 + wn * 32 + nt * 8 + (lane & 3) * 2;
            if (out32) {
                float2 v0, v1;
                v0.x = acc[mt][nt][0]; v0.y = acc[mt][nt][1];
                v1.x = acc[mt][nt][2]; v1.y = acc[mt][nt][3];
                if (bias) {
                    float b0 = bias[col], b1 = bias[col + 1];
                    v0.x += b0; v0.y += b1;
                    v1.x += b0; v1.y += b1;
                }
                *(float2*)(out32 + (size_t)row * N + col)       = v0;
                *(float2*)(out32 + (size_t)(row + 8) * N + col) = v1;
            } else {
#pragma unroll
                for (int rr = 0; rr < 2; rr++) {
                    size_t o = (size_t)(row + rr * 8) * N + col;
                    float x0 = acc[mt][nt][rr * 2 + 0] * scale;
                    float x1 = acc[mt][nt][rr * 2 + 1] * scale;
                    __nv_bfloat162 hv, lv;
                    hv.x = __float2bfloat16(x0);
                    hv.y = __float2bfloat16(x1);
                    lv.x = __float2bfloat16(x0 - __bfloat162float(hv.x));
                    lv.y = __float2bfloat16(x1 - __bfloat162float(hv.y));
                    *(__nv_bfloat162*)(outh + o) = hv;
                    *(__nv_bfloat162*)(outl + o) = lv;
                }
            }
        }
    }
}

__global__ __launch_bounds__(256, 2)
void gemm_tc_kernel(const __nv_bfloat16* __restrict__ Ahi,
                    const __nv_bfloat16* __restrict__ Alo,
                    const __nv_bfloat16* __restrict__ Bhi,
                    const __nv_bfloat16* __restrict__ Blo,
                    const float* __restrict__ bias, float* __restrict__ out32,
                    int M, int N, int K)
{
    extern __shared__ char smem[];
    gemm_core(Ahi, Alo, Bhi, Blo, bias, out32, nullptr, nullptr, 1.0f,
              M, N, K, smem);
}

struct QKVParams {
    const __nv_bfloat16 *Ahi[3], *Alo[3], *Bhi[3], *Blo[3];
    __nv_bfloat16 *oh[3], *ol[3];
    float scale[3];
};
__global__ __launch_bounds__(256, 2)
void gemm_qkv_kernel(QKVParams P, int M, int N, int K)
{
    extern __shared__ char smem[];
    const int z = blockIdx.z;
    gemm_core(P.Ahi[z], P.Alo[z], P.Bhi[z], P.Blo[z], nullptr, nullptr,
              P.oh[z], P.ol[z], P.scale[z], M, N, K, smem);
}

// ---------------------------------------------------------------------------
// HMMA flash attention, register-resident softmax:
// Each wn-warp computes PV partials over its OWN 16 k-cols -> P stays in the
// QK accumulator registers (A-frag layout == accumulator layout). Mask via
// k-tile-major bitmask (quad-shared LDG.64). One barrier per k-tile.
// Cross-wn O reduction at the end in smem aliased over the dead K buffer.
// ---------------------------------------------------------------------------
#define AS_QH   0
#define AS_QL   16384
#define AS_K    32768                 // [buf][hi 8192 | lo 8192] x2 = 32KB
#define AS_V    65536                 // 32KB
#define AS_SO   32768                 // epilogue alias over K region (32KB)
#define AS_DEN  98304                 // 512 floats
#define ATT_SMEM (AS_DEN + 2048)

__global__ __launch_bounds__(512, 1)
void attention_tc_kernel(float* __restrict__ resT,
                         __nv_bfloat16* __restrict__ ctx_h,
                         __nv_bfloat16* __restrict__ ctx_l)
{
    extern __shared__ char smem[];
    const uint32_t sbase = smem_u32(smem);
    float* sDen4 = (float*)(smem + AS_DEN);   // [4 wn][128]

    const int tid  = threadIdx.x;
    const int wid  = tid >> 5;
    const int lane = tid & 31;
    const int wm = wid & 3;        // 4 m-warps (32 q-rows each)
    const int wn = wid >> 2;       // 4 k-slice warps (16 k-cols each)
    const int blk = blockIdx.x;
    const int qt  = blk & 15;
    const int h   = (blk >> 4) & 15;
    const int b   = blk >> 8;
    const int q0  = qt * 128;

    const size_t headBase = (size_t)b * Sq * Dq + (size_t)h * Sq * DHq;
    const __nv_bfloat16* Qh = g_qh + headBase;
    const __nv_bfloat16* Ql = g_ql + headBase;
    const __nv_bfloat16* Kh = g_kh + headBase;
    const __nv_bfloat16* Kl = g_kl + headBase;
    const __nv_bfloat16* Vh = g_vh + headBase;
    const __nv_bfloat16* Vl = g_vl + headBase;

    // ---- initial loads: Q (persistent) + K/V stage 0 ----
#pragma unroll
    for (int l = 0; l < 2; l++) {
        int idx = l * 512 + tid;
        int row = idx >> 3, ch = idx & 7;
        uint32_t sw = swz(row, ch);
        size_t o = (size_t)(q0 + row) * DHq + ch * 8;
        cp_async16(sbase + AS_QH + sw, Qh + o);
        cp_async16(sbase + AS_QL + sw, Ql + o);
    }
    {
        int row = tid >> 3, ch = tid & 7;
        uint32_t sw = swz(row, ch);
        size_t o = (size_t)row * DHq + ch * 8;
        cp_async16(sbase + AS_K + sw,        Kh + o);
        cp_async16(sbase + AS_K + 8192 + sw, Kl + o);
        cp_async16(sbase + AS_V + sw,        Vh + o);
        cp_async16(sbase + AS_V + 8192 + sw, Vl + o);
    }
    CP_COMMIT();

    // O partials: [mt][ds][hh2][4] = rows wm*32+mt*16+(r,+8), cols ds*16+hh2*8+c
    float oacc[2][4][2][4];
#pragma unroll
    for (int mt = 0; mt < 2; mt++)
#pragma unroll
        for (int ds = 0; ds < 4; ds++)
#pragma unroll
            for (int hh = 0; hh < 2; hh++)
#pragma unroll
                for (int c = 0; c < 4; c++) oacc[mt][ds][hh][c] = 0.f;
    float denAcc[2][2] = {{0.f, 0.f}, {0.f, 0.f}};

    const int arow = wm * 32 + (lane & 15);
    const int brow = wn * 16 + (lane & 15);
    const int vrow0 = (lane & 7) + ((lane >> 4) << 3);
    const u64* mb = g_mbits + (((size_t)b * 32) << 11) + q0;

    const int NT = Sq / 64;
#pragma unroll 1
    for (int kt = 0; kt < NT; kt++) {
        const int buf = kt & 1;
        CP_WAIT(0);
        __syncthreads();   // K/V[buf] ready; all prev-tile V reads complete

        // prefetch next K/V stage into the other buffer
        if (kt + 1 < NT) {
            const uint32_t kb = sbase + AS_K + (1 - buf) * 16384;
            const uint32_t vb = sbase + AS_V + (1 - buf) * 16384;
            const size_t gk = (size_t)(kt + 1) * 64 * DHq;
            int row = tid >> 3, ch = tid & 7;
            uint32_t sw = swz(row, ch);
            size_t o = gk + (size_t)row * DHq + ch * 8;
            cp_async16(kb + sw,        Kh + o);
            cp_async16(kb + 8192 + sw, Kl + o);
            cp_async16(vb + sw,        Vh + o);
            cp_async16(vb + 8192 + sw, Vl + o);
            CP_COMMIT();
        }

        // ---- S = Q K^T (3-term split), this warp's 16 k-cols ----
        float sacc[2][2][4];
#pragma unroll
        for (int mt = 0; mt < 2; mt++)
#pragma unroll
            for (int hh = 0; hh < 2; hh++)
#pragma unroll
                for (int c = 0; c < 4; c++) sacc[mt][hh][c] = 0.f;

        const uint32_t kbh = sbase + AS_K + buf * 16384;
        const uint32_t kbl = kbh + 8192;
#pragma unroll
        for (int ks = 0; ks < 4; ks++) {
            const int ch = ks * 2 + (lane >> 4);
            uint32_t ah[2][4], al[2][4];
#pragma unroll
            for (int mt = 0; mt < 2; mt++) {
                uint32_t sw = swz(arow + mt * 16, ch);
                ldsm4(ah[mt], sbase + AS_QH + sw);
                ldsm4(al[mt], sbase + AS_QL + sw);
            }
            uint32_t bh[4], bl[4];
            {
                uint32_t sw = swz(brow, ch);
                ldsm4(bh, kbh + sw);
                ldsm4(bl, kbl + sw);
            }
#pragma unroll
            for (int mt = 0; mt < 2; mt++)
#pragma unroll
                for (int hh = 0; hh < 2; hh++) {
                    mma16816(sacc[mt][hh], ah[mt], bh[hh], bh[2 + hh]);
                    mma16816(sacc[mt][hh], ah[mt], bl[hh], bl[2 + hh]);
                    mma16816(sacc[mt][hh], al[mt], bh[hh], bh[2 + hh]);
                }
        }

        // ---- softmax in registers -> P A-fragments (hi/lo) ----
        // A-frag reg index = hh*2 + rr : a0=(r,c) a1=(r+8,c) a2=(r,c+8) a3=(r+8,c+8)
        uint32_t phi[2][4], plo[2][4];
        const u64* mtile = mb + ((size_t)kt << 11);
#pragma unroll
        for (int mt = 0; mt < 2; mt++) {
#pragma unroll
            for (int rr = 0; rr < 2; rr++) {
                const int r = wm * 32 + mt * 16 + (lane >> 2) + rr * 8;
                const u64 mword = mtile[r];
#pragma unroll
                for (int hh = 0; hh < 2; hh++) {
                    const int colg = wn * 16 + hh * 8 + (lane & 3) * 2;
                    float p0 = ((mword >> colg) & 1ull)
                             ? __expf(sacc[mt][hh][rr * 2 + 0]) : 0.f;
                    float p1 = ((mword >> (colg + 1)) & 1ull)
                             ? __expf(sacc[mt][hh][rr * 2 + 1]) : 0.f;
                    denAcc[mt][rr] += p0 + p1;
                    __nv_bfloat162 h2;
                    h2.x = __float2bfloat16(p0);
                    h2.y = __float2bfloat16(p1);
                    phi[mt][hh * 2 + rr] = *(uint32_t*)&h2;
                    plo[mt][hh * 2 + rr] =
                        packbf2(p0 - __bfloat162float(h2.x),
                                p1 - __bfloat162float(h2.y));
                }
            }
        }

        // ---- O += P V over this warp's k-slice (A in registers) ----
        const uint32_t vbh = sbase + AS_V + buf * 16384;
        const uint32_t vbl = vbh + 8192;
#pragma unroll
        for (int ds = 0; ds < 4; ds++) {
            uint32_t bh[4], bl[4];
            uint32_t sw = swz(wn * 16 + vrow0, ds * 2 + ((lane >> 3) & 1));
            ldsm4t(bh, vbh + sw);
            ldsm4t(bl, vbl + sw);
#pragma unroll
            for (int mt = 0; mt < 2; mt++)
#pragma unroll
                for (int hh = 0; hh < 2; hh++) {
                    mma16816(oacc[mt][ds][hh], phi[mt], bh[hh], bh[2 + hh]);
                    mma16816(oacc[mt][ds][hh], phi[mt], bl[hh], bl[2 + hh]);
                    mma16816(oacc[mt][ds][hh], plo[mt], bh[hh], bh[2 + hh]);
                }
        }
    }

    // ---- denominator: quad shfl -> per-wn smem slot ----
#pragma unroll
    for (int mt = 0; mt < 2; mt++)
#pragma unroll
        for (int rr = 0; rr < 2; rr++) {
            float d = denAcc[mt][rr];
            d += __shfl_xor_sync(0xffffffffu, d, 1);
            d += __shfl_xor_sync(0xffffffffu, d, 2);
            if ((lane & 3) == 0)
                sDen4[wn * 128 + wm * 32 + mt * 16 + (lane >> 2) + rr * 8] = d;
        }
    __syncthreads();   // K/V smem now dead; den slots written

    // ---- cross-wn O reduction into sO (aliased over K buffer) ----
    float* sO = (float*)(smem + AS_SO);   // [128][64] fp32
#pragma unroll 1
    for (int round = 0; round < 4; round++) {
        if (wn == round) {
#pragma unroll
            for (int mt = 0; mt < 2; mt++)
#pragma unroll
                for (int ds = 0; ds < 4; ds++)
#pragma unroll
                    for (int hh = 0; hh < 2; hh++)
#pragma unroll
                        for (int rr = 0; rr < 2; rr++) {
                            int r = wm * 32 + mt * 16 + (lane >> 2) + rr * 8;
                            int c = ds * 16 + hh * 8 + (lane & 3) * 2;
                            float* p = &sO[r * 64 + c];
                            if (round == 0) {
                                p[0] = oacc[mt][ds][hh][rr * 2 + 0];
                                p[1] = oacc[mt][ds][hh][rr * 2 + 1];
                            } else {
                                p[0] += oacc[mt][ds][hh][rr * 2 + 0];
                                p[1] += oacc[mt][ds][hh][rr * 2 + 1];
                            }
                        }
        }
        __syncthreads();
    }

    // ---- final: normalize, write split context + resT ----
    {
        const int r  = tid >> 2;            // 0..127
        const int cb = (tid & 3) * 16;      // 0,16,32,48
        float dn = sDen4[r] + sDen4[128 + r] + sDen4[256 + r] + sDen4[384 + r];
        float inv = dn > 0.f ? 1.f / dn : 0.f;     // NaN->0 semantics
        int s2 = q0 + r;
        size_t co = ((size_t)b * Sq + s2) * Dq + h * DHq + cb;
        float xv[16];
#pragma unroll
        for (int j = 0; j < 16; j++) xv[j] = sO[r * 64 + cb + j] * inv;
        uint32_t hp[8], lp[8];
#pragma unroll
        for (int j = 0; j < 8; j++) {
            __nv_bfloat162 h2;
            h2.x = __float2bfloat16(xv[2 * j]);
            h2.y = __float2bfloat16(xv[2 * j + 1]);
            hp[j] = *(uint32_t*)&h2;
            lp[j] = packbf2(xv[2 * j]     - __bfloat162float(h2.x),
                            xv[2 * j + 1] - __bfloat162float(h2.y));
        }
        *(uint4*)(ctx_h + co)     = *(uint4*)&hp[0];
        *(uint4*)(ctx_h + co + 8) = *(uint4*)&hp[4];
        *(uint4*)(ctx_l + co)     = *(uint4*)&lp[0];
        *(uint4*)(ctx_l + co + 8) = *(uint4*)&lp[4];
        if (resT) {
            float* rp = resT + (((size_t)h * Bq + b) * Sq + s2) * DHq + cb;
#pragma unroll
            for (int j = 0; j < 4; j++)
                *(float4*)(rp + 4 * j) = *(float4*)&xv[4 * j];
        }
    }
}

// ---------------------------------------------------------------------------
extern "C" void kernel_launch(void* const* d_in, const int* in_sizes, int n_in,
                              void* d_out, int out_size)
{
    const float* query = (const float*)d_in[0];
    const float* key_  = (const float*)d_in[1];
    const float* value = (const float*)d_in[2];
    const void*  mask  = d_in[3];
    const float* Wq    = (const float*)d_in[4];
    const float* Wk    = (const float*)d_in[5];
    const float* Wv    = (const float*)d_in[6];
    const float* fcw   = (const float*)d_in[7];
    const float* fcb   = (const float*)d_in[8];
    float* out = (float*)d_out;

    __nv_bfloat16 *qh, *ql, *kh, *kl, *vh, *vl;
    __nv_bfloat16 *xhi, *xlo, *yhi, *ylo, *zhi, *zlo;
    __nv_bfloat16 *w1h, *w1l, *w2h, *w2l, *w3h, *w3l, *w4h, *w4l;
    cudaGetSymbolAddress((void**)&qh,  g_qh);
    cudaGetSymbolAddress((void**)&ql,  g_ql);
    cudaGetSymbolAddress((void**)&kh,  g_kh);
    cudaGetSymbolAddress((void**)&kl,  g_kl);
    cudaGetSymbolAddress((void**)&vh,  g_vh);
    cudaGetSymbolAddress((void**)&vl,  g_vl);
    cudaGetSymbolAddress((void**)&xhi, g_xhi);
    cudaGetSymbolAddress((void**)&xlo, g_xlo);
    cudaGetSymbolAddress((void**)&yhi, g_yhi);
    cudaGetSymbolAddress((void**)&ylo, g_ylo);
    cudaGetSymbolAddress((void**)&zhi, g_zhi);
    cudaGetSymbolAddress((void**)&zlo, g_zlo);
    cudaGetSymbolAddress((void**)&w1h, g_w1h);
    cudaGetSymbolAddress((void**)&w1l, g_w1l);
    cudaGetSymbolAddress((void**)&w2h, g_w2h);
    cudaGetSymbolAddress((void**)&w2l, g_w2l);
    cudaGetSymbolAddress((void**)&w3h, g_w3h);
    cudaGetSymbolAddress((void**)&w3l, g_w3l);
    cudaGetSymbolAddress((void**)&w4h, g_w4h);
    cudaGetSymbolAddress((void**)&w4l, g_w4l);

    cudaFuncSetAttribute(gemm_tc_kernel,
                         cudaFuncAttributeMaxDynamicSharedMemorySize, GSMEM);
    cudaFuncSetAttribute(gemm_qkv_kernel,
                         cudaFuncAttributeMaxDynamicSharedMemorySize, GSMEM);
    cudaFuncSetAttribute(attention_tc_kernel,
                         cudaFuncAttributeMaxDynamicSharedMemorySize, ATT_SMEM);

    detect_mask_kernel<<<1, 32>>>((const unsigned char*)mask);
    mask_bits_kernel<<<MWORDS / 256, 256>>>(mask);

    const int M = Bq * Sq;               // 8192
    const int nX = M * Dq, nW = Dq * Dq;
    const int bX = nX / 1024, bW = nW / 1024;

    // one batched split launch: q, k, v, Wq, Wk, Wv, fcw
    SplitParams sp{};
    const float* srcs[7] = {query, key_, value, Wq, Wk, Wv, fcw};
    __nv_bfloat16* his[7] = {xhi, yhi, zhi, w1h, w2h, w3h, w4h};
    __nv_bfloat16* los[7] = {xlo, ylo, zlo, w1l, w2l, w3l, w4l};
    int off = 0;
    for (int t = 0; t < 7; t++) {
        sp.src[t] = srcs[t]; sp.hi[t] = his[t]; sp.lo[t] = los[t];
        sp.blkStart[t] = off;
        off += (t < 3) ? bX : bW;
    }
    sp.blkStart[7] = off;
    sp.nT = 7;
    split_all_kernel<<<off, 256>>>(sp);

    // merged Q/K/V projection GEMMs (Q pre-scaled by 1/8)
    QKVParams qp{};
    qp.Ahi[0] = xhi; qp.Alo[0] = xlo; qp.Bhi[0] = w1h; qp.Blo[0] = w1l;
    qp.oh[0] = qh; qp.ol[0] = ql; qp.scale[0] = 0.125f;
    qp.Ahi[1] = yhi; qp.Alo[1] = ylo; qp.Bhi[1] = w2h; qp.Blo[1] = w2l;
    qp.oh[1] = kh; qp.ol[1] = kl; qp.scale[1] = 1.0f;
    qp.Ahi[2] = zhi; qp.Alo[2] = zlo; qp.Bhi[2] = w3h; qp.Blo[2] = w3l;
    qp.oh[2] = vh; qp.ol[2] = vl; qp.scale[2] = 1.0f;
    dim3 gq(Dq / 64, M / 128, 3);      // (16, 64, 3)
    gemm_qkv_kernel<<<gq, 256, GSMEM>>>(qp, M, Dq, Dq);

    // attention writes context split into xhi/xlo + resT fp32
    float* resT = (out_size >= 2 * BSDq) ? (out + BSDq) : nullptr;
    attention_tc_kernel<<<Bq * Hq * (Sq / 128), 512, ATT_SMEM>>>(resT, xhi, xlo);

    // final FC: fp32 out with bias
    dim3 gf(Dq / 64, M / 128);         // (16, 64)
    gemm_tc_kernel<<<gf, 256, GSMEM>>>(xhi, xlo, w4h, w4l, fcb, out, M, Dq, Dq);
}

// round 14
// speedup vs baseline: 1.9976x; 1.0259x over previous
#include <cuda_runtime.h>
#include <cuda_bf16.h>
#include <cstdint>
#include <cstddef>

// Problem constants
#define Bq   4
#define Sq   2048
#define Dq   1024
#define Hq   16
#define DHq  64
#define BSDq (Bq*Sq*Dq)   // 8388608
#define MWORDS (Bq*Sq*(Sq/64))   // 262144 u64 mask words

typedef unsigned long long u64;

// ---------------- generic-PTX tensor-core helpers (sm_80+ ISA) -------------
__device__ __forceinline__ uint32_t smem_u32(const void* p) {
    uint32_t a;
    asm("{ .reg .u64 t; cvta.to.shared.u64 t, %1; cvt.u32.u64 %0, t; }"
        : "=r"(a) : "l"(p));
    return a;
}
__device__ __forceinline__ void cp_async16(uint32_t s, const void* g) {
    asm volatile("cp.async.cg.shared.global [%0], [%1], 16;" :: "r"(s), "l"(g));
}
#define CP_COMMIT() asm volatile("cp.async.commit_group;" ::: "memory")
#define CP_WAIT(n)  asm volatile("cp.async.wait_group %0;" :: "n"(n) : "memory")

__device__ __forceinline__ void ldsm4(uint32_t* r, uint32_t addr) {
    asm volatile("ldmatrix.sync.aligned.m8n8.x4.shared.b16 {%0,%1,%2,%3}, [%4];"
                 : "=r"(r[0]), "=r"(r[1]), "=r"(r[2]), "=r"(r[3]) : "r"(addr));
}
__device__ __forceinline__ void ldsm4t(uint32_t* r, uint32_t addr) {
    asm volatile("ldmatrix.sync.aligned.m8n8.x4.trans.shared.b16 {%0,%1,%2,%3}, [%4];"
                 : "=r"(r[0]), "=r"(r[1]), "=r"(r[2]), "=r"(r[3]) : "r"(addr));
}
// D(f32) += A(bf16) * B(bf16); m16n8k16 row.col
__device__ __forceinline__ void mma16816(float* d, const uint32_t* a,
                                         uint32_t b0, uint32_t b1) {
    asm volatile(
        "mma.sync.aligned.m16n8k16.row.col.f32.bf16.bf16.f32 "
        "{%0,%1,%2,%3}, {%4,%5,%6,%7}, {%8,%9}, {%0,%1,%2,%3};"
        : "+f"(d[0]), "+f"(d[1]), "+f"(d[2]), "+f"(d[3])
        : "r"(a[0]), "r"(a[1]), "r"(a[2]), "r"(a[3]), "r"(b0), "r"(b1));
}
// byte offset of (row, 16B-chunk) in a [rows][64 bf16] tile, xor swizzle
__device__ __forceinline__ uint32_t swz(int row, int ch) {
    uint32_t off = (uint32_t)(row * 128 + ch * 16);
    return off ^ (((uint32_t)row & 7u) << 4);
}
__device__ __forceinline__ uint32_t packbf2(float a, float b) {
    __nv_bfloat162 v;
    v.x = __float2bfloat16(a);
    v.y = __float2bfloat16(b);
    return *(uint32_t*)&v;
}
// single-instruction pack: result = {lo16=bf16(a), hi16=bf16(b)}
__device__ __forceinline__ uint32_t cvt2(float a, float b) {
    uint32_t r;
    asm("cvt.rn.bf16x2.f32 %0, %1, %2;" : "=r"(r) : "f"(b), "f"(a));
    return r;
}

// ---------------- scratch (device globals: allocation-free rule) -----------
__device__ int g_mask_kind;                      // 0=uint8, else 4-byte elems
__device__ __align__(16) u64 g_mbits[MWORDS];    // packed mask bits [b][kt][row]
__device__ __align__(16) __nv_bfloat16 g_qh[BSDq];
__device__ __align__(16) __nv_bfloat16 g_ql[BSDq];
__device__ __align__(16) __nv_bfloat16 g_kh[BSDq];
__device__ __align__(16) __nv_bfloat16 g_kl[BSDq];
__device__ __align__(16) __nv_bfloat16 g_vh[BSDq];
__device__ __align__(16) __nv_bfloat16 g_vl[BSDq];
__device__ __align__(16) __nv_bfloat16 g_xhi[BSDq];   // q split / ctx split
__device__ __align__(16) __nv_bfloat16 g_xlo[BSDq];
__device__ __align__(16) __nv_bfloat16 g_yhi[BSDq];   // k split
__device__ __align__(16) __nv_bfloat16 g_ylo[BSDq];
__device__ __align__(16) __nv_bfloat16 g_zhi[BSDq];   // v split
__device__ __align__(16) __nv_bfloat16 g_zlo[BSDq];
__device__ __align__(16) __nv_bfloat16 g_w1h[Dq * Dq]; // Wq
__device__ __align__(16) __nv_bfloat16 g_w1l[Dq * Dq];
__device__ __align__(16) __nv_bfloat16 g_w2h[Dq * Dq]; // Wk
__device__ __align__(16) __nv_bfloat16 g_w2l[Dq * Dq];
__device__ __align__(16) __nv_bfloat16 g_w3h[Dq * Dq]; // Wv
__device__ __align__(16) __nv_bfloat16 g_w3l[Dq * Dq];
__device__ __align__(16) __nv_bfloat16 g_w4h[Dq * Dq]; // fc_w
__device__ __align__(16) __nv_bfloat16 g_w4l[Dq * Dq];

// ---------------------------------------------------------------------------
__global__ void detect_mask_kernel(const unsigned char* __restrict__ m) {
    if (threadIdx.x != 0) return;
    int c0 = 0, c1 = 0, c2 = 0, c3 = 0;
    for (int i = 0; i < 4096; i += 4) {
        if (m[i + 0]) c0++;
        if (m[i + 1]) c1++;
        if (m[i + 2]) c2++;
        if (m[i + 3]) c3++;
    }
    int kind;
    if (c1 == 0 && c2 == 0 && c3 == 0) kind = 1;   // int32
    else if (c0 == 0 && c1 == 0)       kind = 2;   // float32
    else                               kind = 0;   // uint8
    g_mask_kind = kind;
}

// pack mask -> u64 words, stored TRANSPOSED: [b][kt][row]
__global__ __launch_bounds__(256)
void mask_bits_kernel(const void* __restrict__ mask) {
    int w = blockIdx.x * 256 + threadIdx.x;   // linear over [b][row][kt]
    if (w >= MWORDS) return;
    u64 bits = 0;
    if (g_mask_kind == 0) {
        const uint4* p = (const uint4*)((const unsigned char*)mask + (size_t)w * 64);
#pragma unroll
        for (int q = 0; q < 4; q++) {
            uint4 v = p[q];
            const uint32_t ww[4] = {v.x, v.y, v.z, v.w};
#pragma unroll
            for (int k = 0; k < 4; k++)
#pragma unroll
                for (int j = 0; j < 4; j++)
                    if ((ww[k] >> (8 * j)) & 0xffu)
                        bits |= 1ull << (q * 16 + k * 4 + j);
        }
    } else {   // 4-byte elements
        const uint4* p = (const uint4*)((const uint32_t*)mask + (size_t)w * 64);
#pragma unroll
        for (int q = 0; q < 16; q++) {
            uint4 v = p[q];
            if (v.x) bits |= 1ull << (q * 4 + 0);
            if (v.y) bits |= 1ull << (q * 4 + 1);
            if (v.z) bits |= 1ull << (q * 4 + 2);
            if (v.w) bits |= 1ull << (q * 4 + 3);
        }
    }
    int kt  = w & 31;
    int row = (w >> 5) & (Sq - 1);
    int b   = w >> 16;
    g_mbits[(((size_t)b * 32 + kt) << 11) + row] = bits;
}

// ---- batched fp32 -> bf16 hi/lo split for up to 8 tensors -----------------
struct SplitParams {
    const float* src[8];
    __nv_bfloat16* hi[8];
    __nv_bfloat16* lo[8];
    int blkStart[9];
    int nT;
};

__global__ __launch_bounds__(256)
void split_all_kernel(SplitParams P)
{
    int blk = blockIdx.x;
    int t = 0;
    while (t + 1 < P.nT && blk >= P.blkStart[t + 1]) t++;
    int i = (blk - P.blkStart[t]) * 256 * 4 + threadIdx.x * 4;
    const float* x = P.src[t];
    float4 v = *(const float4*)(x + i);
    __nv_bfloat16 h0 = __float2bfloat16(v.x), h1 = __float2bfloat16(v.y);
    __nv_bfloat16 h2 = __float2bfloat16(v.z), h3 = __float2bfloat16(v.w);
    __nv_bfloat162 hA, hB, lA, lB;
    hA.x = h0; hA.y = h1; hB.x = h2; hB.y = h3;
    lA.x = __float2bfloat16(v.x - __bfloat162float(h0));
    lA.y = __float2bfloat16(v.y - __bfloat162float(h1));
    lB.x = __float2bfloat16(v.z - __bfloat162float(h2));
    lB.y = __float2bfloat16(v.w - __bfloat162float(h3));
    *(__nv_bfloat162*)(P.hi[t] + i)     = hA;
    *(__nv_bfloat162*)(P.hi[t] + i + 2) = hB;
    *(__nv_bfloat162*)(P.lo[t] + i)     = lA;
    *(__nv_bfloat162*)(P.lo[t] + i + 2) = lB;
}

// ---------------------------------------------------------------------------
// HMMA split-bf16 GEMM core: 128x64 CTA tile, 256 threads, 2 CTAs/SM.
// (unchanged from R12 — validated at tensor=63.8%)
// ---------------------------------------------------------------------------
#define GSTAGE  49152
#define GA_HI   0
#define GA_LO   16384
#define GB_HI   32768
#define GB_LO   40960
#define GSMEM   (2*GSTAGE)          // 96KB

__device__ __forceinline__ void gemm_core(
    const __nv_bfloat16* __restrict__ Ahi, const __nv_bfloat16* __restrict__ Alo,
    const __nv_bfloat16* __restrict__ Bhi, const __nv_bfloat16* __restrict__ Blo,
    const float* __restrict__ bias, float* __restrict__ out32,
    __nv_bfloat16* __restrict__ outh, __nv_bfloat16* __restrict__ outl,
    float scale, int M, int N, int K, char* smem)
{
    const uint32_t sbase = smem_u32(smem);
    const int tid  = threadIdx.x;
    const int wid  = tid >> 5;
    const int lane = tid & 31;
    const int m0 = blockIdx.y * 128;
    const int n0 = blockIdx.x * 64;
    const int wm = wid & 3;
    const int wn = wid >> 2;

    float acc[2][4][4];
#pragma unroll
    for (int i = 0; i < 2; i++)
#pragma unroll
        for (int j = 0; j < 4; j++)
#pragma unroll
            for (int c = 0; c < 4; c++) acc[i][j][c] = 0.f;

    auto load_stage = [&](int t, int buf) {
        const int k0 = t * 64;
        const uint32_t sb = sbase + buf * GSTAGE;
#pragma unroll
        for (int l = 0; l < 4; l++) {
            int idx = l * 256 + tid;
            int row = idx >> 3, ch = idx & 7;
            uint32_t sw = swz(row, ch);
            size_t ao = (size_t)(m0 + row) * K + k0 + ch * 8;
            cp_async16(sb + GA_HI + sw, Ahi + ao);
            cp_async16(sb + GA_LO + sw, Alo + ao);
        }
#pragma unroll
        for (int l = 0; l < 2; l++) {
            int idx = l * 256 + tid;
            int row = idx >> 3, ch = idx & 7;
            uint32_t sw = swz(row, ch);
            size_t bo = (size_t)(n0 + row) * K + k0 + ch * 8;
            cp_async16(sb + GB_HI + sw, Bhi + bo);
            cp_async16(sb + GB_LO + sw, Blo + bo);
        }
    };

    load_stage(0, 0);
    CP_COMMIT();

    const int arow = wm * 32 + (lane & 15);
    const int brow = wn * 32 + (lane & 15);

    const int NT = K / 64;
#pragma unroll 1
    for (int t = 0; t < NT; t++) {
        const int buf = t & 1;
        if (t + 1 < NT) {
            load_stage(t + 1, (t + 1) & 1);
            CP_COMMIT();
            CP_WAIT(1);
        } else {
            CP_WAIT(0);
        }
        __syncthreads();

        const uint32_t sb = sbase + buf * GSTAGE;
#pragma unroll
        for (int ks = 0; ks < 4; ks++) {
            const int ch = ks * 2 + (lane >> 4);
            uint32_t ah[2][4], al[2][4];
#pragma unroll
            for (int mt = 0; mt < 2; mt++) {
                uint32_t sw = swz(arow + mt * 16, ch);
                ldsm4(ah[mt], sb + GA_HI + sw);
                ldsm4(al[mt], sb + GA_LO + sw);
            }
            uint32_t bh[2][4], bl[2][4];
#pragma unroll
            for (int nb = 0; nb < 2; nb++) {
                uint32_t sw = swz(brow + nb * 16, ch);
                ldsm4(bh[nb], sb + GB_HI + sw);
                ldsm4(bl[nb], sb + GB_LO + sw);
            }
#pragma unroll
            for (int mt = 0; mt < 2; mt++)
#pragma unroll
                for (int nt = 0; nt < 4; nt++) {
                    const int nb = nt >> 1, hh = nt & 1;
                    mma16816(acc[mt][nt], ah[mt], bh[nb][hh], bh[nb][2 + hh]);
                    mma16816(acc[mt][nt], ah[mt], bl[nb][hh], bl[nb][2 + hh]);
                    mma16816(acc[mt][nt], al[mt], bh[nb][hh], bh[nb][2 + hh]);
                }
        }
        __syncthreads();
    }

#pragma unroll
    for (int mt = 0; mt < 2; mt++) {
#pragma unroll
        for (int nt = 0; nt < 4; nt++) {
            int row = m0 + wm * 32 + mt * 16 + (lane >> 2);
            int col = n0 + wn * 32 + nt * 8 + (lane & 3) * 2;
            if (out32) {
                float2 v0, v1;
                v0.x = acc[mt][nt][0]; v0.y = acc[mt][nt][1];
                v1.x = acc[mt][nt][2]; v1.y = acc[mt][nt][3];
                if (bias) {
                    float b0 = bias[col], b1 = bias[col + 1];
                    v0.x += b0; v0.y += b1;
                    v1.x += b0; v1.y += b1;
                }
                *(float2*)(out32 + (size_t)row * N + col)       = v0;
                *(float2*)(out32 + (size_t)(row + 8) * N + col) = v1;
            } else {
#pragma unroll
                for (int rr = 0; rr < 2; rr++) {
                    size_t o = (size_t)(row + rr * 8) * N + col;
                    float x0 = acc[mt][nt][rr * 2 + 0] * scale;
                    float x1 = acc[mt][nt][rr * 2 + 1] * scale;
                    __nv_bfloat162 hv, lv;
                    hv.x = __float2bfloat16(x0);
                    hv.y = __float2bfloat16(x1);
                    lv.x = __float2bfloat16(x0 - __bfloat162float(hv.x));
                    lv.y = __float2bfloat16(x1 - __bfloat162float(hv.y));
                    *(__nv_bfloat162*)(outh + o) = hv;
                    *(__nv_bfloat162*)(outl + o) = lv;
                }
            }
        }
    }
}

__global__ __launch_bounds__(256, 2)
void gemm_tc_kernel(const __nv_bfloat16* __restrict__ Ahi,
                    const __nv_bfloat16* __restrict__ Alo,
                    const __nv_bfloat16* __restrict__ Bhi,
                    const __nv_bfloat16* __restrict__ Blo,
                    const float* __restrict__ bias, float* __restrict__ out32,
                    int M, int N, int K)
{
    extern __shared__ char smem[];
    gemm_core(Ahi, Alo, Bhi, Blo, bias, out32, nullptr, nullptr, 1.0f,
              M, N, K, smem);
}

struct QKVParams {
    const __nv_bfloat16 *Ahi[3], *Alo[3], *Bhi[3], *Blo[3];
    __nv_bfloat16 *oh[3], *ol[3];
    float scale[3];
};
__global__ __launch_bounds__(256, 2)
void gemm_qkv_kernel(QKVParams P, int M, int N, int K)
{
    extern __shared__ char smem[];
    const int z = blockIdx.z;
    gemm_core(P.Ahi[z], P.Alo[z], P.Bhi[z], P.Blo[z], nullptr, nullptr,
              P.oh[z], P.ol[z], P.scale[z], M, N, K, smem);
}

// ---------------------------------------------------------------------------
// HMMA flash attention, register-resident softmax, 2 CTAs/SM:
// CTA = 64 q-rows, 256 threads (8 warps: 2 wm x 4 wn). Same per-thread inner
// loops as R13; occupancy-2 overlaps softmax/barriers with the peer CTA's MMAs.
// ---------------------------------------------------------------------------
#define AS_QH   0                     // 8KB (64 rows)
#define AS_QL   8192                  // 8KB
#define AS_K    16384                 // [buf][hi 8KB | lo 8KB] x2 = 32KB
#define AS_V    49152                 // 32KB
#define AS_SO   16384                 // epilogue alias over K region (64x68 f32)
#define AS_DEN  81920                 // 4 x 64 floats = 1KB
#define ATT_SMEM (AS_DEN + 1024)      // 82944

__global__ __launch_bounds__(256, 2)
void attention_tc_kernel(float* __restrict__ resT,
                         __nv_bfloat16* __restrict__ ctx_h,
                         __nv_bfloat16* __restrict__ ctx_l)
{
    extern __shared__ char smem[];
    const uint32_t sbase = smem_u32(smem);
    float* sDen4 = (float*)(smem + AS_DEN);   // [4 wn][64]

    const int tid  = threadIdx.x;
    const int wid  = tid >> 5;
    const int lane = tid & 31;
    const int wm = wid & 1;        // 2 m-warps (32 q-rows each)
    const int wn = wid >> 1;       // 4 k-slice warps (16 k-cols each)
    const int blk = blockIdx.x;
    const int qt  = blk & 31;
    const int h   = (blk >> 5) & 15;
    const int b   = blk >> 9;
    const int q0  = qt * 64;

    const size_t headBase = (size_t)b * Sq * Dq + (size_t)h * Sq * DHq;
    const __nv_bfloat16* Qh = g_qh + headBase;
    const __nv_bfloat16* Ql = g_ql + headBase;
    const __nv_bfloat16* Kh = g_kh + headBase;
    const __nv_bfloat16* Kl = g_kl + headBase;
    const __nv_bfloat16* Vh = g_vh + headBase;
    const __nv_bfloat16* Vl = g_vl + headBase;

    // ---- initial loads: Q (persistent) + K/V stage 0 (2 iters each) ----
#pragma unroll
    for (int l = 0; l < 2; l++) {
        int idx = l * 256 + tid;
        int row = idx >> 3, ch = idx & 7;
        uint32_t sw = swz(row, ch);
        size_t o = (size_t)(q0 + row) * DHq + ch * 8;
        cp_async16(sbase + AS_QH + sw, Qh + o);
        cp_async16(sbase + AS_QL + sw, Ql + o);
    }
#pragma unroll
    for (int l = 0; l < 2; l++) {
        int idx = l * 256 + tid;
        int row = idx >> 3, ch = idx & 7;
        uint32_t sw = swz(row, ch);
        size_t o = (size_t)row * DHq + ch * 8;
        cp_async16(sbase + AS_K + sw,        Kh + o);
        cp_async16(sbase + AS_K + 8192 + sw, Kl + o);
        cp_async16(sbase + AS_V + sw,        Vh + o);
        cp_async16(sbase + AS_V + 8192 + sw, Vl + o);
    }
    CP_COMMIT();

    // O partials: [mt][ds][hh2][4]
    float oacc[2][4][2][4];
#pragma unroll
    for (int mt = 0; mt < 2; mt++)
#pragma unroll
        for (int ds = 0; ds < 4; ds++)
#pragma unroll
            for (int hh = 0; hh < 2; hh++)
#pragma unroll
                for (int c = 0; c < 4; c++) oacc[mt][ds][hh][c] = 0.f;
    float denAcc[2][2] = {{0.f, 0.f}, {0.f, 0.f}};

    const int arow = wm * 32 + (lane & 15);
    const int brow = wn * 16 + (lane & 15);
    const int vrow0 = (lane & 7) + ((lane >> 4) << 3);
    const u64* mb = g_mbits + (((size_t)b * 32) << 11) + q0;

    const int NT = Sq / 64;
#pragma unroll 1
    for (int kt = 0; kt < NT; kt++) {
        const int buf = kt & 1;
        CP_WAIT(0);
        __syncthreads();   // K/V[buf] ready; all prev-tile V reads complete

        // prefetch next K/V stage into the other buffer
        if (kt + 1 < NT) {
            const uint32_t kb = sbase + AS_K + (1 - buf) * 16384;
            const uint32_t vb = sbase + AS_V + (1 - buf) * 16384;
            const size_t gk = (size_t)(kt + 1) * 64 * DHq;
#pragma unroll
            for (int l = 0; l < 2; l++) {
                int idx = l * 256 + tid;
                int row = idx >> 3, ch = idx & 7;
                uint32_t sw = swz(row, ch);
                size_t o = gk + (size_t)row * DHq + ch * 8;
                cp_async16(kb + sw,        Kh + o);
                cp_async16(kb + 8192 + sw, Kl + o);
                cp_async16(vb + sw,        Vh + o);
                cp_async16(vb + 8192 + sw, Vl + o);
            }
            CP_COMMIT();
        }

        // ---- S = Q K^T (3-term split), this warp's 16 k-cols ----
        float sacc[2][2][4];
#pragma unroll
        for (int mt = 0; mt < 2; mt++)
#pragma unroll
            for (int hh = 0; hh < 2; hh++)
#pragma unroll
                for (int c = 0; c < 4; c++) sacc[mt][hh][c] = 0.f;

        const uint32_t kbh = sbase + AS_K + buf * 16384;
        const uint32_t kbl = kbh + 8192;
#pragma unroll
        for (int ks = 0; ks < 4; ks++) {
            const int ch = ks * 2 + (lane >> 4);
            uint32_t ah[2][4], al[2][4];
#pragma unroll
            for (int mt = 0; mt < 2; mt++) {
                uint32_t sw = swz(arow + mt * 16, ch);
                ldsm4(ah[mt], sbase + AS_QH + sw);
                ldsm4(al[mt], sbase + AS_QL + sw);
            }
            uint32_t bh[4], bl[4];
            {
                uint32_t sw = swz(brow, ch);
                ldsm4(bh, kbh + sw);
                ldsm4(bl, kbl + sw);
            }
#pragma unroll
            for (int mt = 0; mt < 2; mt++)
#pragma unroll
                for (int hh = 0; hh < 2; hh++) {
                    mma16816(sacc[mt][hh], ah[mt], bh[hh], bh[2 + hh]);
                    mma16816(sacc[mt][hh], ah[mt], bl[hh], bl[2 + hh]);
                    mma16816(sacc[mt][hh], al[mt], bh[hh], bh[2 + hh]);
                }
        }

        // ---- softmax in registers -> P A-fragments (hi/lo) ----
        uint32_t phi[2][4], plo[2][4];
        const u64* mtile = mb + ((size_t)kt << 11);
#pragma unroll
        for (int mt = 0; mt < 2; mt++) {
#pragma unroll
            for (int rr = 0; rr < 2; rr++) {
                const int r = wm * 32 + mt * 16 + (lane >> 2) + rr * 8;
                const u64 mword = mtile[r];
#pragma unroll
                for (int hh = 0; hh < 2; hh++) {
                    const int colg = wn * 16 + hh * 8 + (lane & 3) * 2;
                    float p0 = ((mword >> colg) & 1ull)
                             ? __expf(sacc[mt][hh][rr * 2 + 0]) : 0.f;
                    float p1 = ((mword >> (colg + 1)) & 1ull)
                             ? __expf(sacc[mt][hh][rr * 2 + 1]) : 0.f;
                    denAcc[mt][rr] += p0 + p1;
                    uint32_t hp = cvt2(p0, p1);
                    phi[mt][hh * 2 + rr] = hp;
                    float h0f = __uint_as_float(hp << 16);
                    float h1f = __uint_as_float(hp & 0xffff0000u);
                    plo[mt][hh * 2 + rr] = cvt2(p0 - h0f, p1 - h1f);
                }
            }
        }

        // ---- O += P V over this warp's k-slice (A in registers) ----
        const uint32_t vbh = sbase + AS_V + buf * 16384;
        const uint32_t vbl = vbh + 8192;
#pragma unroll
        for (int ds = 0; ds < 4; ds++) {
            uint32_t bh[4], bl[4];
            uint32_t sw = swz(wn * 16 + vrow0, ds * 2 + ((lane >> 3) & 1));
            ldsm4t(bh, vbh + sw);
            ldsm4t(bl, vbl + sw);
#pragma unroll
            for (int mt = 0; mt < 2; mt++)
#pragma unroll
                for (int hh = 0; hh < 2; hh++) {
                    mma16816(oacc[mt][ds][hh], phi[mt], bh[hh], bh[2 + hh]);
                    mma16816(oacc[mt][ds][hh], phi[mt], bl[hh], bl[2 + hh]);
                    mma16816(oacc[mt][ds][hh], plo[mt], bh[hh], bh[2 + hh]);
                }
        }
    }

    // ---- denominator: quad shfl -> per-wn smem slot ----
#pragma unroll
    for (int mt = 0; mt < 2; mt++)
#pragma unroll
        for (int rr = 0; rr < 2; rr++) {
            float d = denAcc[mt][rr];
            d += __shfl_xor_sync(0xffffffffu, d, 1);
            d += __shfl_xor_sync(0xffffffffu, d, 2);
            if ((lane & 3) == 0)
                sDen4[wn * 64 + wm * 32 + mt * 16 + (lane >> 2) + rr * 8] = d;
        }
    __syncthreads();   // K smem now dead; den slots written

    // ---- cross-wn O reduction into sO (aliased over K buffer, pitch 68) ----
    float* sO = (float*)(smem + AS_SO);
#pragma unroll 1
    for (int round = 0; round < 4; round++) {
        if (wn == round) {
#pragma unroll
            for (int mt = 0; mt < 2; mt++)
#pragma unroll
                for (int ds = 0; ds < 4; ds++)
#pragma unroll
                    for (int hh = 0; hh < 2; hh++)
#pragma unroll
                        for (int rr = 0; rr < 2; rr++) {
                            int r = wm * 32 + mt * 16 + (lane >> 2) + rr * 8;
                            int c = ds * 16 + hh * 8 + (lane & 3) * 2;
                            float* p = &sO[r * 68 + c];
                            if (round == 0) {
                                p[0] = oacc[mt][ds][hh][rr * 2 + 0];
                                p[1] = oacc[mt][ds][hh][rr * 2 + 1];
                            } else {
                                p[0] += oacc[mt][ds][hh][rr * 2 + 0];
                                p[1] += oacc[mt][ds][hh][rr * 2 + 1];
                            }
                        }
        }
        __syncthreads();
    }

    // ---- final: normalize, write split context + resT ----
    {
        const int r  = tid >> 2;            // 0..63
        const int cb = (tid & 3) * 16;      // 0,16,32,48
        float dn = sDen4[r] + sDen4[64 + r] + sDen4[128 + r] + sDen4[192 + r];
        float inv = dn > 0.f ? 1.f / dn : 0.f;     // NaN->0 semantics
        int s2 = q0 + r;
        size_t co = ((size_t)b * Sq + s2) * Dq + h * DHq + cb;
        float xv[16];
#pragma unroll
        for (int j = 0; j < 16; j++) xv[j] = sO[r * 68 + cb + j] * inv;
        uint32_t hp[8], lp[8];
#pragma unroll
        for (int j = 0; j < 8; j++) {
            __nv_bfloat162 h2;
            h2.x = __float2bfloat16(xv[2 * j]);
            h2.y = __float2bfloat16(xv[2 * j + 1]);
            hp[j] = *(uint32_t*)&h2;
            lp[j] = packbf2(xv[2 * j]     - __bfloat162float(h2.x),
                            xv[2 * j + 1] - __bfloat162float(h2.y));
        }
        *(uint4*)(ctx_h + co)     = *(uint4*)&hp[0];
        *(uint4*)(ctx_h + co + 8) = *(uint4*)&hp[4];
        *(uint4*)(ctx_l + co)     = *(uint4*)&lp[0];
        *(uint4*)(ctx_l + co + 8) = *(uint4*)&lp[4];
        if (resT) {
            float* rp = resT + (((size_t)h * Bq + b) * Sq + s2) * DHq + cb;
#pragma unroll
            for (int j = 0; j < 4; j++)
                *(float4*)(rp + 4 * j) = *(float4*)&xv[4 * j];
        }
    }
}

// ---------------------------------------------------------------------------
extern "C" void kernel_launch(void* const* d_in, const int* in_sizes, int n_in,
                              void* d_out, int out_size)
{
    const float* query = (const float*)d_in[0];
    const float* key_  = (const float*)d_in[1];
    const float* value = (const float*)d_in[2];
    const void*  mask  = d_in[3];
    const float* Wq    = (const float*)d_in[4];
    const float* Wk    = (const float*)d_in[5];
    const float* Wv    = (const float*)d_in[6];
    const float* fcw   = (const float*)d_in[7];
    const float* fcb   = (const float*)d_in[8];
    float* out = (float*)d_out;

    __nv_bfloat16 *qh, *ql, *kh, *kl, *vh, *vl;
    __nv_bfloat16 *xhi, *xlo, *yhi, *ylo, *zhi, *zlo;
    __nv_bfloat16 *w1h, *w1l, *w2h, *w2l, *w3h, *w3l, *w4h, *w4l;
    cudaGetSymbolAddress((void**)&qh,  g_qh);
    cudaGetSymbolAddress((void**)&ql,  g_ql);
    cudaGetSymbolAddress((void**)&kh,  g_kh);
    cudaGetSymbolAddress((void**)&kl,  g_kl);
    cudaGetSymbolAddress((void**)&vh,  g_vh);
    cudaGetSymbolAddress((void**)&vl,  g_vl);
    cudaGetSymbolAddress((void**)&xhi, g_xhi);
    cudaGetSymbolAddress((void**)&xlo, g_xlo);
    cudaGetSymbolAddress((void**)&yhi, g_yhi);
    cudaGetSymbolAddress((void**)&ylo, g_ylo);
    cudaGetSymbolAddress((void**)&zhi, g_zhi);
    cudaGetSymbolAddress((void**)&zlo, g_zlo);
    cudaGetSymbolAddress((void**)&w1h, g_w1h);
    cudaGetSymbolAddress((void**)&w1l, g_w1l);
    cudaGetSymbolAddress((void**)&w2h, g_w2h);
    cudaGetSymbolAddress((void**)&w2l, g_w2l);
    cudaGetSymbolAddress((void**)&w3h, g_w3h);
    cudaGetSymbolAddress((void**)&w3l, g_w3l);
    cudaGetSymbolAddress((void**)&w4h, g_w4h);
    cudaGetSymbolAddress((void**)&w4l, g_w4l);

    cudaFuncSetAttribute(gemm_tc_kernel,
                         cudaFuncAttributeMaxDynamicSharedMemorySize, GSMEM);
    cudaFuncSetAttribute(gemm_qkv_kernel,
                         cudaFuncAttributeMaxDynamicSharedMemorySize, GSMEM);
    cudaFuncSetAttribute(attention_tc_kernel,
                         cudaFuncAttributeMaxDynamicSharedMemorySize, ATT_SMEM);

    detect_mask_kernel<<<1, 32>>>((const unsigned char*)mask);
    mask_bits_kernel<<<MWORDS / 256, 256>>>(mask);

    const int M = Bq * Sq;               // 8192
    const int nX = M * Dq, nW = Dq * Dq;
    const int bX = nX / 1024, bW = nW / 1024;

    // one batched split launch: q, k, v, Wq, Wk, Wv, fcw
    SplitParams sp{};
    const float* srcs[7] = {query, key_, value, Wq, Wk, Wv, fcw};
    __nv_bfloat16* his[7] = {xhi, yhi, zhi, w1h, w2h, w3h, w4h};
    __nv_bfloat16* los[7] = {xlo, ylo, zlo, w1l, w2l, w3l, w4l};
    int off = 0;
    for (int t = 0; t < 7; t++) {
        sp.src[t] = srcs[t]; sp.hi[t] = his[t]; sp.lo[t] = los[t];
        sp.blkStart[t] = off;
        off += (t < 3) ? bX : bW;
    }
    sp.blkStart[7] = off;
    sp.nT = 7;
    split_all_kernel<<<off, 256>>>(sp);

    // merged Q/K/V projection GEMMs (Q pre-scaled by 1/8)
    QKVParams qp{};
    qp.Ahi[0] = xhi; qp.Alo[0] = xlo; qp.Bhi[0] = w1h; qp.Blo[0] = w1l;
    qp.oh[0] = qh; qp.ol[0] = ql; qp.scale[0] = 0.125f;
    qp.Ahi[1] = yhi; qp.Alo[1] = ylo; qp.Bhi[1] = w2h; qp.Blo[1] = w2l;
    qp.oh[1] = kh; qp.ol[1] = kl; qp.scale[1] = 1.0f;
    qp.Ahi[2] = zhi; qp.Alo[2] = zlo; qp.Bhi[2] = w3h; qp.Blo[2] = w3l;
    qp.oh[2] = vh; qp.ol[2] = vl; qp.scale[2] = 1.0f;
    dim3 gq(Dq / 64, M / 128, 3);      // (16, 64, 3)
    gemm_qkv_kernel<<<gq, 256, GSMEM>>>(qp, M, Dq, Dq);

    // attention writes context split into xhi/xlo + resT fp32
    float* resT = (out_size >= 2 * BSDq) ? (out + BSDq) : nullptr;
    attention_tc_kernel<<<Bq * Hq * (Sq / 64), 256, ATT_SMEM>>>(resT, xhi, xlo);

    // final FC: fp32 out with bias
    dim3 gf(Dq / 64, M / 128);         // (16, 64)
    gemm_tc_kernel<<<gf, 256, GSMEM>>>(xhi, xlo, w4h, w4l, fcb, out, M, Dq, Dq);
}

// round 15
// speedup vs baseline: 2.3571x; 1.1799x over previous
#include <cuda_runtime.h>
#include <cuda_bf16.h>
#include <cuda_fp16.h>
#include <cstdint>
#include <cstddef>

// Problem constants
#define Bq   4
#define Sq   2048
#define Dq   1024
#define Hq   16
#define DHq  64
#define BSDq (Bq*Sq*Dq)   // 8388608
#define MWORDS (Bq*Sq*(Sq/64))   // 262144 u64 mask words

typedef unsigned long long u64;

// ---------------- generic-PTX tensor-core helpers (sm_80+ ISA) -------------
__device__ __forceinline__ uint32_t smem_u32(const void* p) {
    uint32_t a;
    asm("{ .reg .u64 t; cvta.to.shared.u64 t, %1; cvt.u32.u64 %0, t; }"
        : "=r"(a) : "l"(p));
    return a;
}
__device__ __forceinline__ void cp_async16(uint32_t s, const void* g) {
    asm volatile("cp.async.cg.shared.global [%0], [%1], 16;" :: "r"(s), "l"(g));
}
#define CP_COMMIT() asm volatile("cp.async.commit_group;" ::: "memory")
#define CP_WAIT(n)  asm volatile("cp.async.wait_group %0;" :: "n"(n) : "memory")

__device__ __forceinline__ void ldsm4(uint32_t* r, uint32_t addr) {
    asm volatile("ldmatrix.sync.aligned.m8n8.x4.shared.b16 {%0,%1,%2,%3}, [%4];"
                 : "=r"(r[0]), "=r"(r[1]), "=r"(r[2]), "=r"(r[3]) : "r"(addr));
}
__device__ __forceinline__ void ldsm4t(uint32_t* r, uint32_t addr) {
    asm volatile("ldmatrix.sync.aligned.m8n8.x4.trans.shared.b16 {%0,%1,%2,%3}, [%4];"
                 : "=r"(r[0]), "=r"(r[1]), "=r"(r[2]), "=r"(r[3]) : "r"(addr));
}
// D(f32) += A(bf16) * B(bf16); m16n8k16 row.col
__device__ __forceinline__ void mma16816(float* d, const uint32_t* a,
                                         uint32_t b0, uint32_t b1) {
    asm volatile(
        "mma.sync.aligned.m16n8k16.row.col.f32.bf16.bf16.f32 "
        "{%0,%1,%2,%3}, {%4,%5,%6,%7}, {%8,%9}, {%0,%1,%2,%3};"
        : "+f"(d[0]), "+f"(d[1]), "+f"(d[2]), "+f"(d[3])
        : "r"(a[0]), "r"(a[1]), "r"(a[2]), "r"(a[3]), "r"(b0), "r"(b1));
}
// D(f32) += A(f16) * B(f16); m16n8k16 row.col
__device__ __forceinline__ void mma16816h(float* d, const uint32_t* a,
                                          uint32_t b0, uint32_t b1) {
    asm volatile(
        "mma.sync.aligned.m16n8k16.row.col.f32.f16.f16.f32 "
        "{%0,%1,%2,%3}, {%4,%5,%6,%7}, {%8,%9}, {%0,%1,%2,%3};"
        : "+f"(d[0]), "+f"(d[1]), "+f"(d[2]), "+f"(d[3])
        : "r"(a[0]), "r"(a[1]), "r"(a[2]), "r"(a[3]), "r"(b0), "r"(b1));
}
// byte offset of (row, 16B-chunk) in a [rows][64 x 16bit] tile, xor swizzle
__device__ __forceinline__ uint32_t swz(int row, int ch) {
    uint32_t off = (uint32_t)(row * 128 + ch * 16);
    return off ^ (((uint32_t)row & 7u) << 4);
}
__device__ __forceinline__ uint32_t packbf2(float a, float b) {
    __nv_bfloat162 v;
    v.x = __float2bfloat16(a);
    v.y = __float2bfloat16(b);
    return *(uint32_t*)&v;
}
// single-instruction pack: {lo16=f16(a), hi16=f16(b)}
__device__ __forceinline__ uint32_t cvt2h(float a, float b) {
    uint32_t r;
    asm("cvt.rn.f16x2.f32 %0, %1, %2;" : "=r"(r) : "f"(b), "f"(a));
    return r;
}

// ---------------- scratch (device globals: allocation-free rule) -----------
__device__ int g_mask_kind;                      // 0=uint8, else 4-byte elems
__device__ __align__(16) u64 g_mbits[MWORDS];    // packed mask bits [b][kt][row]
__device__ __align__(16) __half g_qh[BSDq];      // Q fp16 hi (A operand)
__device__ __align__(16) __half g_kh[BSDq];      // K fp16 hi+lo (B operand)
__device__ __align__(16) __half g_kl[BSDq];
__device__ __align__(16) __half g_vh[BSDq];      // V fp16 hi+lo
__device__ __align__(16) __half g_vl[BSDq];
__device__ __align__(16) __nv_bfloat16 g_xhi[BSDq];   // q split / ctx split
__device__ __align__(16) __nv_bfloat16 g_xlo[BSDq];
__device__ __align__(16) __nv_bfloat16 g_yhi[BSDq];   // k split
__device__ __align__(16) __nv_bfloat16 g_ylo[BSDq];
__device__ __align__(16) __nv_bfloat16 g_zhi[BSDq];   // v split
__device__ __align__(16) __nv_bfloat16 g_zlo[BSDq];
__device__ __align__(16) __nv_bfloat16 g_w1h[Dq * Dq]; // Wq
__device__ __align__(16) __nv_bfloat16 g_w1l[Dq * Dq];
__device__ __align__(16) __nv_bfloat16 g_w2h[Dq * Dq]; // Wk
__device__ __align__(16) __nv_bfloat16 g_w2l[Dq * Dq];
__device__ __align__(16) __nv_bfloat16 g_w3h[Dq * Dq]; // Wv
__device__ __align__(16) __nv_bfloat16 g_w3l[Dq * Dq];
__device__ __align__(16) __nv_bfloat16 g_w4h[Dq * Dq]; // fc_w
__device__ __align__(16) __nv_bfloat16 g_w4l[Dq * Dq];

// ---------------------------------------------------------------------------
__global__ void detect_mask_kernel(const unsigned char* __restrict__ m) {
    if (threadIdx.x != 0) return;
    int c0 = 0, c1 = 0, c2 = 0, c3 = 0;
    for (int i = 0; i < 4096; i += 4) {
        if (m[i + 0]) c0++;
        if (m[i + 1]) c1++;
        if (m[i + 2]) c2++;
        if (m[i + 3]) c3++;
    }
    int kind;
    if (c1 == 0 && c2 == 0 && c3 == 0) kind = 1;   // int32
    else if (c0 == 0 && c1 == 0)       kind = 2;   // float32
    else                               kind = 0;   // uint8
    g_mask_kind = kind;
}

// pack mask -> u64 words, stored TRANSPOSED: [b][kt][row]
__global__ __launch_bounds__(256)
void mask_bits_kernel(const void* __restrict__ mask) {
    int w = blockIdx.x * 256 + threadIdx.x;   // linear over [b][row][kt]
    if (w >= MWORDS) return;
    u64 bits = 0;
    if (g_mask_kind == 0) {
        const uint4* p = (const uint4*)((const unsigned char*)mask + (size_t)w * 64);
#pragma unroll
        for (int q = 0; q < 4; q++) {
            uint4 v = p[q];
            const uint32_t ww[4] = {v.x, v.y, v.z, v.w};
#pragma unroll
            for (int k = 0; k < 4; k++)
#pragma unroll
                for (int j = 0; j < 4; j++)
                    if ((ww[k] >> (8 * j)) & 0xffu)
                        bits |= 1ull << (q * 16 + k * 4 + j);
        }
    } else {   // 4-byte elements
        const uint4* p = (const uint4*)((const uint32_t*)mask + (size_t)w * 64);
#pragma unroll
        for (int q = 0; q < 16; q++) {
            uint4 v = p[q];
            if (v.x) bits |= 1ull << (q * 4 + 0);
            if (v.y) bits |= 1ull << (q * 4 + 1);
            if (v.z) bits |= 1ull << (q * 4 + 2);
            if (v.w) bits |= 1ull << (q * 4 + 3);
        }
    }
    int kt  = w & 31;
    int row = (w >> 5) & (Sq - 1);
    int b   = w >> 16;
    g_mbits[(((size_t)b * 32 + kt) << 11) + row] = bits;
}

// ---- batched fp32 -> bf16 hi/lo split for up to 8 tensors -----------------
struct SplitParams {
    const float* src[8];
    __nv_bfloat16* hi[8];
    __nv_bfloat16* lo[8];
    int blkStart[9];
    int nT;
};

__global__ __launch_bounds__(256)
void split_all_kernel(SplitParams P)
{
    int blk = blockIdx.x;
    int t = 0;
    while (t + 1 < P.nT && blk >= P.blkStart[t + 1]) t++;
    int i = (blk - P.blkStart[t]) * 256 * 4 + threadIdx.x * 4;
    const float* x = P.src[t];
    float4 v = *(const float4*)(x + i);
    __nv_bfloat16 h0 = __float2bfloat16(v.x), h1 = __float2bfloat16(v.y);
    __nv_bfloat16 h2 = __float2bfloat16(v.z), h3 = __float2bfloat16(v.w);
    __nv_bfloat162 hA, hB, lA, lB;
    hA.x = h0; hA.y = h1; hB.x = h2; hB.y = h3;
    lA.x = __float2bfloat16(v.x - __bfloat162float(h0));
    lA.y = __float2bfloat16(v.y - __bfloat162float(h1));
    lB.x = __float2bfloat16(v.z - __bfloat162float(h2));
    lB.y = __float2bfloat16(v.w - __bfloat162float(h3));
    *(__nv_bfloat162*)(P.hi[t] + i)     = hA;
    *(__nv_bfloat162*)(P.hi[t] + i + 2) = hB;
    *(__nv_bfloat162*)(P.lo[t] + i)     = lA;
    *(__nv_bfloat162*)(P.lo[t] + i + 2) = lB;
}

// ---------------------------------------------------------------------------
// HMMA split-bf16 GEMM core: 128x64 CTA tile, 256 threads, 2 CTAs/SM.
// (bf16 3-term mainloop unchanged — validated at tensor=63.8%)
// fp16 output path: hi (+optional lo) for attention operands.
// ---------------------------------------------------------------------------
#define GSTAGE  49152
#define GA_HI   0
#define GA_LO   16384
#define GB_HI   32768
#define GB_LO   40960
#define GSMEM   (2*GSTAGE)          // 96KB

__device__ __forceinline__ void gemm_core(
    const __nv_bfloat16* __restrict__ Ahi, const __nv_bfloat16* __restrict__ Alo,
    const __nv_bfloat16* __restrict__ Bhi, const __nv_bfloat16* __restrict__ Blo,
    const float* __restrict__ bias, float* __restrict__ out32,
    __half* __restrict__ outh, __half* __restrict__ outl,
    float scale, int M, int N, int K, char* smem)
{
    const uint32_t sbase = smem_u32(smem);
    const int tid  = threadIdx.x;
    const int wid  = tid >> 5;
    const int lane = tid & 31;
    const int m0 = blockIdx.y * 128;
    const int n0 = blockIdx.x * 64;
    const int wm = wid & 3;
    const int wn = wid >> 2;

    float acc[2][4][4];
#pragma unroll
    for (int i = 0; i < 2; i++)
#pragma unroll
        for (int j = 0; j < 4; j++)
#pragma unroll
            for (int c = 0; c < 4; c++) acc[i][j][c] = 0.f;

    auto load_stage = [&](int t, int buf) {
        const int k0 = t * 64;
        const uint32_t sb = sbase + buf * GSTAGE;
#pragma unroll
        for (int l = 0; l < 4; l++) {
            int idx = l * 256 + tid;
            int row = idx >> 3, ch = idx & 7;
            uint32_t sw = swz(row, ch);
            size_t ao = (size_t)(m0 + row) * K + k0 + ch * 8;
            cp_async16(sb + GA_HI + sw, Ahi + ao);
            cp_async16(sb + GA_LO + sw, Alo + ao);
        }
#pragma unroll
        for (int l = 0; l < 2; l++) {
            int idx = l * 256 + tid;
            int row = idx >> 3, ch = idx & 7;
            uint32_t sw = swz(row, ch);
            size_t bo = (size_t)(n0 + row) * K + k0 + ch * 8;
            cp_async16(sb + GB_HI + sw, Bhi + bo);
            cp_async16(sb + GB_LO + sw, Blo + bo);
        }
    };

    load_stage(0, 0);
    CP_COMMIT();

    const int arow = wm * 32 + (lane & 15);
    const int brow = wn * 32 + (lane & 15);

    const int NT = K / 64;
#pragma unroll 1
    for (int t = 0; t < NT; t++) {
        const int buf = t & 1;
        if (t + 1 < NT) {
            load_stage(t + 1, (t + 1) & 1);
            CP_COMMIT();
            CP_WAIT(1);
        } else {
            CP_WAIT(0);
        }
        __syncthreads();

        const uint32_t sb = sbase + buf * GSTAGE;
#pragma unroll
        for (int ks = 0; ks < 4; ks++) {
            const int ch = ks * 2 + (lane >> 4);
            uint32_t ah[2][4], al[2][4];
#pragma unroll
            for (int mt = 0; mt < 2; mt++) {
                uint32_t sw = swz(arow + mt * 16, ch);
                ldsm4(ah[mt], sb + GA_HI + sw);
                ldsm4(al[mt], sb + GA_LO + sw);
            }
            uint32_t bh[2][4], bl[2][4];
#pragma unroll
            for (int nb = 0; nb < 2; nb++) {
                uint32_t sw = swz(brow + nb * 16, ch);
                ldsm4(bh[nb], sb + GB_HI + sw);
                ldsm4(bl[nb], sb + GB_LO + sw);
            }
#pragma unroll
            for (int mt = 0; mt < 2; mt++)
#pragma unroll
                for (int nt = 0; nt < 4; nt++) {
                    const int nb = nt >> 1, hh = nt & 1;
                    mma16816(acc[mt][nt], ah[mt], bh[nb][hh], bh[nb][2 + hh]);
                    mma16816(acc[mt][nt], ah[mt], bl[nb][hh], bl[nb][2 + hh]);
                    mma16816(acc[mt][nt], al[mt], bh[nb][hh], bh[nb][2 + hh]);
                }
        }
        __syncthreads();
    }

#pragma unroll
    for (int mt = 0; mt < 2; mt++) {
#pragma unroll
        for (int nt = 0; nt < 4; nt++) {
            int row = m0 + wm * 32 + mt * 16 + (lane >> 2);
            int col = n0 + wn * 32 + nt * 8 + (lane & 3) * 2;
            if (out32) {
                float2 v0, v1;
                v0.x = acc[mt][nt][0]; v0.y = acc[mt][nt][1];
                v1.x = acc[mt][nt][2]; v1.y = acc[mt][nt][3];
                if (bias) {
                    float b0 = bias[col], b1 = bias[col + 1];
                    v0.x += b0; v0.y += b1;
                    v1.x += b0; v1.y += b1;
                }
                *(float2*)(out32 + (size_t)row * N + col)       = v0;
                *(float2*)(out32 + (size_t)(row + 8) * N + col) = v1;
            } else {
#pragma unroll
                for (int rr = 0; rr < 2; rr++) {
                    size_t o = (size_t)(row + rr * 8) * N + col;
                    float x0 = acc[mt][nt][rr * 2 + 0] * scale;
                    float x1 = acc[mt][nt][rr * 2 + 1] * scale;
                    __half h0 = __float2half_rn(x0);
                    __half h1 = __float2half_rn(x1);
                    __half2 hv; hv.x = h0; hv.y = h1;
                    *(__half2*)(outh + o) = hv;
                    if (outl) {
                        __half2 lv;
                        lv.x = __float2half_rn(x0 - __half2float(h0));
                        lv.y = __float2half_rn(x1 - __half2float(h1));
                        *(__half2*)(outl + o) = lv;
                    }
                }
            }
        }
    }
}

__global__ __launch_bounds__(256, 2)
void gemm_tc_kernel(const __nv_bfloat16* __restrict__ Ahi,
                    const __nv_bfloat16* __restrict__ Alo,
                    const __nv_bfloat16* __restrict__ Bhi,
                    const __nv_bfloat16* __restrict__ Blo,
                    const float* __restrict__ bias, float* __restrict__ out32,
                    int M, int N, int K)
{
    extern __shared__ char smem[];
    gemm_core(Ahi, Alo, Bhi, Blo, bias, out32, nullptr, nullptr, 1.0f,
              M, N, K, smem);
}

struct QKVParams {
    const __nv_bfloat16 *Ahi[3], *Alo[3], *Bhi[3], *Blo[3];
    __half *oh[3], *ol[3];
    float scale[3];
};
__global__ __launch_bounds__(256, 2)
void gemm_qkv_kernel(QKVParams P, int M, int N, int K)
{
    extern __shared__ char smem[];
    const int z = blockIdx.z;
    gemm_core(P.Ahi[z], P.Alo[z], P.Bhi[z], P.Blo[z], nullptr, nullptr,
              P.oh[z], P.ol[z], P.scale[z], M, N, K, smem);
}

// ---------------------------------------------------------------------------
// HMMA flash attention, fp16 2-term split, register-resident softmax,
// 2 CTAs/SM. CTA = 64 q-rows, 256 threads (2 wm x 4 wn).
// QK: S = Qh * (Kh + Kl);  PV: O = Ph * (Vh + Vl).  (A-side fp16 hi only)
// ---------------------------------------------------------------------------
#define AS_QH   0                     // 8KB (64 rows x 64 f16)
#define AS_K    8192                  // [buf][hi 8KB | lo 8KB] x2 = 32KB
#define AS_V    40960                 // 32KB
#define AS_SO   8192                  // epilogue alias over K region (64x68 f32)
#define AS_DEN  73728                 // 4 x 64 floats = 1KB
#define ATT_SMEM (AS_DEN + 1024)      // 74752

__global__ __launch_bounds__(256, 2)
void attention_tc_kernel(float* __restrict__ resT,
                         __nv_bfloat16* __restrict__ ctx_h,
                         __nv_bfloat16* __restrict__ ctx_l)
{
    extern __shared__ char smem[];
    const uint32_t sbase = smem_u32(smem);
    float* sDen4 = (float*)(smem + AS_DEN);   // [4 wn][64]

    const int tid  = threadIdx.x;
    const int wid  = tid >> 5;
    const int lane = tid & 31;
    const int wm = wid & 1;        // 2 m-warps (32 q-rows each)
    const int wn = wid >> 1;       // 4 k-slice warps (16 k-cols each)
    const int blk = blockIdx.x;
    const int qt  = blk & 31;
    const int h   = (blk >> 5) & 15;
    const int b   = blk >> 9;
    const int q0  = qt * 64;

    const size_t headBase = (size_t)b * Sq * Dq + (size_t)h * Sq * DHq;
    const __half* Qh = g_qh + headBase;
    const __half* Kh = g_kh + headBase;
    const __half* Kl = g_kl + headBase;
    const __half* Vh = g_vh + headBase;
    const __half* Vl = g_vl + headBase;

    // ---- initial loads: Q (persistent, hi only) + K/V stage 0 ----
#pragma unroll
    for (int l = 0; l < 2; l++) {
        int idx = l * 256 + tid;
        int row = idx >> 3, ch = idx & 7;
        uint32_t sw = swz(row, ch);
        cp_async16(sbase + AS_QH + sw, Qh + (size_t)(q0 + row) * DHq + ch * 8);
    }
#pragma unroll
    for (int l = 0; l < 2; l++) {
        int idx = l * 256 + tid;
        int row = idx >> 3, ch = idx & 7;
        uint32_t sw = swz(row, ch);
        size_t o = (size_t)row * DHq + ch * 8;
        cp_async16(sbase + AS_K + sw,        Kh + o);
        cp_async16(sbase + AS_K + 8192 + sw, Kl + o);
        cp_async16(sbase + AS_V + sw,        Vh + o);
        cp_async16(sbase + AS_V + 8192 + sw, Vl + o);
    }
    CP_COMMIT();

    // O partials: [mt][ds][hh2][4]
    float oacc[2][4][2][4];
#pragma unroll
    for (int mt = 0; mt < 2; mt++)
#pragma unroll
        for (int ds = 0; ds < 4; ds++)
#pragma unroll
            for (int hh = 0; hh < 2; hh++)
#pragma unroll
                for (int c = 0; c < 4; c++) oacc[mt][ds][hh][c] = 0.f;
    float denAcc[2][2] = {{0.f, 0.f}, {0.f, 0.f}};

    const int arow = wm * 32 + (lane & 15);
    const int brow = wn * 16 + (lane & 15);
    const int vrow0 = (lane & 7) + ((lane >> 4) << 3);
    const u64* mb = g_mbits + (((size_t)b * 32) << 11) + q0;

    const int NT = Sq / 64;
#pragma unroll 1
    for (int kt = 0; kt < NT; kt++) {
        const int buf = kt & 1;
        CP_WAIT(0);
        __syncthreads();   // K/V[buf] ready; all prev-tile V reads complete

        // prefetch next K/V stage into the other buffer
        if (kt + 1 < NT) {
            const uint32_t kb = sbase + AS_K + (1 - buf) * 16384;
            const uint32_t vb = sbase + AS_V + (1 - buf) * 16384;
            const size_t gk = (size_t)(kt + 1) * 64 * DHq;
#pragma unroll
            for (int l = 0; l < 2; l++) {
                int idx = l * 256 + tid;
                int row = idx >> 3, ch = idx & 7;
                uint32_t sw = swz(row, ch);
                size_t o = gk + (size_t)row * DHq + ch * 8;
                cp_async16(kb + sw,        Kh + o);
                cp_async16(kb + 8192 + sw, Kl + o);
                cp_async16(vb + sw,        Vh + o);
                cp_async16(vb + 8192 + sw, Vl + o);
            }
            CP_COMMIT();
        }

        // ---- S = Qh * (Kh + Kl), this warp's 16 k-cols ----
        float sacc[2][2][4];
#pragma unroll
        for (int mt = 0; mt < 2; mt++)
#pragma unroll
            for (int hh = 0; hh < 2; hh++)
#pragma unroll
                for (int c = 0; c < 4; c++) sacc[mt][hh][c] = 0.f;

        const uint32_t kbh = sbase + AS_K + buf * 16384;
        const uint32_t kbl = kbh + 8192;
#pragma unroll
        for (int ks = 0; ks < 4; ks++) {
            const int ch = ks * 2 + (lane >> 4);
            uint32_t ah[2][4];
#pragma unroll
            for (int mt = 0; mt < 2; mt++) {
                uint32_t sw = swz(arow + mt * 16, ch);
                ldsm4(ah[mt], sbase + AS_QH + sw);
            }
            uint32_t bh[4], bl[4];
            {
                uint32_t sw = swz(brow, ch);
                ldsm4(bh, kbh + sw);
                ldsm4(bl, kbl + sw);
            }
#pragma unroll
            for (int mt = 0; mt < 2; mt++)
#pragma unroll
                for (int hh = 0; hh < 2; hh++) {
                    mma16816h(sacc[mt][hh], ah[mt], bh[hh], bh[2 + hh]);
                    mma16816h(sacc[mt][hh], ah[mt], bl[hh], bl[2 + hh]);
                }
        }

        // ---- softmax in registers -> P A-fragments (fp16 hi only) ----
        uint32_t phi[2][4];
        const u64* mtile = mb + ((size_t)kt << 11);
#pragma unroll
        for (int mt = 0; mt < 2; mt++) {
#pragma unroll
            for (int rr = 0; rr < 2; rr++) {
                const int r = wm * 32 + mt * 16 + (lane >> 2) + rr * 8;
                const u64 mword = mtile[r];
#pragma unroll
                for (int hh = 0; hh < 2; hh++) {
                    const int colg = wn * 16 + hh * 8 + (lane & 3) * 2;
                    float p0 = ((mword >> colg) & 1ull)
                             ? __expf(sacc[mt][hh][rr * 2 + 0]) : 0.f;
                    float p1 = ((mword >> (colg + 1)) & 1ull)
                             ? __expf(sacc[mt][hh][rr * 2 + 1]) : 0.f;
                    denAcc[mt][rr] += p0 + p1;
                    phi[mt][hh * 2 + rr] = cvt2h(p0, p1);
                }
            }
        }

        // ---- O += Ph * (Vh + Vl) over this warp's k-slice ----
        const uint32_t vbh = sbase + AS_V + buf * 16384;
        const uint32_t vbl = vbh + 8192;
#pragma unroll
        for (int ds = 0; ds < 4; ds++) {
            uint32_t bh[4], bl[4];
            uint32_t sw = swz(wn * 16 + vrow0, ds * 2 + ((lane >> 3) & 1));
            ldsm4t(bh, vbh + sw);
            ldsm4t(bl, vbl + sw);
#pragma unroll
            for (int mt = 0; mt < 2; mt++)
#pragma unroll
                for (int hh = 0; hh < 2; hh++) {
                    mma16816h(oacc[mt][ds][hh], phi[mt], bh[hh], bh[2 + hh]);
                    mma16816h(oacc[mt][ds][hh], phi[mt], bl[hh], bl[2 + hh]);
                }
        }
    }

    // ---- denominator: quad shfl -> per-wn smem slot ----
#pragma unroll
    for (int mt = 0; mt < 2; mt++)
#pragma unroll
        for (int rr = 0; rr < 2; rr++) {
            float d = denAcc[mt][rr];
            d += __shfl_xor_sync(0xffffffffu, d, 1);
            d += __shfl_xor_sync(0xffffffffu, d, 2);
            if ((lane & 3) == 0)
                sDen4[wn * 64 + wm * 32 + mt * 16 + (lane >> 2) + rr * 8] = d;
        }
    __syncthreads();   // K smem now dead; den slots written

    // ---- cross-wn O reduction into sO (aliased over K buffer, pitch 68) ----
    float* sO = (float*)(smem + AS_SO);
#pragma unroll 1
    for (int round = 0; round < 4; round++) {
        if (wn == round) {
#pragma unroll
            for (int mt = 0; mt < 2; mt++)
#pragma unroll
                for (int ds = 0; ds < 4; ds++)
#pragma unroll
                    for (int hh = 0; hh < 2; hh++)
#pragma unroll
                        for (int rr = 0; rr < 2; rr++) {
                            int r = wm * 32 + mt * 16 + (lane >> 2) + rr * 8;
                            int c = ds * 16 + hh * 8 + (lane & 3) * 2;
                            float* p = &sO[r * 68 + c];
                            if (round == 0) {
                                p[0] = oacc[mt][ds][hh][rr * 2 + 0];
                                p[1] = oacc[mt][ds][hh][rr * 2 + 1];
                            } else {
                                p[0] += oacc[mt][ds][hh][rr * 2 + 0];
                                p[1] += oacc[mt][ds][hh][rr * 2 + 1];
                            }
                        }
        }
        __syncthreads();
    }

    // ---- final: normalize, write split context (bf16) + resT ----
    {
        const int r  = tid >> 2;            // 0..63
        const int cb = (tid & 3) * 16;      // 0,16,32,48
        float dn = sDen4[r] + sDen4[64 + r] + sDen4[128 + r] + sDen4[192 + r];
        float inv = dn > 0.f ? 1.f / dn : 0.f;     // NaN->0 semantics
        int s2 = q0 + r;
        size_t co = ((size_t)b * Sq + s2) * Dq + h * DHq + cb;
        float xv[16];
#pragma unroll
        for (int j = 0; j < 16; j++) xv[j] = sO[r * 68 + cb + j] * inv;
        uint32_t hp[8], lp[8];
#pragma unroll
        for (int j = 0; j < 8; j++) {
            __nv_bfloat162 h2;
            h2.x = __float2bfloat16(xv[2 * j]);
            h2.y = __float2bfloat16(xv[2 * j + 1]);
            hp[j] = *(uint32_t*)&h2;
            lp[j] = packbf2(xv[2 * j]     - __bfloat162float(h2.x),
                            xv[2 * j + 1] - __bfloat162float(h2.y));
        }
        *(uint4*)(ctx_h + co)     = *(uint4*)&hp[0];
        *(uint4*)(ctx_h + co + 8) = *(uint4*)&hp[4];
        *(uint4*)(ctx_l + co)     = *(uint4*)&lp[0];
        *(uint4*)(ctx_l + co + 8) = *(uint4*)&lp[4];
        if (resT) {
            float* rp = resT + (((size_t)h * Bq + b) * Sq + s2) * DHq + cb;
#pragma unroll
            for (int j = 0; j < 4; j++)
                *(float4*)(rp + 4 * j) = *(float4*)&xv[4 * j];
        }
    }
}

// ---------------------------------------------------------------------------
extern "C" void kernel_launch(void* const* d_in, const int* in_sizes, int n_in,
                              void* d_out, int out_size)
{
    const float* query = (const float*)d_in[0];
    const float* key_  = (const float*)d_in[1];
    const float* value = (const float*)d_in[2];
    const void*  mask  = d_in[3];
    const float* Wq    = (const float*)d_in[4];
    const float* Wk    = (const float*)d_in[5];
    const float* Wv    = (const float*)d_in[6];
    const float* fcw   = (const float*)d_in[7];
    const float* fcb   = (const float*)d_in[8];
    float* out = (float*)d_out;

    __half *qh, *kh, *kl, *vh, *vl;
    __nv_bfloat16 *xhi, *xlo, *yhi, *ylo, *zhi, *zlo;
    __nv_bfloat16 *w1h, *w1l, *w2h, *w2l, *w3h, *w3l, *w4h, *w4l;
    cudaGetSymbolAddress((void**)&qh,  g_qh);
    cudaGetSymbolAddress((void**)&kh,  g_kh);
    cudaGetSymbolAddress((void**)&kl,  g_kl);
    cudaGetSymbolAddress((void**)&vh,  g_vh);
    cudaGetSymbolAddress((void**)&vl,  g_vl);
    cudaGetSymbolAddress((void**)&xhi, g_xhi);
    cudaGetSymbolAddress((void**)&xlo, g_xlo);
    cudaGetSymbolAddress((void**)&yhi, g_yhi);
    cudaGetSymbolAddress((void**)&ylo, g_ylo);
    cudaGetSymbolAddress((void**)&zhi, g_zhi);
    cudaGetSymbolAddress((void**)&zlo, g_zlo);
    cudaGetSymbolAddress((void**)&w1h, g_w1h);
    cudaGetSymbolAddress((void**)&w1l, g_w1l);
    cudaGetSymbolAddress((void**)&w2h, g_w2h);
    cudaGetSymbolAddress((void**)&w2l, g_w2l);
    cudaGetSymbolAddress((void**)&w3h, g_w3h);
    cudaGetSymbolAddress((void**)&w3l, g_w3l);
    cudaGetSymbolAddress((void**)&w4h, g_w4h);
    cudaGetSymbolAddress((void**)&w4l, g_w4l);

    cudaFuncSetAttribute(gemm_tc_kernel,
                         cudaFuncAttributeMaxDynamicSharedMemorySize, GSMEM);
    cudaFuncSetAttribute(gemm_qkv_kernel,
                         cudaFuncAttributeMaxDynamicSharedMemorySize, GSMEM);
    cudaFuncSetAttribute(attention_tc_kernel,
                         cudaFuncAttributeMaxDynamicSharedMemorySize, ATT_SMEM);

    detect_mask_kernel<<<1, 32>>>((const unsigned char*)mask);
    mask_bits_kernel<<<MWORDS / 256, 256>>>(mask);

    const int M = Bq * Sq;               // 8192
    const int nX = M * Dq, nW = Dq * Dq;
    const int bX = nX / 1024, bW = nW / 1024;

    // one batched split launch: q, k, v, Wq, Wk, Wv, fcw
    SplitParams sp{};
    const float* srcs[7] = {query, key_, value, Wq, Wk, Wv, fcw};
    __nv_bfloat16* his[7] = {xhi, yhi, zhi, w1h, w2h, w3h, w4h};
    __nv_bfloat16* los[7] = {xlo, ylo, zlo, w1l, w2l, w3l, w4l};
    int off = 0;
    for (int t = 0; t < 7; t++) {
        sp.src[t] = srcs[t]; sp.hi[t] = his[t]; sp.lo[t] = los[t];
        sp.blkStart[t] = off;
        off += (t < 3) ? bX : bW;
    }
    sp.blkStart[7] = off;
    sp.nT = 7;
    split_all_kernel<<<off, 256>>>(sp);

    // merged Q/K/V projection GEMMs: bf16 3-term; outputs fp16 for attention
    // (Q hi-only pre-scaled by 1/8; K,V hi+lo)
    QKVParams qp{};
    qp.Ahi[0] = xhi; qp.Alo[0] = xlo; qp.Bhi[0] = w1h; qp.Blo[0] = w1l;
    qp.oh[0] = qh; qp.ol[0] = nullptr; qp.scale[0] = 0.125f;
    qp.Ahi[1] = yhi; qp.Alo[1] = ylo; qp.Bhi[1] = w2h; qp.Blo[1] = w2l;
    qp.oh[1] = kh; qp.ol[1] = kl; qp.scale[1] = 1.0f;
    qp.Ahi[2] = zhi; qp.Alo[2] = zlo; qp.Bhi[2] = w3h; qp.Blo[2] = w3l;
    qp.oh[2] = vh; qp.ol[2] = vl; qp.scale[2] = 1.0f;
    dim3 gq(Dq / 64, M / 128, 3);      // (16, 64, 3)
    gemm_qkv_kernel<<<gq, 256, GSMEM>>>(qp, M, Dq, Dq);

    // attention writes context split (bf16) into xhi/xlo + resT fp32
    float* resT = (out_size >= 2 * BSDq) ? (out + BSDq) : nullptr;
    attention_tc_kernel<<<Bq * Hq * (Sq / 64), 256, ATT_SMEM>>>(resT, xhi, xlo);

    // final FC: bf16 3-term, fp32 out with bias
    dim3 gf(Dq / 64, M / 128);         // (16, 64)
    gemm_tc_kernel<<<gf, 256, GSMEM>>>(xhi, xlo, w4h, w4l, fcb, out, M, Dq, Dq);
}

// round 16
// speedup vs baseline: 2.7761x; 1.1778x over previous
#include <cuda_runtime.h>
#include <cuda_bf16.h>
#include <cuda_fp16.h>
#include <cstdint>
#include <cstddef>

// Problem constants
#define Bq   4
#define Sq   2048
#define Dq   1024
#define Hq   16
#define DHq  64
#define BSDq (Bq*Sq*Dq)   // 8388608
#define MWORDS (Bq*Sq*(Sq/64))   // 262144 u64 mask words

typedef unsigned long long u64;

// ---------------- generic-PTX tensor-core helpers (sm_80+ ISA) -------------
__device__ __forceinline__ uint32_t smem_u32(const void* p) {
    uint32_t a;
    asm("{ .reg .u64 t; cvta.to.shared.u64 t, %1; cvt.u32.u64 %0, t; }"
        : "=r"(a) : "l"(p));
    return a;
}
__device__ __forceinline__ void cp_async16(uint32_t s, const void* g) {
    asm volatile("cp.async.cg.shared.global [%0], [%1], 16;" :: "r"(s), "l"(g));
}
#define CP_COMMIT() asm volatile("cp.async.commit_group;" ::: "memory")
#define CP_WAIT(n)  asm volatile("cp.async.wait_group %0;" :: "n"(n) : "memory")

__device__ __forceinline__ void ldsm4(uint32_t* r, uint32_t addr) {
    asm volatile("ldmatrix.sync.aligned.m8n8.x4.shared.b16 {%0,%1,%2,%3}, [%4];"
                 : "=r"(r[0]), "=r"(r[1]), "=r"(r[2]), "=r"(r[3]) : "r"(addr));
}
__device__ __forceinline__ void ldsm4t(uint32_t* r, uint32_t addr) {
    asm volatile("ldmatrix.sync.aligned.m8n8.x4.trans.shared.b16 {%0,%1,%2,%3}, [%4];"
                 : "=r"(r[0]), "=r"(r[1]), "=r"(r[2]), "=r"(r[3]) : "r"(addr));
}
// D(f32) += A(f16) * B(f16); m16n8k16 row.col
__device__ __forceinline__ void mma16816h(float* d, const uint32_t* a,
                                          uint32_t b0, uint32_t b1) {
    asm volatile(
        "mma.sync.aligned.m16n8k16.row.col.f32.f16.f16.f32 "
        "{%0,%1,%2,%3}, {%4,%5,%6,%7}, {%8,%9}, {%0,%1,%2,%3};"
        : "+f"(d[0]), "+f"(d[1]), "+f"(d[2]), "+f"(d[3])
        : "r"(a[0]), "r"(a[1]), "r"(a[2]), "r"(a[3]), "r"(b0), "r"(b1));
}
// byte offset of (row, 16B-chunk) in a [rows][64 x 16bit] tile, xor swizzle
__device__ __forceinline__ uint32_t swz(int row, int ch) {
    uint32_t off = (uint32_t)(row * 128 + ch * 16);
    return off ^ (((uint32_t)row & 7u) << 4);
}
// single-instruction pack: {lo16=f16(a), hi16=f16(b)}
__device__ __forceinline__ uint32_t cvt2h(float a, float b) {
    uint32_t r;
    asm("cvt.rn.f16x2.f32 %0, %1, %2;" : "=r"(r) : "f"(b), "f"(a));
    return r;
}

// ---------------- scratch (device globals: allocation-free rule) -----------
__device__ int g_mask_kind;                      // 0=uint8, else 4-byte elems
__device__ __align__(16) u64 g_mbits[MWORDS];    // packed mask bits [b][kt][row]
__device__ __align__(16) __half g_qh[BSDq];      // Q fp16 hi (A operand)
__device__ __align__(16) __half g_kh[BSDq];      // K fp16 hi+lo (B operand)
__device__ __align__(16) __half g_kl[BSDq];
__device__ __align__(16) __half g_vh[BSDq];      // V fp16 hi+lo
__device__ __align__(16) __half g_vl[BSDq];
__device__ __align__(16) __half g_xh[BSDq];      // query hi / ctx hi (aliased)
__device__ __align__(16) __half g_yh[BSDq];      // key hi
__device__ __align__(16) __half g_zh[BSDq];      // value hi
__device__ __align__(16) __half g_w1h[Dq * Dq];  // Wq hi+lo
__device__ __align__(16) __half g_w1l[Dq * Dq];
__device__ __align__(16) __half g_w2h[Dq * Dq];  // Wk
__device__ __align__(16) __half g_w2l[Dq * Dq];
__device__ __align__(16) __half g_w3h[Dq * Dq];  // Wv
__device__ __align__(16) __half g_w3l[Dq * Dq];
__device__ __align__(16) __half g_w4h[Dq * Dq];  // fc_w
__device__ __align__(16) __half g_w4l[Dq * Dq];

// ---------------------------------------------------------------------------
__global__ void detect_mask_kernel(const unsigned char* __restrict__ m) {
    if (threadIdx.x != 0) return;
    int c0 = 0, c1 = 0, c2 = 0, c3 = 0;
    for (int i = 0; i < 4096; i += 4) {
        if (m[i + 0]) c0++;
        if (m[i + 1]) c1++;
        if (m[i + 2]) c2++;
        if (m[i + 3]) c3++;
    }
    int kind;
    if (c1 == 0 && c2 == 0 && c3 == 0) kind = 1;   // int32
    else if (c0 == 0 && c1 == 0)       kind = 2;   // float32
    else                               kind = 0;   // uint8
    g_mask_kind = kind;
}

// pack mask -> u64 words, stored TRANSPOSED: [b][kt][row]
__global__ __launch_bounds__(256)
void mask_bits_kernel(const void* __restrict__ mask) {
    int w = blockIdx.x * 256 + threadIdx.x;   // linear over [b][row][kt]
    if (w >= MWORDS) return;
    u64 bits = 0;
    if (g_mask_kind == 0) {
        const uint4* p = (const uint4*)((const unsigned char*)mask + (size_t)w * 64);
#pragma unroll
        for (int q = 0; q < 4; q++) {
            uint4 v = p[q];
            const uint32_t ww[4] = {v.x, v.y, v.z, v.w};
#pragma unroll
            for (int k = 0; k < 4; k++)
#pragma unroll
                for (int j = 0; j < 4; j++)
                    if ((ww[k] >> (8 * j)) & 0xffu)
                        bits |= 1ull << (q * 16 + k * 4 + j);
        }
    } else {   // 4-byte elements
        const uint4* p = (const uint4*)((const uint32_t*)mask + (size_t)w * 64);
#pragma unroll
        for (int q = 0; q < 16; q++) {
            uint4 v = p[q];
            if (v.x) bits |= 1ull << (q * 4 + 0);
            if (v.y) bits |= 1ull << (q * 4 + 1);
            if (v.z) bits |= 1ull << (q * 4 + 2);
            if (v.w) bits |= 1ull << (q * 4 + 3);
        }
    }
    int kt  = w & 31;
    int row = (w >> 5) & (Sq - 1);
    int b   = w >> 16;
    g_mbits[(((size_t)b * 32 + kt) << 11) + row] = bits;
}

// ---- batched fp32 -> fp16 hi (+optional lo) split for up to 8 tensors -----
struct SplitParams {
    const float* src[8];
    __half* hi[8];
    __half* lo[8];          // null -> hi only
    int blkStart[9];
    int nT;
};

__global__ __launch_bounds__(256)
void split_all_kernel(SplitParams P)
{
    int blk = blockIdx.x;
    int t = 0;
    while (t + 1 < P.nT && blk >= P.blkStart[t + 1]) t++;
    int i = (blk - P.blkStart[t]) * 256 * 4 + threadIdx.x * 4;
    const float* x = P.src[t];
    float4 v = *(const float4*)(x + i);
    __half h0 = __float2half_rn(v.x), h1 = __float2half_rn(v.y);
    __half h2 = __float2half_rn(v.z), h3 = __float2half_rn(v.w);
    __half2 hA, hB;
    hA.x = h0; hA.y = h1; hB.x = h2; hB.y = h3;
    *(__half2*)(P.hi[t] + i)     = hA;
    *(__half2*)(P.hi[t] + i + 2) = hB;
    if (P.lo[t]) {
        __half2 lA, lB;
        lA.x = __float2half_rn(v.x - __half2float(h0));
        lA.y = __float2half_rn(v.y - __half2float(h1));
        lB.x = __float2half_rn(v.z - __half2float(h2));
        lB.y = __float2half_rn(v.w - __half2float(h3));
        *(__half2*)(P.lo[t] + i)     = lA;
        *(__half2*)(P.lo[t] + i + 2) = lB;
    }
}

// ---------------------------------------------------------------------------
// HMMA fp16 2-term GEMM core: out = Ah @ (Bh + Bl)^T.  128x64 CTA tile,
// 256 threads, stage 32KB -> 64KB dbuf, 2 CTAs/SM. 16 MMAs per ks chunk.
// ---------------------------------------------------------------------------
#define GA_HI   0                    // 128 x 64 f16 = 16KB
#define GB_HI   16384                // 64 x 64 f16 = 8KB
#define GB_LO   24576
#define GSTAGE  32768
#define GSMEM   (2*GSTAGE)           // 64KB

__device__ __forceinline__ void gemm_core(
    const __half* __restrict__ Ah,
    const __half* __restrict__ Bh, const __half* __restrict__ Bl,
    const float* __restrict__ bias, float* __restrict__ out32,
    __half* __restrict__ outh, __half* __restrict__ outl,
    float scale, int M, int N, int K, char* smem)
{
    const uint32_t sbase = smem_u32(smem);
    const int tid  = threadIdx.x;
    const int wid  = tid >> 5;
    const int lane = tid & 31;
    const int m0 = blockIdx.y * 128;
    const int n0 = blockIdx.x * 64;
    const int wm = wid & 3;
    const int wn = wid >> 2;

    float acc[2][4][4];
#pragma unroll
    for (int i = 0; i < 2; i++)
#pragma unroll
        for (int j = 0; j < 4; j++)
#pragma unroll
            for (int c = 0; c < 4; c++) acc[i][j][c] = 0.f;

    auto load_stage = [&](int t, int buf) {
        const int k0 = t * 64;
        const uint32_t sb = sbase + buf * GSTAGE;
#pragma unroll
        for (int l = 0; l < 4; l++) {
            int idx = l * 256 + tid;
            int row = idx >> 3, ch = idx & 7;
            uint32_t sw = swz(row, ch);
            cp_async16(sb + GA_HI + sw, Ah + (size_t)(m0 + row) * K + k0 + ch * 8);
        }
#pragma unroll
        for (int l = 0; l < 2; l++) {
            int idx = l * 256 + tid;
            int row = idx >> 3, ch = idx & 7;
            uint32_t sw = swz(row, ch);
            size_t bo = (size_t)(n0 + row) * K + k0 + ch * 8;
            cp_async16(sb + GB_HI + sw, Bh + bo);
            cp_async16(sb + GB_LO + sw, Bl + bo);
        }
    };

    load_stage(0, 0);
    CP_COMMIT();

    const int arow = wm * 32 + (lane & 15);
    const int brow = wn * 32 + (lane & 15);

    const int NT = K / 64;
#pragma unroll 1
    for (int t = 0; t < NT; t++) {
        const int buf = t & 1;
        if (t + 1 < NT) {
            load_stage(t + 1, (t + 1) & 1);
            CP_COMMIT();
            CP_WAIT(1);        // 2 groups in flight -> drains the older (buf t)
        } else {
            CP_WAIT(0);
        }
        __syncthreads();

        const uint32_t sb = sbase + buf * GSTAGE;
#pragma unroll
        for (int ks = 0; ks < 4; ks++) {
            const int ch = ks * 2 + (lane >> 4);
            uint32_t ah[2][4];
#pragma unroll
            for (int mt = 0; mt < 2; mt++) {
                uint32_t sw = swz(arow + mt * 16, ch);
                ldsm4(ah[mt], sb + GA_HI + sw);
            }
            uint32_t bh[2][4], bl[2][4];
#pragma unroll
            for (int nb = 0; nb < 2; nb++) {
                uint32_t sw = swz(brow + nb * 16, ch);
                ldsm4(bh[nb], sb + GB_HI + sw);
                ldsm4(bl[nb], sb + GB_LO + sw);
            }
#pragma unroll
            for (int mt = 0; mt < 2; mt++)
#pragma unroll
                for (int nt = 0; nt < 4; nt++) {
                    const int nb = nt >> 1, hh = nt & 1;
                    mma16816h(acc[mt][nt], ah[mt], bh[nb][hh], bh[nb][2 + hh]);
                    mma16816h(acc[mt][nt], ah[mt], bl[nb][hh], bl[nb][2 + hh]);
                }
        }
        __syncthreads();       // compute(t) done before load_stage(t+2) -> buf t
    }

#pragma unroll
    for (int mt = 0; mt < 2; mt++) {
#pragma unroll
        for (int nt = 0; nt < 4; nt++) {
            int row = m0 + wm * 32 + mt * 16 + (lane >> 2);
            int col = n0 + wn * 32 + nt * 8 + (lane & 3) * 2;
            if (out32) {
                float2 v0, v1;
                v0.x = acc[mt][nt][0]; v0.y = acc[mt][nt][1];
                v1.x = acc[mt][nt][2]; v1.y = acc[mt][nt][3];
                if (bias) {
                    float b0 = bias[col], b1 = bias[col + 1];
                    v0.x += b0; v0.y += b1;
                    v1.x += b0; v1.y += b1;
                }
                *(float2*)(out32 + (size_t)row * N + col)       = v0;
                *(float2*)(out32 + (size_t)(row + 8) * N + col) = v1;
            } else {
#pragma unroll
                for (int rr = 0; rr < 2; rr++) {
                    size_t o = (size_t)(row + rr * 8) * N + col;
                    float x0 = acc[mt][nt][rr * 2 + 0] * scale;
                    float x1 = acc[mt][nt][rr * 2 + 1] * scale;
                    __half h0 = __float2half_rn(x0);
                    __half h1 = __float2half_rn(x1);
                    __half2 hv; hv.x = h0; hv.y = h1;
                    *(__half2*)(outh + o) = hv;
                    if (outl) {
                        __half2 lv;
                        lv.x = __float2half_rn(x0 - __half2float(h0));
                        lv.y = __float2half_rn(x1 - __half2float(h1));
                        *(__half2*)(outl + o) = lv;
                    }
                }
            }
        }
    }
}

__global__ __launch_bounds__(256, 2)
void gemm_tc_kernel(const __half* __restrict__ Ah,
                    const __half* __restrict__ Bh,
                    const __half* __restrict__ Bl,
                    const float* __restrict__ bias, float* __restrict__ out32,
                    int M, int N, int K)
{
    extern __shared__ char smem[];
    gemm_core(Ah, Bh, Bl, bias, out32, nullptr, nullptr, 1.0f, M, N, K, smem);
}

struct QKVParams {
    const __half *Ah[3], *Bh[3], *Bl[3];
    __half *oh[3], *ol[3];
    float scale[3];
};
__global__ __launch_bounds__(256, 2)
void gemm_qkv_kernel(QKVParams P, int M, int N, int K)
{
    extern __shared__ char smem[];
    const int z = blockIdx.z;
    gemm_core(P.Ah[z], P.Bh[z], P.Bl[z], nullptr, nullptr,
              P.oh[z], P.ol[z], P.scale[z], M, N, K, smem);
}

// ---------------------------------------------------------------------------
// HMMA flash attention, fp16 2-term split, register-resident softmax,
// 2 CTAs/SM. CTA = 64 q-rows, 256 threads (2 wm x 4 wn).
// QK: S = Qh * (Kh + Kl);  PV: O = Ph * (Vh + Vl).  ctx output fp16 hi only.
// ---------------------------------------------------------------------------
#define AS_QH   0                     // 8KB (64 rows x 64 f16)
#define AS_K    8192                  // [buf][hi 8KB | lo 8KB] x2 = 32KB
#define AS_V    40960                 // 32KB
#define AS_SO   8192                  // epilogue alias over K region (64x68 f32)
#define AS_DEN  73728                 // 4 x 64 floats = 1KB
#define ATT_SMEM (AS_DEN + 1024)      // 74752

__global__ __launch_bounds__(256, 2)
void attention_tc_kernel(float* __restrict__ resT, __half* __restrict__ ctx)
{
    extern __shared__ char smem[];
    const uint32_t sbase = smem_u32(smem);
    float* sDen4 = (float*)(smem + AS_DEN);   // [4 wn][64]

    const int tid  = threadIdx.x;
    const int wid  = tid >> 5;
    const int lane = tid & 31;
    const int wm = wid & 1;        // 2 m-warps (32 q-rows each)
    const int wn = wid >> 1;       // 4 k-slice warps (16 k-cols each)
    const int blk = blockIdx.x;
    const int qt  = blk & 31;
    const int h   = (blk >> 5) & 15;
    const int b   = blk >> 9;
    const int q0  = qt * 64;

    const size_t headBase = (size_t)b * Sq * Dq + (size_t)h * Sq * DHq;
    const __half* Qh = g_qh + headBase;
    const __half* Kh = g_kh + headBase;
    const __half* Kl = g_kl + headBase;
    const __half* Vh = g_vh + headBase;
    const __half* Vl = g_vl + headBase;

    // ---- initial loads: Q (persistent, hi only) + K/V stage 0 ----
#pragma unroll
    for (int l = 0; l < 2; l++) {
        int idx = l * 256 + tid;
        int row = idx >> 3, ch = idx & 7;
        uint32_t sw = swz(row, ch);
        cp_async16(sbase + AS_QH + sw, Qh + (size_t)(q0 + row) * DHq + ch * 8);
    }
#pragma unroll
    for (int l = 0; l < 2; l++) {
        int idx = l * 256 + tid;
        int row = idx >> 3, ch = idx & 7;
        uint32_t sw = swz(row, ch);
        size_t o = (size_t)row * DHq + ch * 8;
        cp_async16(sbase + AS_K + sw,        Kh + o);
        cp_async16(sbase + AS_K + 8192 + sw, Kl + o);
        cp_async16(sbase + AS_V + sw,        Vh + o);
        cp_async16(sbase + AS_V + 8192 + sw, Vl + o);
    }
    CP_COMMIT();

    // O partials: [mt][ds][hh2][4]
    float oacc[2][4][2][4];
#pragma unroll
    for (int mt = 0; mt < 2; mt++)
#pragma unroll
        for (int ds = 0; ds < 4; ds++)
#pragma unroll
            for (int hh = 0; hh < 2; hh++)
#pragma unroll
                for (int c = 0; c < 4; c++) oacc[mt][ds][hh][c] = 0.f;
    float denAcc[2][2] = {{0.f, 0.f}, {0.f, 0.f}};

    const int arow = wm * 32 + (lane & 15);
    const int brow = wn * 16 + (lane & 15);
    const int vrow0 = (lane & 7) + ((lane >> 4) << 3);
    const u64* mb = g_mbits + (((size_t)b * 32) << 11) + q0;

    const int NT = Sq / 64;
#pragma unroll 1
    for (int kt = 0; kt < NT; kt++) {
        const int buf = kt & 1;
        CP_WAIT(0);
        __syncthreads();   // K/V[buf] ready; all prev-tile V reads complete

        // prefetch next K/V stage into the other buffer
        if (kt + 1 < NT) {
            const uint32_t kb = sbase + AS_K + (1 - buf) * 16384;
            const uint32_t vb = sbase + AS_V + (1 - buf) * 16384;
            const size_t gk = (size_t)(kt + 1) * 64 * DHq;
#pragma unroll
            for (int l = 0; l < 2; l++) {
                int idx = l * 256 + tid;
                int row = idx >> 3, ch = idx & 7;
                uint32_t sw = swz(row, ch);
                size_t o = gk + (size_t)row * DHq + ch * 8;
                cp_async16(kb + sw,        Kh + o);
                cp_async16(kb + 8192 + sw, Kl + o);
                cp_async16(vb + sw,        Vh + o);
                cp_async16(vb + 8192 + sw, Vl + o);
            }
            CP_COMMIT();
        }

        // ---- S = Qh * (Kh + Kl), this warp's 16 k-cols ----
        float sacc[2][2][4];
#pragma unroll
        for (int mt = 0; mt < 2; mt++)
#pragma unroll
            for (int hh = 0; hh < 2; hh++)
#pragma unroll
                for (int c = 0; c < 4; c++) sacc[mt][hh][c] = 0.f;

        const uint32_t kbh = sbase + AS_K + buf * 16384;
        const uint32_t kbl = kbh + 8192;
#pragma unroll
        for (int ks = 0; ks < 4; ks++) {
            const int ch = ks * 2 + (lane >> 4);
            uint32_t ah[2][4];
#pragma unroll
            for (int mt = 0; mt < 2; mt++) {
                uint32_t sw = swz(arow + mt * 16, ch);
                ldsm4(ah[mt], sbase + AS_QH + sw);
            }
            uint32_t bh[4], bl[4];
            {
                uint32_t sw = swz(brow, ch);
                ldsm4(bh, kbh + sw);
                ldsm4(bl, kbl + sw);
            }
#pragma unroll
            for (int mt = 0; mt < 2; mt++)
#pragma unroll
                for (int hh = 0; hh < 2; hh++) {
                    mma16816h(sacc[mt][hh], ah[mt], bh[hh], bh[2 + hh]);
                    mma16816h(sacc[mt][hh], ah[mt], bl[hh], bl[2 + hh]);
                }
        }

        // ---- softmax in registers -> P A-fragments (fp16 hi only) ----
        uint32_t phi[2][4];
        const u64* mtile = mb + ((size_t)kt << 11);
#pragma unroll
        for (int mt = 0; mt < 2; mt++) {
#pragma unroll
            for (int rr = 0; rr < 2; rr++) {
                const int r = wm * 32 + mt * 16 + (lane >> 2) + rr * 8;
                const u64 mword = mtile[r];
#pragma unroll
                for (int hh = 0; hh < 2; hh++) {
                    const int colg = wn * 16 + hh * 8 + (lane & 3) * 2;
                    float p0 = ((mword >> colg) & 1ull)
                             ? __expf(sacc[mt][hh][rr * 2 + 0]) : 0.f;
                    float p1 = ((mword >> (colg + 1)) & 1ull)
                             ? __expf(sacc[mt][hh][rr * 2 + 1]) : 0.f;
                    denAcc[mt][rr] += p0 + p1;
                    phi[mt][hh * 2 + rr] = cvt2h(p0, p1);
                }
            }
        }

        // ---- O += Ph * (Vh + Vl) over this warp's k-slice ----
        const uint32_t vbh = sbase + AS_V + buf * 16384;
        const uint32_t vbl = vbh + 8192;
#pragma unroll
        for (int ds = 0; ds < 4; ds++) {
            uint32_t bh[4], bl[4];
            uint32_t sw = swz(wn * 16 + vrow0, ds * 2 + ((lane >> 3) & 1));
            ldsm4t(bh, vbh + sw);
            ldsm4t(bl, vbl + sw);
#pragma unroll
            for (int mt = 0; mt < 2; mt++)
#pragma unroll
                for (int hh = 0; hh < 2; hh++) {
                    mma16816h(oacc[mt][ds][hh], phi[mt], bh[hh], bh[2 + hh]);
                    mma16816h(oacc[mt][ds][hh], phi[mt], bl[hh], bl[2 + hh]);
                }
        }
    }

    // ---- denominator: quad shfl -> per-wn smem slot ----
#pragma unroll
    for (int mt = 0; mt < 2; mt++)
#pragma unroll
        for (int rr = 0; rr < 2; rr++) {
            float d = denAcc[mt][rr];
            d += __shfl_xor_sync(0xffffffffu, d, 1);
            d += __shfl_xor_sync(0xffffffffu, d, 2);
            if ((lane & 3) == 0)
                sDen4[wn * 64 + wm * 32 + mt * 16 + (lane >> 2) + rr * 8] = d;
        }
    __syncthreads();   // K smem now dead; den slots written

    // ---- cross-wn O reduction into sO (aliased over K buffer, pitch 68) ----
    float* sO = (float*)(smem + AS_SO);
#pragma unroll 1
    for (int round = 0; round < 4; round++) {
        if (wn == round) {
#pragma unroll
            for (int mt = 0; mt < 2; mt++)
#pragma unroll
                for (int ds = 0; ds < 4; ds++)
#pragma unroll
                    for (int hh = 0; hh < 2; hh++)
#pragma unroll
                        for (int rr = 0; rr < 2; rr++) {
                            int r = wm * 32 + mt * 16 + (lane >> 2) + rr * 8;
                            int c = ds * 16 + hh * 8 + (lane & 3) * 2;
                            float* p = &sO[r * 68 + c];
                            if (round == 0) {
                                p[0] = oacc[mt][ds][hh][rr * 2 + 0];
                                p[1] = oacc[mt][ds][hh][rr * 2 + 1];
                            } else {
                                p[0] += oacc[mt][ds][hh][rr * 2 + 0];
                                p[1] += oacc[mt][ds][hh][rr * 2 + 1];
                            }
                        }
        }
        __syncthreads();
    }

    // ---- final: normalize, write ctx (fp16 hi) + resT (fp32) ----
    {
        const int r  = tid >> 2;            // 0..63
        const int cb = (tid & 3) * 16;      // 0,16,32,48
        float dn = sDen4[r] + sDen4[64 + r] + sDen4[128 + r] + sDen4[192 + r];
        float inv = dn > 0.f ? 1.f / dn : 0.f;     // NaN->0 semantics
        int s2 = q0 + r;
        size_t co = ((size_t)b * Sq + s2) * Dq + h * DHq + cb;
        float xv[16];
#pragma unroll
        for (int j = 0; j < 16; j++) xv[j] = sO[r * 68 + cb + j] * inv;
        uint32_t hp[8];
#pragma unroll
        for (int j = 0; j < 8; j++)
            hp[j] = cvt2h(xv[2 * j], xv[2 * j + 1]);
        *(uint4*)(ctx + co)     = *(uint4*)&hp[0];
        *(uint4*)(ctx + co + 8) = *(uint4*)&hp[4];
        if (resT) {
            float* rp = resT + (((size_t)h * Bq + b) * Sq + s2) * DHq + cb;
#pragma unroll
            for (int j = 0; j < 4; j++)
                *(float4*)(rp + 4 * j) = *(float4*)&xv[4 * j];
        }
    }
}

// ---------------------------------------------------------------------------
extern "C" void kernel_launch(void* const* d_in, const int* in_sizes, int n_in,
                              void* d_out, int out_size)
{
    const float* query = (const float*)d_in[0];
    const float* key_  = (const float*)d_in[1];
    const float* value = (const float*)d_in[2];
    const void*  mask  = d_in[3];
    const float* Wq    = (const float*)d_in[4];
    const float* Wk    = (const float*)d_in[5];
    const float* Wv    = (const float*)d_in[6];
    const float* fcw   = (const float*)d_in[7];
    const float* fcb   = (const float*)d_in[8];
    float* out = (float*)d_out;

    __half *qh, *kh, *kl, *vh, *vl, *xh, *yh, *zh;
    __half *w1h, *w1l, *w2h, *w2l, *w3h, *w3l, *w4h, *w4l;
    cudaGetSymbolAddress((void**)&qh,  g_qh);
    cudaGetSymbolAddress((void**)&kh,  g_kh);
    cudaGetSymbolAddress((void**)&kl,  g_kl);
    cudaGetSymbolAddress((void**)&vh,  g_vh);
    cudaGetSymbolAddress((void**)&vl,  g_vl);
    cudaGetSymbolAddress((void**)&xh,  g_xh);
    cudaGetSymbolAddress((void**)&yh,  g_yh);
    cudaGetSymbolAddress((void**)&zh,  g_zh);
    cudaGetSymbolAddress((void**)&w1h, g_w1h);
    cudaGetSymbolAddress((void**)&w1l, g_w1l);
    cudaGetSymbolAddress((void**)&w2h, g_w2h);
    cudaGetSymbolAddress((void**)&w2l, g_w2l);
    cudaGetSymbolAddress((void**)&w3h, g_w3h);
    cudaGetSymbolAddress((void**)&w3l, g_w3l);
    cudaGetSymbolAddress((void**)&w4h, g_w4h);
    cudaGetSymbolAddress((void**)&w4l, g_w4l);

    cudaFuncSetAttribute(gemm_tc_kernel,
                         cudaFuncAttributeMaxDynamicSharedMemorySize, GSMEM);
    cudaFuncSetAttribute(gemm_qkv_kernel,
                         cudaFuncAttributeMaxDynamicSharedMemorySize, GSMEM);
    cudaFuncSetAttribute(attention_tc_kernel,
                         cudaFuncAttributeMaxDynamicSharedMemorySize, ATT_SMEM);

    detect_mask_kernel<<<1, 32>>>((const unsigned char*)mask);
    mask_bits_kernel<<<MWORDS / 256, 256>>>(mask);

    const int M = Bq * Sq;               // 8192
    const int nX = M * Dq, nW = Dq * Dq;
    const int bX = nX / 1024, bW = nW / 1024;

    // one batched split launch: q,k,v (hi only) + Wq,Wk,Wv,fcw (hi+lo)
    SplitParams sp{};
    const float* srcs[7] = {query, key_, value, Wq, Wk, Wv, fcw};
    __half* his[7] = {xh, yh, zh, w1h, w2h, w3h, w4h};
    __half* los[7] = {nullptr, nullptr, nullptr, w1l, w2l, w3l, w4l};
    int off = 0;
    for (int t = 0; t < 7; t++) {
        sp.src[t] = srcs[t]; sp.hi[t] = his[t]; sp.lo[t] = los[t];
        sp.blkStart[t] = off;
        off += (t < 3) ? bX : bW;
    }
    sp.blkStart[7] = off;
    sp.nT = 7;
    split_all_kernel<<<off, 256>>>(sp);

    // merged Q/K/V projection GEMMs: fp16 2-term
    // (Q hi-only pre-scaled by 1/8; K,V hi+lo outputs)
    QKVParams qp{};
    qp.Ah[0] = xh; qp.Bh[0] = w1h; qp.Bl[0] = w1l;
    qp.oh[0] = qh; qp.ol[0] = nullptr; qp.scale[0] = 0.125f;
    qp.Ah[1] = yh; qp.Bh[1] = w2h; qp.Bl[1] = w2l;
    qp.oh[1] = kh; qp.ol[1] = kl; qp.scale[1] = 1.0f;
    qp.Ah[2] = zh; qp.Bh[2] = w3h; qp.Bl[2] = w3l;
    qp.oh[2] = vh; qp.ol[2] = vl; qp.scale[2] = 1.0f;
    dim3 gq(Dq / 64, M / 128, 3);      // (16, 64, 3)
    gemm_qkv_kernel<<<gq, 256, GSMEM>>>(qp, M, Dq, Dq);

    // attention writes ctx (fp16 hi, aliased over g_xh — q input is consumed)
    float* resT = (out_size >= 2 * BSDq) ? (out + BSDq) : nullptr;
    attention_tc_kernel<<<Bq * Hq * (Sq / 64), 256, ATT_SMEM>>>(resT, xh);

    // final FC: fp16 2-term, fp32 out with bias
    dim3 gf(Dq / 64, M / 128);         // (16, 64)
    gemm_tc_kernel<<<gf, 256, GSMEM>>>(xh, w4h, w4l, fcb, out, M, Dq, Dq);
}

// round 17
// speedup vs baseline: 3.0381x; 1.0944x over previous
#include <cuda_runtime.h>
#include <cuda_bf16.h>
#include <cuda_fp16.h>
#include <cstdint>
#include <cstddef>

// Problem constants
#define Bq   4
#define Sq   2048
#define Dq   1024
#define Hq   16
#define DHq  64
#define BSDq (Bq*Sq*Dq)   // 8388608
#define MWORDS (Bq*Sq*(Sq/64))   // 262144 u64 mask words

typedef unsigned long long u64;

// ---------------- generic-PTX tensor-core helpers (sm_80+ ISA) -------------
__device__ __forceinline__ uint32_t smem_u32(const void* p) {
    uint32_t a;
    asm("{ .reg .u64 t; cvta.to.shared.u64 t, %1; cvt.u32.u64 %0, t; }"
        : "=r"(a) : "l"(p));
    return a;
}
__device__ __forceinline__ void cp_async16(uint32_t s, const void* g) {
    asm volatile("cp.async.cg.shared.global [%0], [%1], 16;" :: "r"(s), "l"(g));
}
#define CP_COMMIT() asm volatile("cp.async.commit_group;" ::: "memory")
#define CP_WAIT(n)  asm volatile("cp.async.wait_group %0;" :: "n"(n) : "memory")

__device__ __forceinline__ void ldsm4(uint32_t* r, uint32_t addr) {
    asm volatile("ldmatrix.sync.aligned.m8n8.x4.shared.b16 {%0,%1,%2,%3}, [%4];"
                 : "=r"(r[0]), "=r"(r[1]), "=r"(r[2]), "=r"(r[3]) : "r"(addr));
}
__device__ __forceinline__ void ldsm4t(uint32_t* r, uint32_t addr) {
    asm volatile("ldmatrix.sync.aligned.m8n8.x4.trans.shared.b16 {%0,%1,%2,%3}, [%4];"
                 : "=r"(r[0]), "=r"(r[1]), "=r"(r[2]), "=r"(r[3]) : "r"(addr));
}
// D(f32) += A(f16) * B(f16); m16n8k16 row.col
__device__ __forceinline__ void mma16816h(float* d, const uint32_t* a,
                                          uint32_t b0, uint32_t b1) {
    asm volatile(
        "mma.sync.aligned.m16n8k16.row.col.f32.f16.f16.f32 "
        "{%0,%1,%2,%3}, {%4,%5,%6,%7}, {%8,%9}, {%0,%1,%2,%3};"
        : "+f"(d[0]), "+f"(d[1]), "+f"(d[2]), "+f"(d[3])
        : "r"(a[0]), "r"(a[1]), "r"(a[2]), "r"(a[3]), "r"(b0), "r"(b1));
}
// byte offset of (row, 16B-chunk) in a [rows][64 x 16bit] tile, xor swizzle
__device__ __forceinline__ uint32_t swz(int row, int ch) {
    uint32_t off = (uint32_t)(row * 128 + ch * 16);
    return off ^ (((uint32_t)row & 7u) << 4);
}
// single-instruction pack: {lo16=f16(a), hi16=f16(b)}
__device__ __forceinline__ uint32_t cvt2h(float a, float b) {
    uint32_t r;
    asm("cvt.rn.f16x2.f32 %0, %1, %2;" : "=r"(r) : "f"(b), "f"(a));
    return r;
}

// ---------------- scratch (device globals: allocation-free rule) -----------
__device__ int g_mask_kind;                      // 0=uint8, else 4-byte elems
__device__ __align__(16) u64 g_mbits[MWORDS];    // packed mask bits [b][kt][row]
__device__ __align__(16) __half g_qh[BSDq];      // Q fp16 hi (A operand)
__device__ __align__(16) __half g_kh[BSDq];      // K fp16 hi (B operand)
__device__ __align__(16) __half g_vh[BSDq];      // V fp16 hi+lo
__device__ __align__(16) __half g_vl[BSDq];
__device__ __align__(16) __half g_xh[BSDq];      // query hi / ctx hi (aliased)
__device__ __align__(16) __half g_yh[BSDq];      // key hi
__device__ __align__(16) __half g_zh[BSDq];      // value hi
__device__ __align__(16) __half g_w1h[Dq * Dq];  // Wq hi+lo
__device__ __align__(16) __half g_w1l[Dq * Dq];
__device__ __align__(16) __half g_w2h[Dq * Dq];  // Wk
__device__ __align__(16) __half g_w2l[Dq * Dq];
__device__ __align__(16) __half g_w3h[Dq * Dq];  // Wv
__device__ __align__(16) __half g_w3l[Dq * Dq];
__device__ __align__(16) __half g_w4h[Dq * Dq];  // fc_w
__device__ __align__(16) __half g_w4l[Dq * Dq];

// ---------------------------------------------------------------------------
__global__ void detect_mask_kernel(const unsigned char* __restrict__ m) {
    if (threadIdx.x != 0) return;
    int c0 = 0, c1 = 0, c2 = 0, c3 = 0;
    for (int i = 0; i < 4096; i += 4) {
        if (m[i + 0]) c0++;
        if (m[i + 1]) c1++;
        if (m[i + 2]) c2++;
        if (m[i + 3]) c3++;
    }
    int kind;
    if (c1 == 0 && c2 == 0 && c3 == 0) kind = 1;   // int32
    else if (c0 == 0 && c1 == 0)       kind = 2;   // float32
    else                               kind = 0;   // uint8
    g_mask_kind = kind;
}

// pack mask -> u64 words, stored TRANSPOSED: [b][kt][row]
__global__ __launch_bounds__(256)
void mask_bits_kernel(const void* __restrict__ mask) {
    int w = blockIdx.x * 256 + threadIdx.x;   // linear over [b][row][kt]
    if (w >= MWORDS) return;
    u64 bits = 0;
    if (g_mask_kind == 0) {
        const uint4* p = (const uint4*)((const unsigned char*)mask + (size_t)w * 64);
#pragma unroll
        for (int q = 0; q < 4; q++) {
            uint4 v = p[q];
            const uint32_t ww[4] = {v.x, v.y, v.z, v.w};
#pragma unroll
            for (int k = 0; k < 4; k++)
#pragma unroll
                for (int j = 0; j < 4; j++)
                    if ((ww[k] >> (8 * j)) & 0xffu)
                        bits |= 1ull << (q * 16 + k * 4 + j);
        }
    } else {   // 4-byte elements
        const uint4* p = (const uint4*)((const uint32_t*)mask + (size_t)w * 64);
#pragma unroll
        for (int q = 0; q < 16; q++) {
            uint4 v = p[q];
            if (v.x) bits |= 1ull << (q * 4 + 0);
            if (v.y) bits |= 1ull << (q * 4 + 1);
            if (v.z) bits |= 1ull << (q * 4 + 2);
            if (v.w) bits |= 1ull << (q * 4 + 3);
        }
    }
    int kt  = w & 31;
    int row = (w >> 5) & (Sq - 1);
    int b   = w >> 16;
    g_mbits[(((size_t)b * 32 + kt) << 11) + row] = bits;
}

// ---- batched fp32 -> fp16 hi (+optional lo) split for up to 8 tensors -----
struct SplitParams {
    const float* src[8];
    __half* hi[8];
    __half* lo[8];          // null -> hi only
    int blkStart[9];
    int nT;
};

__global__ __launch_bounds__(256)
void split_all_kernel(SplitParams P)
{
    int blk = blockIdx.x;
    int t = 0;
    while (t + 1 < P.nT && blk >= P.blkStart[t + 1]) t++;
    int i = (blk - P.blkStart[t]) * 256 * 4 + threadIdx.x * 4;
    const float* x = P.src[t];
    float4 v = *(const float4*)(x + i);
    __half h0 = __float2half_rn(v.x), h1 = __float2half_rn(v.y);
    __half h2 = __float2half_rn(v.z), h3 = __float2half_rn(v.w);
    __half2 hA, hB;
    hA.x = h0; hA.y = h1; hB.x = h2; hB.y = h3;
    *(__half2*)(P.hi[t] + i)     = hA;
    *(__half2*)(P.hi[t] + i + 2) = hB;
    if (P.lo[t]) {
        __half2 lA, lB;
        lA.x = __float2half_rn(v.x - __half2float(h0));
        lA.y = __float2half_rn(v.y - __half2float(h1));
        lB.x = __float2half_rn(v.z - __half2float(h2));
        lB.y = __float2half_rn(v.w - __half2float(h3));
        *(__half2*)(P.lo[t] + i)     = lA;
        *(__half2*)(P.lo[t] + i + 2) = lB;
    }
}

// ---------------------------------------------------------------------------
// HMMA fp16 2-term GEMM core: out = Ah @ (Bh + Bl)^T.  128x64 CTA tile,
// 256 threads, stage 32KB -> 64KB dbuf, 2 CTAs/SM. (R16-proven)
// ---------------------------------------------------------------------------
#define GA_HI   0                    // 128 x 64 f16 = 16KB
#define GB_HI   16384                // 64 x 64 f16 = 8KB
#define GB_LO   24576
#define GSTAGE  32768
#define GSMEM   (2*GSTAGE)           // 64KB

__device__ __forceinline__ void gemm_core(
    const __half* __restrict__ Ah,
    const __half* __restrict__ Bh, const __half* __restrict__ Bl,
    const float* __restrict__ bias, float* __restrict__ out32,
    __half* __restrict__ outh, __half* __restrict__ outl,
    float scale, int M, int N, int K, char* smem)
{
    const uint32_t sbase = smem_u32(smem);
    const int tid  = threadIdx.x;
    const int wid  = tid >> 5;
    const int lane = tid & 31;
    const int m0 = blockIdx.y * 128;
    const int n0 = blockIdx.x * 64;
    const int wm = wid & 3;
    const int wn = wid >> 2;

    float acc[2][4][4];
#pragma unroll
    for (int i = 0; i < 2; i++)
#pragma unroll
        for (int j = 0; j < 4; j++)
#pragma unroll
            for (int c = 0; c < 4; c++) acc[i][j][c] = 0.f;

    auto load_stage = [&](int t, int buf) {
        const int k0 = t * 64;
        const uint32_t sb = sbase + buf * GSTAGE;
#pragma unroll
        for (int l = 0; l < 4; l++) {
            int idx = l * 256 + tid;
            int row = idx >> 3, ch = idx & 7;
            uint32_t sw = swz(row, ch);
            cp_async16(sb + GA_HI + sw, Ah + (size_t)(m0 + row) * K + k0 + ch * 8);
        }
#pragma unroll
        for (int l = 0; l < 2; l++) {
            int idx = l * 256 + tid;
            int row = idx >> 3, ch = idx & 7;
            uint32_t sw = swz(row, ch);
            size_t bo = (size_t)(n0 + row) * K + k0 + ch * 8;
            cp_async16(sb + GB_HI + sw, Bh + bo);
            cp_async16(sb + GB_LO + sw, Bl + bo);
        }
    };

    load_stage(0, 0);
    CP_COMMIT();

    const int arow = wm * 32 + (lane & 15);
    const int brow = wn * 32 + (lane & 15);

    const int NT = K / 64;
#pragma unroll 1
    for (int t = 0; t < NT; t++) {
        const int buf = t & 1;
        if (t + 1 < NT) {
            load_stage(t + 1, (t + 1) & 1);
            CP_COMMIT();
            CP_WAIT(1);        // 2 groups in flight -> drains the older (buf t)
        } else {
            CP_WAIT(0);
        }
        __syncthreads();

        const uint32_t sb = sbase + buf * GSTAGE;
#pragma unroll
        for (int ks = 0; ks < 4; ks++) {
            const int ch = ks * 2 + (lane >> 4);
            uint32_t ah[2][4];
#pragma unroll
            for (int mt = 0; mt < 2; mt++) {
                uint32_t sw = swz(arow + mt * 16, ch);
                ldsm4(ah[mt], sb + GA_HI + sw);
            }
            uint32_t bh[2][4], bl[2][4];
#pragma unroll
            for (int nb = 0; nb < 2; nb++) {
                uint32_t sw = swz(brow + nb * 16, ch);
                ldsm4(bh[nb], sb + GB_HI + sw);
                ldsm4(bl[nb], sb + GB_LO + sw);
            }
#pragma unroll
            for (int mt = 0; mt < 2; mt++)
#pragma unroll
                for (int nt = 0; nt < 4; nt++) {
                    const int nb = nt >> 1, hh = nt & 1;
                    mma16816h(acc[mt][nt], ah[mt], bh[nb][hh], bh[nb][2 + hh]);
                    mma16816h(acc[mt][nt], ah[mt], bl[nb][hh], bl[nb][2 + hh]);
                }
        }
        __syncthreads();       // compute(t) done before load_stage(t+2) -> buf t
    }

#pragma unroll
    for (int mt = 0; mt < 2; mt++) {
#pragma unroll
        for (int nt = 0; nt < 4; nt++) {
            int row = m0 + wm * 32 + mt * 16 + (lane >> 2);
            int col = n0 + wn * 32 + nt * 8 + (lane & 3) * 2;
            if (out32) {
                float2 v0, v1;
                v0.x = acc[mt][nt][0]; v0.y = acc[mt][nt][1];
                v1.x = acc[mt][nt][2]; v1.y = acc[mt][nt][3];
                if (bias) {
                    float b0 = bias[col], b1 = bias[col + 1];
                    v0.x += b0; v0.y += b1;
                    v1.x += b0; v1.y += b1;
                }
                *(float2*)(out32 + (size_t)row * N + col)       = v0;
                *(float2*)(out32 + (size_t)(row + 8) * N + col) = v1;
            } else {
#pragma unroll
                for (int rr = 0; rr < 2; rr++) {
                    size_t o = (size_t)(row + rr * 8) * N + col;
                    float x0 = acc[mt][nt][rr * 2 + 0] * scale;
                    float x1 = acc[mt][nt][rr * 2 + 1] * scale;
                    __half h0 = __float2half_rn(x0);
                    __half h1 = __float2half_rn(x1);
                    __half2 hv; hv.x = h0; hv.y = h1;
                    *(__half2*)(outh + o) = hv;
                    if (outl) {
                        __half2 lv;
                        lv.x = __float2half_rn(x0 - __half2float(h0));
                        lv.y = __float2half_rn(x1 - __half2float(h1));
                        *(__half2*)(outl + o) = lv;
                    }
                }
            }
        }
    }
}

__global__ __launch_bounds__(256, 2)
void gemm_tc_kernel(const __half* __restrict__ Ah,
                    const __half* __restrict__ Bh,
                    const __half* __restrict__ Bl,
                    const float* __restrict__ bias, float* __restrict__ out32,
                    int M, int N, int K)
{
    extern __shared__ char smem[];
    gemm_core(Ah, Bh, Bl, bias, out32, nullptr, nullptr, 1.0f, M, N, K, smem);
}

struct QKVParams {
    const __half *Ah[3], *Bh[3], *Bl[3];
    __half *oh[3], *ol[3];
    float scale[3];
};
__global__ __launch_bounds__(256, 2)
void gemm_qkv_kernel(QKVParams P, int M, int N, int K)
{
    extern __shared__ char smem[];
    const int z = blockIdx.z;
    gemm_core(P.Ah[z], P.Bh[z], P.Bl[z], nullptr, nullptr,
              P.oh[z], P.ol[z], P.scale[z], M, N, K, smem);
}

// ---------------------------------------------------------------------------
// HMMA flash attention: QK = Qh*Kh (1 term), PV = Ph*(Vh+Vl) (2 terms),
// register-resident softmax, 2 CTAs/SM. CTA = 64 q-rows, 256 threads.
// ---------------------------------------------------------------------------
#define AS_QH   0                     // 8KB (64 rows x 64 f16)
#define AS_K    8192                  // [buf] 8KB x2 = 16KB (hi only)
#define AS_V    24576                 // [buf][hi 8KB | lo 8KB] x2 = 32KB
#define AS_SO   8192                  // epilogue alias (64x68 f32 = 17408B)
#define AS_DEN  57344                 // 4 x 64 floats = 1KB
#define ATT_SMEM (AS_DEN + 1024)      // 58368

__global__ __launch_bounds__(256, 2)
void attention_tc_kernel(float* __restrict__ resT, __half* __restrict__ ctx)
{
    extern __shared__ char smem[];
    const uint32_t sbase = smem_u32(smem);
    float* sDen4 = (float*)(smem + AS_DEN);   // [4 wn][64]

    const int tid  = threadIdx.x;
    const int wid  = tid >> 5;
    const int lane = tid & 31;
    const int wm = wid & 1;        // 2 m-warps (32 q-rows each)
    const int wn = wid >> 1;       // 4 k-slice warps (16 k-cols each)
    const int blk = blockIdx.x;
    const int qt  = blk & 31;
    const int h   = (blk >> 5) & 15;
    const int b   = blk >> 9;
    const int q0  = qt * 64;

    const size_t headBase = (size_t)b * Sq * Dq + (size_t)h * Sq * DHq;
    const __half* Qh = g_qh + headBase;
    const __half* Kh = g_kh + headBase;
    const __half* Vh = g_vh + headBase;
    const __half* Vl = g_vl + headBase;

    // ---- initial loads: Q (persistent) + K/V stage 0 ----
#pragma unroll
    for (int l = 0; l < 2; l++) {
        int idx = l * 256 + tid;
        int row = idx >> 3, ch = idx & 7;
        uint32_t sw = swz(row, ch);
        cp_async16(sbase + AS_QH + sw, Qh + (size_t)(q0 + row) * DHq + ch * 8);
    }
#pragma unroll
    for (int l = 0; l < 2; l++) {
        int idx = l * 256 + tid;
        int row = idx >> 3, ch = idx & 7;
        uint32_t sw = swz(row, ch);
        size_t o = (size_t)row * DHq + ch * 8;
        cp_async16(sbase + AS_K + sw,        Kh + o);
        cp_async16(sbase + AS_V + sw,        Vh + o);
        cp_async16(sbase + AS_V + 8192 + sw, Vl + o);
    }
    CP_COMMIT();

    // O partials: [mt][ds][hh2][4]
    float oacc[2][4][2][4];
#pragma unroll
    for (int mt = 0; mt < 2; mt++)
#pragma unroll
        for (int ds = 0; ds < 4; ds++)
#pragma unroll
            for (int hh = 0; hh < 2; hh++)
#pragma unroll
                for (int c = 0; c < 4; c++) oacc[mt][ds][hh][c] = 0.f;
    float denAcc[2][2] = {{0.f, 0.f}, {0.f, 0.f}};

    const int arow = wm * 32 + (lane & 15);
    const int brow = wn * 16 + (lane & 15);
    const int vrow0 = (lane & 7) + ((lane >> 4) << 3);
    const u64* mb = g_mbits + (((size_t)b * 32) << 11) + q0;

    const int NT = Sq / 64;
#pragma unroll 1
    for (int kt = 0; kt < NT; kt++) {
        const int buf = kt & 1;
        CP_WAIT(0);
        __syncthreads();   // K/V[buf] ready; all prev-tile V reads complete

        // prefetch next K/V stage into the other buffer
        if (kt + 1 < NT) {
            const uint32_t kb = sbase + AS_K + (1 - buf) * 8192;
            const uint32_t vb = sbase + AS_V + (1 - buf) * 16384;
            const size_t gk = (size_t)(kt + 1) * 64 * DHq;
#pragma unroll
            for (int l = 0; l < 2; l++) {
                int idx = l * 256 + tid;
                int row = idx >> 3, ch = idx & 7;
                uint32_t sw = swz(row, ch);
                size_t o = gk + (size_t)row * DHq + ch * 8;
                cp_async16(kb + sw,        Kh + o);
                cp_async16(vb + sw,        Vh + o);
                cp_async16(vb + 8192 + sw, Vl + o);
            }
            CP_COMMIT();
        }

        // ---- S = Qh * Kh, this warp's 16 k-cols ----
        float sacc[2][2][4];
#pragma unroll
        for (int mt = 0; mt < 2; mt++)
#pragma unroll
            for (int hh = 0; hh < 2; hh++)
#pragma unroll
                for (int c = 0; c < 4; c++) sacc[mt][hh][c] = 0.f;

        const uint32_t kbh = sbase + AS_K + buf * 8192;
#pragma unroll
        for (int ks = 0; ks < 4; ks++) {
            const int ch = ks * 2 + (lane >> 4);
            uint32_t ah[2][4];
#pragma unroll
            for (int mt = 0; mt < 2; mt++) {
                uint32_t sw = swz(arow + mt * 16, ch);
                ldsm4(ah[mt], sbase + AS_QH + sw);
            }
            uint32_t bh[4];
            {
                uint32_t sw = swz(brow, ch);
                ldsm4(bh, kbh + sw);
            }
#pragma unroll
            for (int mt = 0; mt < 2; mt++)
#pragma unroll
                for (int hh = 0; hh < 2; hh++)
                    mma16816h(sacc[mt][hh], ah[mt], bh[hh], bh[2 + hh]);
        }

        // ---- softmax in registers -> P A-fragments (fp16 hi only) ----
        uint32_t phi[2][4];
        const u64* mtile = mb + ((size_t)kt << 11);
#pragma unroll
        for (int mt = 0; mt < 2; mt++) {
#pragma unroll
            for (int rr = 0; rr < 2; rr++) {
                const int r = wm * 32 + mt * 16 + (lane >> 2) + rr * 8;
                const u64 mword = mtile[r];
#pragma unroll
                for (int hh = 0; hh < 2; hh++) {
                    const int colg = wn * 16 + hh * 8 + (lane & 3) * 2;
                    float p0 = ((mword >> colg) & 1ull)
                             ? __expf(sacc[mt][hh][rr * 2 + 0]) : 0.f;
                    float p1 = ((mword >> (colg + 1)) & 1ull)
                             ? __expf(sacc[mt][hh][rr * 2 + 1]) : 0.f;
                    denAcc[mt][rr] += p0 + p1;
                    phi[mt][hh * 2 + rr] = cvt2h(p0, p1);
                }
            }
        }

        // ---- O += Ph * (Vh + Vl) over this warp's k-slice ----
        const uint32_t vbh = sbase + AS_V + buf * 16384;
        const uint32_t vbl = vbh + 8192;
#pragma unroll
        for (int ds = 0; ds < 4; ds++) {
            uint32_t bh[4], bl[4];
            uint32_t sw = swz(wn * 16 + vrow0, ds * 2 + ((lane >> 3) & 1));
            ldsm4t(bh, vbh + sw);
            ldsm4t(bl, vbl + sw);
#pragma unroll
            for (int mt = 0; mt < 2; mt++)
#pragma unroll
                for (int hh = 0; hh < 2; hh++) {
                    mma16816h(oacc[mt][ds][hh], phi[mt], bh[hh], bh[2 + hh]);
                    mma16816h(oacc[mt][ds][hh], phi[mt], bl[hh], bl[2 + hh]);
                }
        }
    }

    // ---- denominator: quad shfl -> per-wn smem slot ----
#pragma unroll
    for (int mt = 0; mt < 2; mt++)
#pragma unroll
        for (int rr = 0; rr < 2; rr++) {
            float d = denAcc[mt][rr];
            d += __shfl_xor_sync(0xffffffffu, d, 1);
            d += __shfl_xor_sync(0xffffffffu, d, 2);
            if ((lane & 3) == 0)
                sDen4[wn * 64 + wm * 32 + mt * 16 + (lane >> 2) + rr * 8] = d;
        }
    __syncthreads();   // K/V smem now dead; den slots written

    // ---- cross-wn O reduction into sO (aliased, pitch 68) ----
    float* sO = (float*)(smem + AS_SO);
#pragma unroll 1
    for (int round = 0; round < 4; round++) {
        if (wn == round) {
#pragma unroll
            for (int mt = 0; mt < 2; mt++)
#pragma unroll
                for (int ds = 0; ds < 4; ds++)
#pragma unroll
                    for (int hh = 0; hh < 2; hh++)
#pragma unroll
                        for (int rr = 0; rr < 2; rr++) {
                            int r = wm * 32 + mt * 16 + (lane >> 2) + rr * 8;
                            int c = ds * 16 + hh * 8 + (lane & 3) * 2;
                            float* p = &sO[r * 68 + c];
                            if (round == 0) {
                                p[0] = oacc[mt][ds][hh][rr * 2 + 0];
                                p[1] = oacc[mt][ds][hh][rr * 2 + 1];
                            } else {
                                p[0] += oacc[mt][ds][hh][rr * 2 + 0];
                                p[1] += oacc[mt][ds][hh][rr * 2 + 1];
                            }
                        }
        }
        __syncthreads();
    }

    // ---- final: normalize, write ctx (fp16 hi) + resT (fp32) ----
    {
        const int r  = tid >> 2;            // 0..63
        const int cb = (tid & 3) * 16;      // 0,16,32,48
        float dn = sDen4[r] + sDen4[64 + r] + sDen4[128 + r] + sDen4[192 + r];
        float inv = dn > 0.f ? 1.f / dn : 0.f;     // NaN->0 semantics
        int s2 = q0 + r;
        size_t co = ((size_t)b * Sq + s2) * Dq + h * DHq + cb;
        float xv[16];
#pragma unroll
        for (int j = 0; j < 16; j++) xv[j] = sO[r * 68 + cb + j] * inv;
        uint32_t hp[8];
#pragma unroll
        for (int j = 0; j < 8; j++)
            hp[j] = cvt2h(xv[2 * j], xv[2 * j + 1]);
        *(uint4*)(ctx + co)     = *(uint4*)&hp[0];
        *(uint4*)(ctx + co + 8) = *(uint4*)&hp[4];
        if (resT) {
            float* rp = resT + (((size_t)h * Bq + b) * Sq + s2) * DHq + cb;
#pragma unroll
            for (int j = 0; j < 4; j++)
                *(float4*)(rp + 4 * j) = *(float4*)&xv[4 * j];
        }
    }
}

// ---------------------------------------------------------------------------
extern "C" void kernel_launch(void* const* d_in, const int* in_sizes, int n_in,
                              void* d_out, int out_size)
{
    const float* query = (const float*)d_in[0];
    const float* key_  = (const float*)d_in[1];
    const float* value = (const float*)d_in[2];
    const void*  mask  = d_in[3];
    const float* Wq    = (const float*)d_in[4];
    const float* Wk    = (const float*)d_in[5];
    const float* Wv    = (const float*)d_in[6];
    const float* fcw   = (const float*)d_in[7];
    const float* fcb   = (const float*)d_in[8];
    float* out = (float*)d_out;

    __half *qh, *kh, *vh, *vl, *xh, *yh, *zh;
    __half *w1h, *w1l, *w2h, *w2l, *w3h, *w3l, *w4h, *w4l;
    cudaGetSymbolAddress((void**)&qh,  g_qh);
    cudaGetSymbolAddress((void**)&kh,  g_kh);
    cudaGetSymbolAddress((void**)&vh,  g_vh);
    cudaGetSymbolAddress((void**)&vl,  g_vl);
    cudaGetSymbolAddress((void**)&xh,  g_xh);
    cudaGetSymbolAddress((void**)&yh,  g_yh);
    cudaGetSymbolAddress((void**)&zh,  g_zh);
    cudaGetSymbolAddress((void**)&w1h, g_w1h);
    cudaGetSymbolAddress((void**)&w1l, g_w1l);
    cudaGetSymbolAddress((void**)&w2h, g_w2h);
    cudaGetSymbolAddress((void**)&w2l, g_w2l);
    cudaGetSymbolAddress((void**)&w3h, g_w3h);
    cudaGetSymbolAddress((void**)&w3l, g_w3l);
    cudaGetSymbolAddress((void**)&w4h, g_w4h);
    cudaGetSymbolAddress((void**)&w4l, g_w4l);

    cudaFuncSetAttribute(gemm_tc_kernel,
                         cudaFuncAttributeMaxDynamicSharedMemorySize, GSMEM);
    cudaFuncSetAttribute(gemm_qkv_kernel,
                         cudaFuncAttributeMaxDynamicSharedMemorySize, GSMEM);
    cudaFuncSetAttribute(attention_tc_kernel,
                         cudaFuncAttributeMaxDynamicSharedMemorySize, ATT_SMEM);

    detect_mask_kernel<<<1, 32>>>((const unsigned char*)mask);
    mask_bits_kernel<<<MWORDS / 256, 256>>>(mask);

    const int M = Bq * Sq;               // 8192
    const int nX = M * Dq, nW = Dq * Dq;
    const int bX = nX / 1024, bW = nW / 1024;

    // one batched split launch: q,k,v (hi only) + Wq,Wk,Wv,fcw (hi+lo)
    SplitParams sp{};
    const float* srcs[7] = {query, key_, value, Wq, Wk, Wv, fcw};
    __half* his[7] = {xh, yh, zh, w1h, w2h, w3h, w4h};
    __half* los[7] = {nullptr, nullptr, nullptr, w1l, w2l, w3l, w4l};
    int off = 0;
    for (int t = 0; t < 7; t++) {
        sp.src[t] = srcs[t]; sp.hi[t] = his[t]; sp.lo[t] = los[t];
        sp.blkStart[t] = off;
        off += (t < 3) ? bX : bW;
    }
    sp.blkStart[7] = off;
    sp.nT = 7;
    split_all_kernel<<<off, 256>>>(sp);

    // merged Q/K/V projection GEMMs: fp16 2-term
    // (Q hi-only pre-scaled by 1/8; K hi-only; V hi+lo)
    QKVParams qp{};
    qp.Ah[0] = xh; qp.Bh[0] = w1h; qp.Bl[0] = w1l;
    qp.oh[0] = qh; qp.ol[0] = nullptr; qp.scale[0] = 0.125f;
    qp.Ah[1] = yh; qp.Bh[1] = w2h; qp.Bl[1] = w2l;
    qp.oh[1] = kh; qp.ol[1] = nullptr; qp.scale[1] = 1.0f;
    qp.Ah[2] = zh; qp.Bh[2] = w3h; qp.Bl[2] = w3l;
    qp.oh[2] = vh; qp.ol[2] = vl; qp.scale[2] = 1.0f;
    dim3 gq(Dq / 64, M / 128, 3);      // (16, 64, 3)
    gemm_qkv_kernel<<<gq, 256, GSMEM>>>(qp, M, Dq, Dq);

    // attention writes ctx (fp16 hi, aliased over g_xh — q input is consumed)
    float* resT = (out_size >= 2 * BSDq) ? (out + BSDq) : nullptr;
    attention_tc_kernel<<<Bq * Hq * (Sq / 64), 256, ATT_SMEM>>>(resT, xh);

    // final FC: fp16 2-term, fp32 out with bias
    dim3 gf(Dq / 64, M / 128);         // (16, 64)
    gemm_tc_kernel<<<gf, 256, GSMEM>>>(xh, w4h, w4l, fcb, out, M, Dq, Dq);
}